// round 6
// baseline (speedup 1.0000x reference)
#include <cuda_runtime.h>
#include <cuda_fp16.h>
#include <math.h>
#include <stdint.h>

#define BATCH 8192
#define DTOT  4611
#define KPAD  4672              // 73 * 64, zero-filled tail
#define NCHUNK (KPAD / 64)      // 73
#define TT 256                  // square CTA tile
#define TK 64
#define NTHR 512
#define NTILE (BATCH / TT)      // 32
#define NP0   (NTILE * NTILE)              // 1024 pass-0 tiles
#define NP1   (NTILE * (NTILE + 1) / 2)    // 528 pass-1 (upper-tri) tiles
#define STAGE_BYTES 65536       // A 32KB + B 32KB
#define SMEM_TOTAL (3 * STAGE_BYTES)

// ---------------- static device scratch -------------------------------------
__device__ __half g_Gh[(size_t)BATCH * KPAD];   // fp16 G for MMA
__device__ __half g_Ph[(size_t)BATCH * KPAD];   // fp16 prior for MMA
__device__ float    g_rnG[BATCH];
__device__ float    g_rnP[BATCH];
__device__ unsigned g_minP[BATCH];
__device__ unsigned g_minG[BATCH];
__device__ float    g_recon[BATCH];

// monotone float<->uint key: atomicMin(uint) == min(float), exact+deterministic
__device__ __forceinline__ unsigned fkey(float f) {
    unsigned u = __float_as_uint(f);
    return (u & 0x80000000u) ? ~u : (u | 0x80000000u);
}
__device__ __forceinline__ float funkey(unsigned k) {
    unsigned u = (k & 0x80000000u) ? (k ^ 0x80000000u) : ~k;
    return __uint_as_float(u);
}

__device__ __forceinline__ uint32_t smem_u32(const void* p) {
    uint32_t a;
    asm("{ .reg .u64 t; cvta.to.shared.u64 t, %1; cvt.u32.u64 %0, t; }" : "=r"(a) : "l"(p));
    return a;
}

__device__ __forceinline__ void ldsm_x4(uint32_t& r0, uint32_t& r1, uint32_t& r2,
                                        uint32_t& r3, uint32_t addr) {
    asm volatile("ldmatrix.sync.aligned.m8n8.x4.shared.b16 {%0,%1,%2,%3}, [%4];"
                 : "=r"(r0), "=r"(r1), "=r"(r2), "=r"(r3) : "r"(addr));
}

__device__ __forceinline__ void mma16816(float* d, const uint32_t* a,
                                         uint32_t b0, uint32_t b1) {
    asm volatile("mma.sync.aligned.m16n8k16.row.col.f32.f16.f16.f32 "
                 "{%0,%1,%2,%3}, {%4,%5,%6,%7}, {%8,%9}, {%0,%1,%2,%3};"
                 : "+f"(d[0]), "+f"(d[1]), "+f"(d[2]), "+f"(d[3])
                 : "r"(a[0]), "r"(a[1]), "r"(a[2]), "r"(a[3]), "r"(b0), "r"(b1));
}

// ---------------- phase A: hypernetwork + norms + fused decode ---------------
__global__ __launch_bounds__(512)
void build_G_decode_kernel(const float* __restrict__ n,
                           const float* __restrict__ z,
                           const float* __restrict__ znext,
                           float* __restrict__ out,
                           const float* __restrict__ w1W, const float* __restrict__ w1b,
                           const float* __restrict__ b1W, const float* __restrict__ b1b,
                           const float* __restrict__ w2W, const float* __restrict__ w2b,
                           const float* __restrict__ b2W, const float* __restrict__ b2b,
                           const float* __restrict__ w3W, const float* __restrict__ w3b,
                           const float* __restrict__ b3W, const float* __restrict__ b3b)
{
    __shared__ float ns[25];
    __shared__ float row[KPAD];
    __shared__ float sm[512];
    __shared__ float h1[64], h2[64], zh[3];
    const int b = blockIdx.x;
    const int t = threadIdx.x;
    if (t < 25) ns[t] = n[b * 25 + t];
    __syncthreads();

    float s = 0.f;
    for (int c = t; c < KPAD; c += 512) {
        float val = 0.f;
        if (c < DTOT) {
            const float* W; const float* bias; int local, width;
            if      (c < 192)  { W = w1W; bias = w1b; local = c;        width = 192;  }
            else if (c < 256)  { W = b1W; bias = b1b; local = c - 192;  width = 64;   }
            else if (c < 4352) { W = w2W; bias = w2b; local = c - 256;  width = 4096; }
            else if (c < 4416) { W = b2W; bias = b2b; local = c - 4352; width = 64;   }
            else if (c < 4608) { W = w3W; bias = w3b; local = c - 4416; width = 192;  }
            else               { W = b3W; bias = b3b; local = c - 4608; width = 3;    }
            float acc = 0.f;
            #pragma unroll
            for (int k = 0; k < 25; k++) acc += ns[k] * W[k * width + local];
            val = acc + bias[local];
            s += val * val;
        }
        row[c] = val;
        g_Gh[(long)b * KPAD + c] = __float2half_rn(val);
    }
    sm[t] = s;
    __syncthreads();
    for (int off = 256; off > 0; off >>= 1) {
        if (t < off) sm[t] += sm[t + off];
        __syncthreads();
    }
    if (t == 0) g_rnG[b] = sm[0];

    // ---- decode MLP from smem row ----
    if (t < 64) {
        const float z0 = z[b * 3], z1 = z[b * 3 + 1], z2 = z[b * 3 + 2];
        float a = row[t * 3] * z0 + row[t * 3 + 1] * z1 + row[t * 3 + 2] * z2
                + row[192 + t];
        h1[t] = (a > 0.f) ? a : expm1f(a);
    }
    __syncthreads();
    if (t < 64) {
        float s2 = 0.f;
        #pragma unroll 8
        for (int jj = 0; jj < 64; jj++) {
            const int j = (jj + t) & 63;
            s2 += row[256 + t * 64 + j] * h1[j];
        }
        s2 += row[4352 + t];
        h2[t] = (s2 > 0.f) ? s2 : expm1f(s2);
    }
    __syncthreads();
    if (t < 3) {
        float s3 = 0.f;
        #pragma unroll 8
        for (int j = 0; j < 64; j++) s3 += row[4416 + t * 64 + j] * h2[j];
        s3 += row[4608 + t];
        out[2 + b * 3 + t] = s3;
        zh[t] = s3;
    }
    __syncthreads();
    if (t == 0) {
        float d0 = zh[0] - znext[b * 3];
        float d1 = zh[1] - znext[b * 3 + 1];
        float d2 = zh[2] - znext[b * 3 + 2];
        g_recon[b] = d0 * d0 + d1 * d1 + d2 * d2;
    }
}

__global__ __launch_bounds__(256)
void split_prior_kernel(const float* __restrict__ prior)
{
    __shared__ float sm[256];
    const int b = blockIdx.x;
    float s = 0.f;
    for (int c = threadIdx.x; c < KPAD; c += 256) {
        float val = 0.f;
        if (c < DTOT) { val = prior[(long)b * DTOT + c]; s += val * val; }
        g_Ph[(long)b * KPAD + c] = __float2half_rn(val);
    }
    sm[threadIdx.x] = s;
    __syncthreads();
    for (int off = 128; off > 0; off >>= 1) {
        if (threadIdx.x < off) sm[threadIdx.x] += sm[threadIdx.x + off];
        __syncthreads();
    }
    if (threadIdx.x == 0) g_rnP[b] = sm[0];
}

__global__ void init_min_kernel()
{
    int t = blockIdx.x * 256 + threadIdx.x;
    if (t < BATCH) { g_minP[t] = 0xFFFFFFFFu; g_minG[t] = 0xFFFFFFFFu; }
}

// ---------------- phase C: HMMA fused GEMM + min (both passes, one launch) ---
__device__ __forceinline__ void load_tile(uint32_t sbase, const __half* __restrict__ g,
                                          long row0, int k0, int tid)
{
    const int nunits = TT * 8;              // 2048 16B units, 128B per row
    #pragma unroll 4
    for (int u = tid; u < nunits; u += NTHR) {
        const int r = u >> 3, un = u & 7;
        const int sw = un ^ (r & 7);
        const void* src = g + (row0 + r) * (long)KPAD + k0 + un * 8;
        asm volatile("cp.async.cg.shared.global [%0], [%1], 16;"
                     :: "r"(sbase + (uint32_t)(r * 128 + sw * 16)), "l"(src) : "memory");
    }
}

// blockIdx.x < NP0: pass 0 tile (A = prior), colmin[j] = min_i (rnP[i]-2 P.G)
// else: pass 1 upper-tri tile (A = G, ib <= jb): col-min AND row-min folded,
//       diagonal masked.
__global__ __launch_bounds__(NTHR, 1)
void min_gemm_hmma_kernel()
{
    const int bid = blockIdx.x;
    const int pass = (bid >= NP0);
    int ib, jb;
    if (!pass) { ib = bid >> 5; jb = bid & 31; }
    else {
        const int t = bid - NP0;
        jb = (int)((sqrtf(8.f * (float)t + 1.f) - 1.f) * 0.5f);
        while ((jb + 1) * (jb + 2) / 2 <= t) jb++;
        while (jb * (jb + 1) / 2 > t) jb--;
        ib = t - jb * (jb + 1) / 2;
    }
    const long i0 = (long)ib * TT;
    const long j0 = (long)jb * TT;

    const __half* __restrict__ A  = pass ? g_Gh : g_Ph;
    const float* __restrict__ rnA = pass ? g_rnG : g_rnP;
    unsigned* colmin              = pass ? g_minG : g_minP;

    extern __shared__ char smem[];
    const uint32_t sb = smem_u32(smem);
    const int tid = threadIdx.x;
    const int lane = tid & 31;
    const int wid = tid >> 5;                // 0..15
    const int wm = wid >> 2;                 // 0..3  (M, 64 rows each)
    const int wn = wid & 3;                  // 0..3  (N, 64 cols each)

    float d[4][8][4];
    #pragma unroll
    for (int mi = 0; mi < 4; mi++)
        #pragma unroll
        for (int ni = 0; ni < 8; ni++)
            #pragma unroll
            for (int q = 0; q < 4; q++) d[mi][ni][q] = 0.f;

    // per-thread ldmatrix row bases
    int aoff[4], asw[4], boff[4], bsw[4];
    const int ahalf = (lane >> 4) & 1;
    const int bhalf = (lane >> 3) & 1;
    #pragma unroll
    for (int mi = 0; mi < 4; mi++) {
        int row = wm * 64 + mi * 16 + (lane & 7) + ((lane >> 3) & 1) * 8;
        aoff[mi] = row * 128; asw[mi] = row & 7;
    }
    #pragma unroll
    for (int nb = 0; nb < 4; nb++) {
        int row = wn * 64 + nb * 16 + (lane & 7) + ((lane >> 4) & 1) * 8;
        boff[nb] = row * 128; bsw[nb] = row & 7;
    }

    // prologue: chunks 0,1 into stages 0,1
    load_tile(sb,                       A,    i0, 0,  tid);
    load_tile(sb + 32768,               g_Gh, j0, 0,  tid);
    asm volatile("cp.async.commit_group;" ::: "memory");
    load_tile(sb + STAGE_BYTES,         A,    i0, TK, tid);
    load_tile(sb + STAGE_BYTES + 32768, g_Gh, j0, TK, tid);
    asm volatile("cp.async.commit_group;" ::: "memory");

    int stage = 0, next = 2;
    for (int c = 0; c < NCHUNK; c++) {
        if (c + 2 < NCHUNK) {
            const uint32_t sn = sb + (uint32_t)next * STAGE_BYTES;
            load_tile(sn,         A,    i0, (c + 2) * TK, tid);
            load_tile(sn + 32768, g_Gh, j0, (c + 2) * TK, tid);
            asm volatile("cp.async.commit_group;" ::: "memory");
            asm volatile("cp.async.wait_group 2;" ::: "memory");
        } else if (c + 1 < NCHUNK) {
            asm volatile("cp.async.wait_group 1;" ::: "memory");
        } else {
            asm volatile("cp.async.wait_group 0;" ::: "memory");
        }
        __syncthreads();

        const uint32_t Ab = sb + (uint32_t)stage * STAGE_BYTES;
        const uint32_t Bb = Ab + 32768;

        #pragma unroll
        for (int ks = 0; ks < 4; ks++) {
            uint32_t a[4][4], b[4][4];
            #pragma unroll
            for (int mi = 0; mi < 4; mi++)
                ldsm_x4(a[mi][0], a[mi][1], a[mi][2], a[mi][3],
                        Ab + aoff[mi] + (uint32_t)(((ks * 2 + ahalf) ^ asw[mi]) * 16));
            #pragma unroll
            for (int nb = 0; nb < 4; nb++)
                ldsm_x4(b[nb][0], b[nb][1], b[nb][2], b[nb][3],
                        Bb + boff[nb] + (uint32_t)(((ks * 2 + bhalf) ^ bsw[nb]) * 16));
            #pragma unroll
            for (int mi = 0; mi < 4; mi++)
                #pragma unroll
                for (int nb = 0; nb < 4; nb++) {
                    mma16816(d[mi][nb * 2],     a[mi], b[nb][0], b[nb][1]);
                    mma16816(d[mi][nb * 2 + 1], a[mi], b[nb][2], b[nb][3]);
                }
        }
        __syncthreads();
        stage = (stage + 1) % 3;
        next  = (next + 1) % 3;
    }

    // ---------------- epilogue ------------------------------------------------
    const int g = lane >> 2, tig = lane & 3;
    float cmin[8][2];
    #pragma unroll
    for (int ni = 0; ni < 8; ni++) { cmin[ni][0] = 1e30f; cmin[ni][1] = 1e30f; }
    float rmin[4][2];
    #pragma unroll
    for (int mi = 0; mi < 4; mi++) { rmin[mi][0] = 1e30f; rmin[mi][1] = 1e30f; }

    float rnj0[8], rnj1[8];
    if (pass) {
        #pragma unroll
        for (int ni = 0; ni < 8; ni++) {
            const long jg = j0 + wn * 64 + ni * 8 + 2 * tig;
            rnj0[ni] = g_rnG[jg];
            rnj1[ni] = g_rnG[jg + 1];
        }
    }

    #pragma unroll
    for (int mi = 0; mi < 4; mi++) {
        const long ig0 = i0 + wm * 64 + mi * 16 + g;
        const long ig1 = ig0 + 8;
        const float rn0 = rnA[ig0];
        const float rn1 = rnA[ig1];
        #pragma unroll
        for (int ni = 0; ni < 8; ni++) {
            const float d0 = d[mi][ni][0], d1 = d[mi][ni][1];
            const float d2 = d[mi][ni][2], d3 = d[mi][ni][3];
            float v0 = fmaf(-2.f, d0, rn0);
            float v1 = fmaf(-2.f, d1, rn0);
            float v2 = fmaf(-2.f, d2, rn1);
            float v3 = fmaf(-2.f, d3, rn1);
            if (pass) {
                const long jg = j0 + wn * 64 + ni * 8 + 2 * tig;
                float w0 = fmaf(-2.f, d0, rnj0[ni]);
                float w1 = fmaf(-2.f, d1, rnj1[ni]);
                float w2 = fmaf(-2.f, d2, rnj0[ni]);
                float w3 = fmaf(-2.f, d3, rnj1[ni]);
                if (ig0 == jg)     { v0 = 1e30f; w0 = 1e30f; }
                if (ig0 == jg + 1) { v1 = 1e30f; w1 = 1e30f; }
                if (ig1 == jg)     { v2 = 1e30f; w2 = 1e30f; }
                if (ig1 == jg + 1) { v3 = 1e30f; w3 = 1e30f; }
                rmin[mi][0] = fminf(rmin[mi][0], fminf(w0, w1));
                rmin[mi][1] = fminf(rmin[mi][1], fminf(w2, w3));
            }
            cmin[ni][0] = fminf(cmin[ni][0], fminf(v0, v2));
            cmin[ni][1] = fminf(cmin[ni][1], fminf(v1, v3));
        }
    }

    // column-min: reduce across g-lanes (bits 2..4)
    #pragma unroll
    for (int off = 4; off <= 16; off <<= 1)
        #pragma unroll
        for (int ni = 0; ni < 8; ni++) {
            cmin[ni][0] = fminf(cmin[ni][0], __shfl_xor_sync(0xFFFFFFFFu, cmin[ni][0], off));
            cmin[ni][1] = fminf(cmin[ni][1], __shfl_xor_sync(0xFFFFFFFFu, cmin[ni][1], off));
        }
    if (pass) {
        // row-min: reduce across tig-lanes (bits 0..1)
        #pragma unroll
        for (int off = 1; off <= 2; off <<= 1)
            #pragma unroll
            for (int mi = 0; mi < 4; mi++) {
                rmin[mi][0] = fminf(rmin[mi][0], __shfl_xor_sync(0xFFFFFFFFu, rmin[mi][0], off));
                rmin[mi][1] = fminf(rmin[mi][1], __shfl_xor_sync(0xFFFFFFFFu, rmin[mi][1], off));
            }
    }

    float* cbuf = (float*)smem;              // [4][256]
    float* rbuf = cbuf + 1024;               // [256][4]
    if (lane < 4) {
        #pragma unroll
        for (int ni = 0; ni < 8; ni++) {
            const int col = wn * 64 + ni * 8 + 2 * lane;
            cbuf[wm * 256 + col]     = cmin[ni][0];
            cbuf[wm * 256 + col + 1] = cmin[ni][1];
        }
    }
    if (pass && tig == 0) {
        #pragma unroll
        for (int mi = 0; mi < 4; mi++) {
            const int r0 = wm * 64 + mi * 16 + g;     // unique (r, wn) per writer
            rbuf[r0 * 4 + wn]       = rmin[mi][0];
            rbuf[(r0 + 8) * 4 + wn] = rmin[mi][1];
        }
    }
    __syncthreads();

    if (tid < TT) {
        const float m = fminf(fminf(cbuf[tid], cbuf[256 + tid]),
                              fminf(cbuf[512 + tid], cbuf[768 + tid]));
        atomicMin(&colmin[j0 + tid], fkey(m));
    } else if (pass) {
        const int r = tid - TT;
        const float m = fminf(fminf(rbuf[r * 4], rbuf[r * 4 + 1]),
                              fminf(rbuf[r * 4 + 2], rbuf[r * 4 + 3]));
        atomicMin(&colmin[i0 + r], fkey(m));
    }
}

// ---------------- phase D: final scalar reductions ---------------------------
__global__ void finalize_kernel(float* __restrict__ out)
{
    __shared__ float s1[1024], s2[1024];
    const int t = threadIdx.x;
    float rsum = 0.f, ksum = 0.f;
    for (int j = t; j < BATCH; j += 1024) {
        rsum += g_recon[j];
        float rn = g_rnG[j];
        float wp = sqrtf(fmaxf(funkey(g_minP[j]) + rn, 0.f) + 1e-8f);
        float ww = sqrtf(fmaxf(funkey(g_minG[j]) + rn, 0.f) + 1e-8f);
        ksum += logf(wp / (ww + 1e-8f) + 1e-8f);
    }
    s1[t] = rsum; s2[t] = ksum;
    __syncthreads();
    for (int off = 512; off > 0; off >>= 1) {
        if (t < off) { s1[t] += s1[t + off]; s2[t] += s2[t + off]; }
        __syncthreads();
    }
    if (t == 0) {
        out[0] = s1[0] / (float)BATCH;
        out[1] = s2[0] / (float)BATCH * (float)DTOT
               + logf((float)BATCH / (float)(BATCH - 1));
    }
}

// ---------------- launch ------------------------------------------------------
extern "C" void kernel_launch(void* const* d_in, const int* in_sizes, int n_in,
                              void* d_out, int out_size)
{
    (void)in_sizes; (void)n_in; (void)out_size;
    const float* z     = (const float*)d_in[0];
    const float* znext = (const float*)d_in[1];
    const float* n     = (const float*)d_in[2];
    const float* prior = (const float*)d_in[3];
    const float* w1W = (const float*)d_in[4];  const float* w1b = (const float*)d_in[5];
    const float* b1W = (const float*)d_in[6];  const float* b1b = (const float*)d_in[7];
    const float* w2W = (const float*)d_in[8];  const float* w2b = (const float*)d_in[9];
    const float* b2W = (const float*)d_in[10]; const float* b2b = (const float*)d_in[11];
    const float* w3W = (const float*)d_in[12]; const float* w3b = (const float*)d_in[13];
    const float* b3W = (const float*)d_in[14]; const float* b3b = (const float*)d_in[15];
    float* out = (float*)d_out;

    cudaFuncSetAttribute(min_gemm_hmma_kernel,
                         cudaFuncAttributeMaxDynamicSharedMemorySize, SMEM_TOTAL);

    init_min_kernel<<<(BATCH + 255) / 256, 256>>>();
    build_G_decode_kernel<<<BATCH, 512>>>(
        n, z, znext, out,
        w1W, w1b, b1W, b1b, w2W, w2b, b2W, b2b, w3W, w3b, b3W, b3b);
    split_prior_kernel<<<BATCH, 256>>>(prior);

    min_gemm_hmma_kernel<<<NP0 + NP1, NTHR, SMEM_TOTAL>>>();

    finalize_kernel<<<1, 1024>>>(out);
}

// round 7
// speedup vs baseline: 2.9505x; 2.9505x over previous
#include <cuda_runtime.h>
#include <cuda_fp16.h>
#include <math.h>
#include <stdint.h>

#define BATCH 8192
#define DTOT  4611
#define KPAD  4672              // 73 * 64, zero-filled tail
#define NCHUNK (KPAD / 64)      // 73
#define TT 128                  // square CTA tile
#define TK 64
#define NTHR 128
#define NTILE (BATCH / TT)      // 64
#define NP0   (NTILE * NTILE)              // 4096 pass-0 tiles
#define NP1   (NTILE * (NTILE + 1) / 2)    // 2080 pass-1 (upper-tri) tiles
#define STAGE_BYTES 32768       // A 16KB + B 16KB
#define SMEM_TOTAL (3 * STAGE_BYTES)

// ---------------- static device scratch -------------------------------------
__device__ __half g_Gh[(size_t)BATCH * KPAD];   // fp16 G for MMA
__device__ __half g_Ph[(size_t)BATCH * KPAD];   // fp16 prior for MMA
__device__ float    g_rnG[BATCH];
__device__ float    g_rnP[BATCH];
__device__ unsigned g_minP[BATCH];
__device__ unsigned g_minG[BATCH];
__device__ float    g_recon[BATCH];

// monotone float<->uint key: atomicMin(uint) == min(float), exact+deterministic
__device__ __forceinline__ unsigned fkey(float f) {
    unsigned u = __float_as_uint(f);
    return (u & 0x80000000u) ? ~u : (u | 0x80000000u);
}
__device__ __forceinline__ float funkey(unsigned k) {
    unsigned u = (k & 0x80000000u) ? (k ^ 0x80000000u) : ~k;
    return __uint_as_float(u);
}

__device__ __forceinline__ uint32_t smem_u32(const void* p) {
    uint32_t a;
    asm("{ .reg .u64 t; cvta.to.shared.u64 t, %1; cvt.u32.u64 %0, t; }" : "=r"(a) : "l"(p));
    return a;
}

__device__ __forceinline__ void ldsm_x4(uint32_t& r0, uint32_t& r1, uint32_t& r2,
                                        uint32_t& r3, uint32_t addr) {
    asm volatile("ldmatrix.sync.aligned.m8n8.x4.shared.b16 {%0,%1,%2,%3}, [%4];"
                 : "=r"(r0), "=r"(r1), "=r"(r2), "=r"(r3) : "r"(addr));
}

__device__ __forceinline__ void mma16816(float* d, const uint32_t* a,
                                         uint32_t b0, uint32_t b1) {
    asm volatile("mma.sync.aligned.m16n8k16.row.col.f32.f16.f16.f32 "
                 "{%0,%1,%2,%3}, {%4,%5,%6,%7}, {%8,%9}, {%0,%1,%2,%3};"
                 : "+f"(d[0]), "+f"(d[1]), "+f"(d[2]), "+f"(d[3])
                 : "r"(a[0]), "r"(a[1]), "r"(a[2]), "r"(a[3]), "r"(b0), "r"(b1));
}

// ---------------- phase A: hypernetwork + norms + fused decode ---------------
__global__ __launch_bounds__(512)
void build_G_decode_kernel(const float* __restrict__ n,
                           const float* __restrict__ z,
                           const float* __restrict__ znext,
                           float* __restrict__ out,
                           const float* __restrict__ w1W, const float* __restrict__ w1b,
                           const float* __restrict__ b1W, const float* __restrict__ b1b,
                           const float* __restrict__ w2W, const float* __restrict__ w2b,
                           const float* __restrict__ b2W, const float* __restrict__ b2b,
                           const float* __restrict__ w3W, const float* __restrict__ w3b,
                           const float* __restrict__ b3W, const float* __restrict__ b3b)
{
    __shared__ float ns[25];
    __shared__ float row[KPAD];
    __shared__ float sm[512];
    __shared__ float h1[64], h2[64], zh[3];
    const int b = blockIdx.x;
    const int t = threadIdx.x;
    if (t < 25) ns[t] = n[b * 25 + t];
    __syncthreads();

    float s = 0.f;
    for (int c = t; c < KPAD; c += 512) {
        float val = 0.f;
        if (c < DTOT) {
            const float* W; const float* bias; int local, width;
            if      (c < 192)  { W = w1W; bias = w1b; local = c;        width = 192;  }
            else if (c < 256)  { W = b1W; bias = b1b; local = c - 192;  width = 64;   }
            else if (c < 4352) { W = w2W; bias = w2b; local = c - 256;  width = 4096; }
            else if (c < 4416) { W = b2W; bias = b2b; local = c - 4352; width = 64;   }
            else if (c < 4608) { W = w3W; bias = w3b; local = c - 4416; width = 192;  }
            else               { W = b3W; bias = b3b; local = c - 4608; width = 3;    }
            float acc = 0.f;
            #pragma unroll
            for (int k = 0; k < 25; k++) acc += ns[k] * W[k * width + local];
            val = acc + bias[local];
            s += val * val;
        }
        row[c] = val;
        g_Gh[(long)b * KPAD + c] = __float2half_rn(val);
    }
    sm[t] = s;
    __syncthreads();
    for (int off = 256; off > 0; off >>= 1) {
        if (t < off) sm[t] += sm[t + off];
        __syncthreads();
    }
    if (t == 0) g_rnG[b] = sm[0];

    // ---- decode MLP from smem row ----
    if (t < 64) {
        const float z0 = z[b * 3], z1 = z[b * 3 + 1], z2 = z[b * 3 + 2];
        float a = row[t * 3] * z0 + row[t * 3 + 1] * z1 + row[t * 3 + 2] * z2
                + row[192 + t];
        h1[t] = (a > 0.f) ? a : expm1f(a);
    }
    __syncthreads();
    if (t < 64) {
        float s2 = 0.f;
        #pragma unroll 8
        for (int jj = 0; jj < 64; jj++) {
            const int j = (jj + t) & 63;
            s2 += row[256 + t * 64 + j] * h1[j];
        }
        s2 += row[4352 + t];
        h2[t] = (s2 > 0.f) ? s2 : expm1f(s2);
    }
    __syncthreads();
    if (t < 3) {
        float s3 = 0.f;
        #pragma unroll 8
        for (int j = 0; j < 64; j++) s3 += row[4416 + t * 64 + j] * h2[j];
        s3 += row[4608 + t];
        out[2 + b * 3 + t] = s3;
        zh[t] = s3;
    }
    __syncthreads();
    if (t == 0) {
        float d0 = zh[0] - znext[b * 3];
        float d1 = zh[1] - znext[b * 3 + 1];
        float d2 = zh[2] - znext[b * 3 + 2];
        g_recon[b] = d0 * d0 + d1 * d1 + d2 * d2;
    }
}

__global__ __launch_bounds__(256)
void split_prior_kernel(const float* __restrict__ prior)
{
    __shared__ float sm[256];
    const int b = blockIdx.x;
    float s = 0.f;
    for (int c = threadIdx.x; c < KPAD; c += 256) {
        float val = 0.f;
        if (c < DTOT) { val = prior[(long)b * DTOT + c]; s += val * val; }
        g_Ph[(long)b * KPAD + c] = __float2half_rn(val);
    }
    sm[threadIdx.x] = s;
    __syncthreads();
    for (int off = 128; off > 0; off >>= 1) {
        if (threadIdx.x < off) sm[threadIdx.x] += sm[threadIdx.x + off];
        __syncthreads();
    }
    if (threadIdx.x == 0) g_rnP[b] = sm[0];
}

__global__ void init_min_kernel()
{
    int t = blockIdx.x * 256 + threadIdx.x;
    if (t < BATCH) { g_minP[t] = 0xFFFFFFFFu; g_minG[t] = 0xFFFFFFFFu; }
}

// ---------------- phase C: HMMA fused GEMM + min (both passes, one launch) ---
__device__ __forceinline__ void load_tile(uint32_t sbase, const __half* __restrict__ g,
                                          long row0, int k0, int tid)
{
    const int nunits = TT * 8;              // 1024 16B units, 128B per row
    #pragma unroll 8
    for (int u = tid; u < nunits; u += NTHR) {
        const int r = u >> 3, un = u & 7;
        const int sw = un ^ (r & 7);
        const void* src = g + (row0 + r) * (long)KPAD + k0 + un * 8;
        asm volatile("cp.async.cg.shared.global [%0], [%1], 16;"
                     :: "r"(sbase + (uint32_t)(r * 128 + sw * 16)), "l"(src) : "memory");
    }
}

#define LDF(B, KS)                                                              \
    { _Pragma("unroll") for (int mi = 0; mi < 4; mi++)                          \
        ldsm_x4(afr[B][mi][0], afr[B][mi][1], afr[B][mi][2], afr[B][mi][3],     \
                Ab + aoff[mi] + (uint32_t)((((KS) * 2 + ahalf) ^ asw[mi]) * 16)); \
      _Pragma("unroll") for (int nb = 0; nb < 4; nb++)                          \
        ldsm_x4(bfr[B][nb][0], bfr[B][nb][1], bfr[B][nb][2], bfr[B][nb][3],     \
                Bb + boff[nb] + (uint32_t)((((KS) * 2 + bhalf) ^ bsw[nb]) * 16)); }

#define MMAS(B)                                                                 \
    { _Pragma("unroll") for (int mi = 0; mi < 4; mi++)                          \
      _Pragma("unroll") for (int nb = 0; nb < 4; nb++) {                        \
          mma16816(d[mi][nb * 2],     afr[B][mi], bfr[B][nb][0], bfr[B][nb][1]); \
          mma16816(d[mi][nb * 2 + 1], afr[B][mi], bfr[B][nb][2], bfr[B][nb][3]); } }

// blockIdx.x < NP0: pass 0 tile (A = prior), colmin[j] = min_i (rnP[i]-2 P.G)
// else: pass 1 upper-tri tile (A = G, ib <= jb): col-min AND row-min folded,
//       diagonal masked.
__global__ __launch_bounds__(NTHR, 2)
void min_gemm_hmma_kernel()
{
    const int bid = blockIdx.x;
    const int pass = (bid >= NP0);
    int ib, jb;
    if (!pass) { ib = bid >> 6; jb = bid & 63; }
    else {
        const int t = bid - NP0;
        jb = (int)((sqrtf(8.f * (float)t + 1.f) - 1.f) * 0.5f);
        while ((jb + 1) * (jb + 2) / 2 <= t) jb++;
        while (jb * (jb + 1) / 2 > t) jb--;
        ib = t - jb * (jb + 1) / 2;
    }
    const long i0 = (long)ib * TT;
    const long j0 = (long)jb * TT;

    const __half* __restrict__ A  = pass ? g_Gh : g_Ph;
    const float* __restrict__ rnA = pass ? g_rnG : g_rnP;
    unsigned* colmin              = pass ? g_minG : g_minP;

    extern __shared__ char smem[];
    const uint32_t sb = smem_u32(smem);
    const int tid = threadIdx.x;
    const int lane = tid & 31;
    const int wid = tid >> 5;                // 0..3
    const int wm = wid >> 1;                 // 0..1  (M, 64 rows each)
    const int wn = wid & 1;                  // 0..1  (N, 64 cols each)

    float d[4][8][4];
    #pragma unroll
    for (int mi = 0; mi < 4; mi++)
        #pragma unroll
        for (int ni = 0; ni < 8; ni++)
            #pragma unroll
            for (int q = 0; q < 4; q++) d[mi][ni][q] = 0.f;

    // per-thread ldmatrix row bases
    int aoff[4], asw[4], boff[4], bsw[4];
    const int ahalf = (lane >> 4) & 1;
    const int bhalf = (lane >> 3) & 1;
    #pragma unroll
    for (int mi = 0; mi < 4; mi++) {
        int row = wm * 64 + mi * 16 + (lane & 7) + ((lane >> 3) & 1) * 8;
        aoff[mi] = row * 128; asw[mi] = row & 7;
    }
    #pragma unroll
    for (int nb = 0; nb < 4; nb++) {
        int row = wn * 64 + nb * 16 + (lane & 7) + ((lane >> 4) & 1) * 8;
        boff[nb] = row * 128; bsw[nb] = row & 7;
    }

    // prologue: chunks 0,1 into stages 0,1
    load_tile(sb,                       A,    i0, 0,  tid);
    load_tile(sb + 16384,               g_Gh, j0, 0,  tid);
    asm volatile("cp.async.commit_group;" ::: "memory");
    load_tile(sb + STAGE_BYTES,         A,    i0, TK, tid);
    load_tile(sb + STAGE_BYTES + 16384, g_Gh, j0, TK, tid);
    asm volatile("cp.async.commit_group;" ::: "memory");

    int stage = 0, next = 2;
    for (int c = 0; c < NCHUNK; c++) {
        if (c + 2 < NCHUNK) {
            const uint32_t sn = sb + (uint32_t)next * STAGE_BYTES;
            load_tile(sn,         A,    i0, (c + 2) * TK, tid);
            load_tile(sn + 16384, g_Gh, j0, (c + 2) * TK, tid);
            asm volatile("cp.async.commit_group;" ::: "memory");
            asm volatile("cp.async.wait_group 2;" ::: "memory");
        } else if (c + 1 < NCHUNK) {
            asm volatile("cp.async.wait_group 1;" ::: "memory");
        } else {
            asm volatile("cp.async.wait_group 0;" ::: "memory");
        }
        __syncthreads();

        const uint32_t Ab = sb + (uint32_t)stage * STAGE_BYTES;
        const uint32_t Bb = Ab + 16384;

        // double-buffered fragment pipeline over the 4 k16 steps
        uint32_t afr[2][4][4], bfr[2][4][4];
        LDF(0, 0)
        LDF(1, 1)
        MMAS(0)
        LDF(0, 2)
        MMAS(1)
        LDF(1, 3)
        MMAS(0)
        MMAS(1)

        __syncthreads();
        stage = (stage + 1) % 3;
        next  = (next + 1) % 3;
    }

    // ---------------- epilogue ------------------------------------------------
    const int g = lane >> 2, tig = lane & 3;
    float cmin[8][2];
    #pragma unroll
    for (int ni = 0; ni < 8; ni++) { cmin[ni][0] = 1e30f; cmin[ni][1] = 1e30f; }
    float rmin[4][2];
    #pragma unroll
    for (int mi = 0; mi < 4; mi++) { rmin[mi][0] = 1e30f; rmin[mi][1] = 1e30f; }

    float rnj0[8], rnj1[8];
    if (pass) {
        #pragma unroll
        for (int ni = 0; ni < 8; ni++) {
            const long jg = j0 + wn * 64 + ni * 8 + 2 * tig;
            rnj0[ni] = g_rnG[jg];
            rnj1[ni] = g_rnG[jg + 1];
        }
    }

    #pragma unroll
    for (int mi = 0; mi < 4; mi++) {
        const long ig0 = i0 + wm * 64 + mi * 16 + g;
        const long ig1 = ig0 + 8;
        const float rn0 = rnA[ig0];
        const float rn1 = rnA[ig1];
        #pragma unroll
        for (int ni = 0; ni < 8; ni++) {
            const float d0 = d[mi][ni][0], d1 = d[mi][ni][1];
            const float d2 = d[mi][ni][2], d3 = d[mi][ni][3];
            float v0 = fmaf(-2.f, d0, rn0);
            float v1 = fmaf(-2.f, d1, rn0);
            float v2 = fmaf(-2.f, d2, rn1);
            float v3 = fmaf(-2.f, d3, rn1);
            if (pass) {
                const long jg = j0 + wn * 64 + ni * 8 + 2 * tig;
                float w0 = fmaf(-2.f, d0, rnj0[ni]);
                float w1 = fmaf(-2.f, d1, rnj1[ni]);
                float w2 = fmaf(-2.f, d2, rnj0[ni]);
                float w3 = fmaf(-2.f, d3, rnj1[ni]);
                if (ig0 == jg)     { v0 = 1e30f; w0 = 1e30f; }
                if (ig0 == jg + 1) { v1 = 1e30f; w1 = 1e30f; }
                if (ig1 == jg)     { v2 = 1e30f; w2 = 1e30f; }
                if (ig1 == jg + 1) { v3 = 1e30f; w3 = 1e30f; }
                rmin[mi][0] = fminf(rmin[mi][0], fminf(w0, w1));
                rmin[mi][1] = fminf(rmin[mi][1], fminf(w2, w3));
            }
            cmin[ni][0] = fminf(cmin[ni][0], fminf(v0, v2));
            cmin[ni][1] = fminf(cmin[ni][1], fminf(v1, v3));
        }
    }

    // column-min: reduce across g-lanes (bits 2..4)
    #pragma unroll
    for (int off = 4; off <= 16; off <<= 1)
        #pragma unroll
        for (int ni = 0; ni < 8; ni++) {
            cmin[ni][0] = fminf(cmin[ni][0], __shfl_xor_sync(0xFFFFFFFFu, cmin[ni][0], off));
            cmin[ni][1] = fminf(cmin[ni][1], __shfl_xor_sync(0xFFFFFFFFu, cmin[ni][1], off));
        }
    if (pass) {
        // row-min: reduce across tig-lanes (bits 0..1)
        #pragma unroll
        for (int off = 1; off <= 2; off <<= 1)
            #pragma unroll
            for (int mi = 0; mi < 4; mi++) {
                rmin[mi][0] = fminf(rmin[mi][0], __shfl_xor_sync(0xFFFFFFFFu, rmin[mi][0], off));
                rmin[mi][1] = fminf(rmin[mi][1], __shfl_xor_sync(0xFFFFFFFFu, rmin[mi][1], off));
            }
    }

    float* cbuf = (float*)smem;              // [2][128]
    float* rbuf = cbuf + 256;                // [128][2]
    if (lane < 4) {
        #pragma unroll
        for (int ni = 0; ni < 8; ni++) {
            const int col = wn * 64 + ni * 8 + 2 * lane;
            cbuf[wm * 128 + col]     = cmin[ni][0];
            cbuf[wm * 128 + col + 1] = cmin[ni][1];
        }
    }
    if (pass && tig == 0) {
        #pragma unroll
        for (int mi = 0; mi < 4; mi++) {
            const int r0 = wm * 64 + mi * 16 + g;     // unique (r, wn) per writer
            rbuf[r0 * 2 + wn]       = rmin[mi][0];
            rbuf[(r0 + 8) * 2 + wn] = rmin[mi][1];
        }
    }
    __syncthreads();

    {
        const float m = fminf(cbuf[tid], cbuf[128 + tid]);
        atomicMin(&colmin[j0 + tid], fkey(m));
    }
    if (pass) {
        const float m = fminf(rbuf[tid * 2], rbuf[tid * 2 + 1]);
        atomicMin(&colmin[i0 + tid], fkey(m));
    }
}

// ---------------- phase D: final scalar reductions ---------------------------
__global__ void finalize_kernel(float* __restrict__ out)
{
    __shared__ float s1[1024], s2[1024];
    const int t = threadIdx.x;
    float rsum = 0.f, ksum = 0.f;
    for (int j = t; j < BATCH; j += 1024) {
        rsum += g_recon[j];
        float rn = g_rnG[j];
        float wp = sqrtf(fmaxf(funkey(g_minP[j]) + rn, 0.f) + 1e-8f);
        float ww = sqrtf(fmaxf(funkey(g_minG[j]) + rn, 0.f) + 1e-8f);
        ksum += logf(wp / (ww + 1e-8f) + 1e-8f);
    }
    s1[t] = rsum; s2[t] = ksum;
    __syncthreads();
    for (int off = 512; off > 0; off >>= 1) {
        if (t < off) { s1[t] += s1[t + off]; s2[t] += s2[t + off]; }
        __syncthreads();
    }
    if (t == 0) {
        out[0] = s1[0] / (float)BATCH;
        out[1] = s2[0] / (float)BATCH * (float)DTOT
               + logf((float)BATCH / (float)(BATCH - 1));
    }
}

// ---------------- launch ------------------------------------------------------
extern "C" void kernel_launch(void* const* d_in, const int* in_sizes, int n_in,
                              void* d_out, int out_size)
{
    (void)in_sizes; (void)n_in; (void)out_size;
    const float* z     = (const float*)d_in[0];
    const float* znext = (const float*)d_in[1];
    const float* n     = (const float*)d_in[2];
    const float* prior = (const float*)d_in[3];
    const float* w1W = (const float*)d_in[4];  const float* w1b = (const float*)d_in[5];
    const float* b1W = (const float*)d_in[6];  const float* b1b = (const float*)d_in[7];
    const float* w2W = (const float*)d_in[8];  const float* w2b = (const float*)d_in[9];
    const float* b2W = (const float*)d_in[10]; const float* b2b = (const float*)d_in[11];
    const float* w3W = (const float*)d_in[12]; const float* w3b = (const float*)d_in[13];
    const float* b3W = (const float*)d_in[14]; const float* b3b = (const float*)d_in[15];
    float* out = (float*)d_out;

    cudaFuncSetAttribute(min_gemm_hmma_kernel,
                         cudaFuncAttributeMaxDynamicSharedMemorySize, SMEM_TOTAL);

    init_min_kernel<<<(BATCH + 255) / 256, 256>>>();
    build_G_decode_kernel<<<BATCH, 512>>>(
        n, z, znext, out,
        w1W, w1b, b1W, b1b, w2W, w2b, b2W, b2b, w3W, w3b, b3W, b3b);
    split_prior_kernel<<<BATCH, 256>>>(prior);

    min_gemm_hmma_kernel<<<NP0 + NP1, NTHR, SMEM_TOTAL>>>();

    finalize_kernel<<<1, 1024>>>(out);
}

// round 8
// speedup vs baseline: 2.9585x; 1.0027x over previous
#include <cuda_runtime.h>
#include <cuda_fp16.h>
#include <math.h>
#include <stdint.h>

#define BATCH 8192
#define DTOT  4611
#define KPAD  4672              // 73 * 64, zero-filled tail
#define NCHUNK (KPAD / 64)      // 73
#define TT 128                  // square CTA tile
#define TK 64
#define NTHR 128
#define NTILE (BATCH / TT)      // 64
#define NP0   (NTILE * NTILE)              // 4096 pass-0 tiles
#define NP1   (NTILE * (NTILE + 1) / 2)    // 2080 pass-1 (upper-tri) tiles
#define STAGE_BYTES 32768       // A 16KB + B 16KB
#define SMEM_TOTAL (3 * STAGE_BYTES)

// ---------------- static device scratch -------------------------------------
__device__ __half g_Gh[(size_t)BATCH * KPAD];   // fp16 G for MMA
__device__ __half g_Ph[(size_t)BATCH * KPAD];   // fp16 prior for MMA
__device__ float    g_rnG[BATCH];
__device__ float    g_rnP[BATCH];
__device__ unsigned g_minP[BATCH];
__device__ unsigned g_minG[BATCH];
__device__ float    g_recon[BATCH];

// monotone float<->uint key: atomicMin(uint) == min(float), exact+deterministic
__device__ __forceinline__ unsigned fkey(float f) {
    unsigned u = __float_as_uint(f);
    return (u & 0x80000000u) ? ~u : (u | 0x80000000u);
}
__device__ __forceinline__ float funkey(unsigned k) {
    unsigned u = (k & 0x80000000u) ? (k ^ 0x80000000u) : ~k;
    return __uint_as_float(u);
}

__device__ __forceinline__ uint32_t smem_u32(const void* p) {
    uint32_t a;
    asm("{ .reg .u64 t; cvta.to.shared.u64 t, %1; cvt.u32.u64 %0, t; }" : "=r"(a) : "l"(p));
    return a;
}

__device__ __forceinline__ void ldsm_x4(uint32_t& r0, uint32_t& r1, uint32_t& r2,
                                        uint32_t& r3, uint32_t addr) {
    asm volatile("ldmatrix.sync.aligned.m8n8.x4.shared.b16 {%0,%1,%2,%3}, [%4];"
                 : "=r"(r0), "=r"(r1), "=r"(r2), "=r"(r3) : "r"(addr));
}

__device__ __forceinline__ void mma16816(float* d, const uint32_t* a,
                                         uint32_t b0, uint32_t b1) {
    asm volatile("mma.sync.aligned.m16n8k16.row.col.f32.f16.f16.f32 "
                 "{%0,%1,%2,%3}, {%4,%5,%6,%7}, {%8,%9}, {%0,%1,%2,%3};"
                 : "+f"(d[0]), "+f"(d[1]), "+f"(d[2]), "+f"(d[3])
                 : "r"(a[0]), "r"(a[1]), "r"(a[2]), "r"(a[3]), "r"(b0), "r"(b1));
}

// ---------------- phase A: hypernetwork + norms + fused decode ---------------
__global__ __launch_bounds__(512)
void build_G_decode_kernel(const float* __restrict__ n,
                           const float* __restrict__ z,
                           const float* __restrict__ znext,
                           float* __restrict__ out,
                           const float* __restrict__ w1W, const float* __restrict__ w1b,
                           const float* __restrict__ b1W, const float* __restrict__ b1b,
                           const float* __restrict__ w2W, const float* __restrict__ w2b,
                           const float* __restrict__ b2W, const float* __restrict__ b2b,
                           const float* __restrict__ w3W, const float* __restrict__ w3b,
                           const float* __restrict__ b3W, const float* __restrict__ b3b)
{
    __shared__ float ns[25];
    __shared__ float row[KPAD];
    __shared__ float sm[512];
    __shared__ float h1[64], h2[64], zh[3];
    const int b = blockIdx.x;
    const int t = threadIdx.x;
    if (t < 25) ns[t] = n[b * 25 + t];
    __syncthreads();

    float s = 0.f;
    for (int c = t; c < KPAD; c += 512) {
        float val = 0.f;
        if (c < DTOT) {
            const float* W; const float* bias; int local, width;
            if      (c < 192)  { W = w1W; bias = w1b; local = c;        width = 192;  }
            else if (c < 256)  { W = b1W; bias = b1b; local = c - 192;  width = 64;   }
            else if (c < 4352) { W = w2W; bias = w2b; local = c - 256;  width = 4096; }
            else if (c < 4416) { W = b2W; bias = b2b; local = c - 4352; width = 64;   }
            else if (c < 4608) { W = w3W; bias = w3b; local = c - 4416; width = 192;  }
            else               { W = b3W; bias = b3b; local = c - 4608; width = 3;    }
            float acc = 0.f;
            #pragma unroll
            for (int k = 0; k < 25; k++) acc += ns[k] * W[k * width + local];
            val = acc + bias[local];
            s += val * val;
        }
        row[c] = val;
        g_Gh[(long)b * KPAD + c] = __float2half_rn(val);
    }
    sm[t] = s;
    __syncthreads();
    for (int off = 256; off > 0; off >>= 1) {
        if (t < off) sm[t] += sm[t + off];
        __syncthreads();
    }
    if (t == 0) g_rnG[b] = sm[0];

    // ---- decode MLP from smem row ----
    if (t < 64) {
        const float z0 = z[b * 3], z1 = z[b * 3 + 1], z2 = z[b * 3 + 2];
        float a = row[t * 3] * z0 + row[t * 3 + 1] * z1 + row[t * 3 + 2] * z2
                + row[192 + t];
        h1[t] = (a > 0.f) ? a : expm1f(a);
    }
    __syncthreads();
    if (t < 64) {
        float s2 = 0.f;
        #pragma unroll 8
        for (int jj = 0; jj < 64; jj++) {
            const int j = (jj + t) & 63;
            s2 += row[256 + t * 64 + j] * h1[j];
        }
        s2 += row[4352 + t];
        h2[t] = (s2 > 0.f) ? s2 : expm1f(s2);
    }
    __syncthreads();
    if (t < 3) {
        float s3 = 0.f;
        #pragma unroll 8
        for (int j = 0; j < 64; j++) s3 += row[4416 + t * 64 + j] * h2[j];
        s3 += row[4608 + t];
        out[2 + b * 3 + t] = s3;
        zh[t] = s3;
    }
    __syncthreads();
    if (t == 0) {
        float d0 = zh[0] - znext[b * 3];
        float d1 = zh[1] - znext[b * 3 + 1];
        float d2 = zh[2] - znext[b * 3 + 2];
        g_recon[b] = d0 * d0 + d1 * d1 + d2 * d2;
    }
}

__global__ __launch_bounds__(256)
void split_prior_kernel(const float* __restrict__ prior)
{
    __shared__ float sm[256];
    const int b = blockIdx.x;
    float s = 0.f;
    for (int c = threadIdx.x; c < KPAD; c += 256) {
        float val = 0.f;
        if (c < DTOT) { val = prior[(long)b * DTOT + c]; s += val * val; }
        g_Ph[(long)b * KPAD + c] = __float2half_rn(val);
    }
    sm[threadIdx.x] = s;
    __syncthreads();
    for (int off = 128; off > 0; off >>= 1) {
        if (threadIdx.x < off) sm[threadIdx.x] += sm[threadIdx.x + off];
        __syncthreads();
    }
    if (threadIdx.x == 0) g_rnP[b] = sm[0];
}

__global__ void init_min_kernel()
{
    int t = blockIdx.x * 256 + threadIdx.x;
    if (t < BATCH) { g_minP[t] = 0xFFFFFFFFu; g_minG[t] = 0xFFFFFFFFu; }
}

// ---------------- phase C: HMMA fused GEMM + min (both passes, one launch) ---
__device__ __forceinline__ void load_tile(uint32_t sbase, const __half* __restrict__ g,
                                          long row0, int k0, int tid)
{
    const int nunits = TT * 8;              // 1024 16B units, 128B per row
    #pragma unroll 8
    for (int u = tid; u < nunits; u += NTHR) {
        const int r = u >> 3, un = u & 7;
        const int sw = un ^ (r & 7);
        const void* src = g + (row0 + r) * (long)KPAD + k0 + un * 8;
        asm volatile("cp.async.cg.shared.global [%0], [%1], 16;"
                     :: "r"(sbase + (uint32_t)(r * 128 + sw * 16)), "l"(src) : "memory");
    }
}

#define LDF(B, KS)                                                              \
    { _Pragma("unroll") for (int mi = 0; mi < 4; mi++)                          \
        ldsm_x4(afr[B][mi][0], afr[B][mi][1], afr[B][mi][2], afr[B][mi][3],     \
                Ab + aoff[mi] + (uint32_t)((((KS) * 2 + ahalf) ^ asw[mi]) * 16)); \
      _Pragma("unroll") for (int nb = 0; nb < 4; nb++)                          \
        ldsm_x4(bfr[B][nb][0], bfr[B][nb][1], bfr[B][nb][2], bfr[B][nb][3],     \
                Bb + boff[nb] + (uint32_t)((((KS) * 2 + bhalf) ^ bsw[nb]) * 16)); }

#define MMAS(B)                                                                 \
    { _Pragma("unroll") for (int mi = 0; mi < 4; mi++)                          \
      _Pragma("unroll") for (int nb = 0; nb < 4; nb++) {                        \
          mma16816(d[mi][nb * 2],     afr[B][mi], bfr[B][nb][0], bfr[B][nb][1]); \
          mma16816(d[mi][nb * 2 + 1], afr[B][mi], bfr[B][nb][2], bfr[B][nb][3]); } }

// blockIdx.x < NP0: pass 0 tile (A = prior), colmin[j] = min_i (rnP[i]-2 P.G)
// else: pass 1 upper-tri tile (A = G, ib <= jb): col-min AND row-min folded,
//       diagonal masked.
__global__ __launch_bounds__(NTHR, 2)
void min_gemm_hmma_kernel()
{
    const int bid = blockIdx.x;
    const int pass = (bid >= NP0);
    int ib, jb;
    if (!pass) { ib = bid >> 6; jb = bid & 63; }
    else {
        const int t = bid - NP0;
        jb = (int)((sqrtf(8.f * (float)t + 1.f) - 1.f) * 0.5f);
        while ((jb + 1) * (jb + 2) / 2 <= t) jb++;
        while (jb * (jb + 1) / 2 > t) jb--;
        ib = t - jb * (jb + 1) / 2;
    }
    const long i0 = (long)ib * TT;
    const long j0 = (long)jb * TT;

    const __half* __restrict__ A  = pass ? g_Gh : g_Ph;
    const float* __restrict__ rnA = pass ? g_rnG : g_rnP;
    unsigned* colmin              = pass ? g_minG : g_minP;

    extern __shared__ char smem[];
    const uint32_t sb = smem_u32(smem);
    const int tid = threadIdx.x;
    const int lane = tid & 31;
    const int wid = tid >> 5;                // 0..3
    const int wm = wid >> 1;                 // 0..1  (M, 64 rows each)
    const int wn = wid & 1;                  // 0..1  (N, 64 cols each)

    float d[4][8][4];
    #pragma unroll
    for (int mi = 0; mi < 4; mi++)
        #pragma unroll
        for (int ni = 0; ni < 8; ni++)
            #pragma unroll
            for (int q = 0; q < 4; q++) d[mi][ni][q] = 0.f;

    // per-thread ldmatrix row bases
    int aoff[4], asw[4], boff[4], bsw[4];
    const int ahalf = (lane >> 4) & 1;
    const int bhalf = (lane >> 3) & 1;
    #pragma unroll
    for (int mi = 0; mi < 4; mi++) {
        int row = wm * 64 + mi * 16 + (lane & 7) + ((lane >> 3) & 1) * 8;
        aoff[mi] = row * 128; asw[mi] = row & 7;
    }
    #pragma unroll
    for (int nb = 0; nb < 4; nb++) {
        int row = wn * 64 + nb * 16 + (lane & 7) + ((lane >> 4) & 1) * 8;
        boff[nb] = row * 128; bsw[nb] = row & 7;
    }

    // prologue: chunks 0,1 into stages 0,1
    load_tile(sb,                       A,    i0, 0,  tid);
    load_tile(sb + 16384,               g_Gh, j0, 0,  tid);
    asm volatile("cp.async.commit_group;" ::: "memory");
    load_tile(sb + STAGE_BYTES,         A,    i0, TK, tid);
    load_tile(sb + STAGE_BYTES + 16384, g_Gh, j0, TK, tid);
    asm volatile("cp.async.commit_group;" ::: "memory");

    // single-sync pipeline:
    //   wait for chunk c's data -> barrier (proves all warps done with c-1's
    //   mma, so stage (c+2)%3 == (c-1)%3 is reusable) -> issue loads for c+2
    //   -> mma on stage c%3. One __syncthreads per chunk.
    int stage = 0, next = 2;
    for (int c = 0; c < NCHUNK; c++) {
        if (c + 1 < NCHUNK) {
            asm volatile("cp.async.wait_group 1;" ::: "memory");
        } else {
            asm volatile("cp.async.wait_group 0;" ::: "memory");
        }
        __syncthreads();

        if (c + 2 < NCHUNK) {
            const uint32_t sn = sb + (uint32_t)next * STAGE_BYTES;
            load_tile(sn,         A,    i0, (c + 2) * TK, tid);
            load_tile(sn + 16384, g_Gh, j0, (c + 2) * TK, tid);
            asm volatile("cp.async.commit_group;" ::: "memory");
        }

        const uint32_t Ab = sb + (uint32_t)stage * STAGE_BYTES;
        const uint32_t Bb = Ab + 16384;

        // double-buffered fragment pipeline over the 4 k16 steps
        uint32_t afr[2][4][4], bfr[2][4][4];
        LDF(0, 0)
        LDF(1, 1)
        MMAS(0)
        LDF(0, 2)
        MMAS(1)
        LDF(1, 3)
        MMAS(0)
        MMAS(1)

        stage = (stage + 1) % 3;
        next  = (next + 1) % 3;
    }
    __syncthreads();      // protect smem reuse by the epilogue buffers

    // ---------------- epilogue ------------------------------------------------
    const int g = lane >> 2, tig = lane & 3;
    float cmin[8][2];
    #pragma unroll
    for (int ni = 0; ni < 8; ni++) { cmin[ni][0] = 1e30f; cmin[ni][1] = 1e30f; }
    float rmin[4][2];
    #pragma unroll
    for (int mi = 0; mi < 4; mi++) { rmin[mi][0] = 1e30f; rmin[mi][1] = 1e30f; }

    float rnj0[8], rnj1[8];
    if (pass) {
        #pragma unroll
        for (int ni = 0; ni < 8; ni++) {
            const long jg = j0 + wn * 64 + ni * 8 + 2 * tig;
            rnj0[ni] = g_rnG[jg];
            rnj1[ni] = g_rnG[jg + 1];
        }
    }

    #pragma unroll
    for (int mi = 0; mi < 4; mi++) {
        const long ig0 = i0 + wm * 64 + mi * 16 + g;
        const long ig1 = ig0 + 8;
        const float rn0 = rnA[ig0];
        const float rn1 = rnA[ig1];
        #pragma unroll
        for (int ni = 0; ni < 8; ni++) {
            const float d0 = d[mi][ni][0], d1 = d[mi][ni][1];
            const float d2 = d[mi][ni][2], d3 = d[mi][ni][3];
            float v0 = fmaf(-2.f, d0, rn0);
            float v1 = fmaf(-2.f, d1, rn0);
            float v2 = fmaf(-2.f, d2, rn1);
            float v3 = fmaf(-2.f, d3, rn1);
            if (pass) {
                const long jg = j0 + wn * 64 + ni * 8 + 2 * tig;
                float w0 = fmaf(-2.f, d0, rnj0[ni]);
                float w1 = fmaf(-2.f, d1, rnj1[ni]);
                float w2 = fmaf(-2.f, d2, rnj0[ni]);
                float w3 = fmaf(-2.f, d3, rnj1[ni]);
                if (ig0 == jg)     { v0 = 1e30f; w0 = 1e30f; }
                if (ig0 == jg + 1) { v1 = 1e30f; w1 = 1e30f; }
                if (ig1 == jg)     { v2 = 1e30f; w2 = 1e30f; }
                if (ig1 == jg + 1) { v3 = 1e30f; w3 = 1e30f; }
                rmin[mi][0] = fminf(rmin[mi][0], fminf(w0, w1));
                rmin[mi][1] = fminf(rmin[mi][1], fminf(w2, w3));
            }
            cmin[ni][0] = fminf(cmin[ni][0], fminf(v0, v2));
            cmin[ni][1] = fminf(cmin[ni][1], fminf(v1, v3));
        }
    }

    // column-min: reduce across g-lanes (bits 2..4)
    #pragma unroll
    for (int off = 4; off <= 16; off <<= 1)
        #pragma unroll
        for (int ni = 0; ni < 8; ni++) {
            cmin[ni][0] = fminf(cmin[ni][0], __shfl_xor_sync(0xFFFFFFFFu, cmin[ni][0], off));
            cmin[ni][1] = fminf(cmin[ni][1], __shfl_xor_sync(0xFFFFFFFFu, cmin[ni][1], off));
        }
    if (pass) {
        // row-min: reduce across tig-lanes (bits 0..1)
        #pragma unroll
        for (int off = 1; off <= 2; off <<= 1)
            #pragma unroll
            for (int mi = 0; mi < 4; mi++) {
                rmin[mi][0] = fminf(rmin[mi][0], __shfl_xor_sync(0xFFFFFFFFu, rmin[mi][0], off));
                rmin[mi][1] = fminf(rmin[mi][1], __shfl_xor_sync(0xFFFFFFFFu, rmin[mi][1], off));
            }
    }

    float* cbuf = (float*)smem;              // [2][128]
    float* rbuf = cbuf + 256;                // [128][2]
    if (lane < 4) {
        #pragma unroll
        for (int ni = 0; ni < 8; ni++) {
            const int col = wn * 64 + ni * 8 + 2 * lane;
            cbuf[wm * 128 + col]     = cmin[ni][0];
            cbuf[wm * 128 + col + 1] = cmin[ni][1];
        }
    }
    if (pass && tig == 0) {
        #pragma unroll
        for (int mi = 0; mi < 4; mi++) {
            const int r0 = wm * 64 + mi * 16 + g;     // unique (r, wn) per writer
            rbuf[r0 * 2 + wn]       = rmin[mi][0];
            rbuf[(r0 + 8) * 2 + wn] = rmin[mi][1];
        }
    }
    __syncthreads();

    {
        const float m = fminf(cbuf[tid], cbuf[128 + tid]);
        atomicMin(&colmin[j0 + tid], fkey(m));
    }
    if (pass) {
        const float m = fminf(rbuf[tid * 2], rbuf[tid * 2 + 1]);
        atomicMin(&colmin[i0 + tid], fkey(m));
    }
}

// ---------------- phase D: final scalar reductions ---------------------------
__global__ void finalize_kernel(float* __restrict__ out)
{
    __shared__ float s1[1024], s2[1024];
    const int t = threadIdx.x;
    float rsum = 0.f, ksum = 0.f;
    for (int j = t; j < BATCH; j += 1024) {
        rsum += g_recon[j];
        float rn = g_rnG[j];
        float wp = sqrtf(fmaxf(funkey(g_minP[j]) + rn, 0.f) + 1e-8f);
        float ww = sqrtf(fmaxf(funkey(g_minG[j]) + rn, 0.f) + 1e-8f);
        ksum += logf(wp / (ww + 1e-8f) + 1e-8f);
    }
    s1[t] = rsum; s2[t] = ksum;
    __syncthreads();
    for (int off = 512; off > 0; off >>= 1) {
        if (t < off) { s1[t] += s1[t + off]; s2[t] += s2[t + off]; }
        __syncthreads();
    }
    if (t == 0) {
        out[0] = s1[0] / (float)BATCH;
        out[1] = s2[0] / (float)BATCH * (float)DTOT
               + logf((float)BATCH / (float)(BATCH - 1));
    }
}

// ---------------- launch ------------------------------------------------------
extern "C" void kernel_launch(void* const* d_in, const int* in_sizes, int n_in,
                              void* d_out, int out_size)
{
    (void)in_sizes; (void)n_in; (void)out_size;
    const float* z     = (const float*)d_in[0];
    const float* znext = (const float*)d_in[1];
    const float* n     = (const float*)d_in[2];
    const float* prior = (const float*)d_in[3];
    const float* w1W = (const float*)d_in[4];  const float* w1b = (const float*)d_in[5];
    const float* b1W = (const float*)d_in[6];  const float* b1b = (const float*)d_in[7];
    const float* w2W = (const float*)d_in[8];  const float* w2b = (const float*)d_in[9];
    const float* b2W = (const float*)d_in[10]; const float* b2b = (const float*)d_in[11];
    const float* w3W = (const float*)d_in[12]; const float* w3b = (const float*)d_in[13];
    const float* b3W = (const float*)d_in[14]; const float* b3b = (const float*)d_in[15];
    float* out = (float*)d_out;

    cudaFuncSetAttribute(min_gemm_hmma_kernel,
                         cudaFuncAttributeMaxDynamicSharedMemorySize, SMEM_TOTAL);

    init_min_kernel<<<(BATCH + 255) / 256, 256>>>();
    build_G_decode_kernel<<<BATCH, 512>>>(
        n, z, znext, out,
        w1W, w1b, b1W, b1b, w2W, w2b, b2W, b2b, w3W, w3b, b3W, b3b);
    split_prior_kernel<<<BATCH, 256>>>(prior);

    min_gemm_hmma_kernel<<<NP0 + NP1, NTHR, SMEM_TOTAL>>>();

    finalize_kernel<<<1, 1024>>>(out);
}

// round 9
// speedup vs baseline: 10.9331x; 3.6955x over previous
#include <cuda_runtime.h>
#include <math.h>
#include <stdint.h>

#define BATCH 8192
#define DTOT  4611
#define RK    26               // rank of G: 25 noise dims + bias

// ---------------- static device scratch -------------------------------------
__device__ float g_Wp[RK * DTOT];      // W' (26 x 4611)
__device__ float g_M[RK * RK];         // W' W'^T
__device__ float g_Pp[(size_t)BATCH * RK];   // prior @ W'^T
__device__ float g_Np[(size_t)BATCH * RK];   // n' = [n, 1]
__device__ float g_U[(size_t)BATCH * RK];    // N' M
__device__ float    g_rnP[BATCH];
__device__ float    g_rnG[BATCH];
__device__ unsigned g_minP[BATCH];
__device__ unsigned g_minG[BATCH];
__device__ float    g_recon[BATCH];

// monotone float<->uint key: atomicMin(uint) == min(float), exact+deterministic
__device__ __forceinline__ unsigned fkey(float f) {
    unsigned u = __float_as_uint(f);
    return (u & 0x80000000u) ? ~u : (u | 0x80000000u);
}
__device__ __forceinline__ float funkey(unsigned k) {
    unsigned u = (k & 0x80000000u) ? (k ^ 0x80000000u) : ~k;
    return __uint_as_float(u);
}

__global__ void init_min_kernel()
{
    int t = blockIdx.x * 256 + threadIdx.x;
    if (t < BATCH) { g_minP[t] = 0xFFFFFFFFu; g_minG[t] = 0xFFFFFFFFu; }
}

// ---------------- build W' (26 x 4611) --------------------------------------
__global__ void build_Wp_kernel(const float* __restrict__ w1W, const float* __restrict__ w1b,
                                const float* __restrict__ b1W, const float* __restrict__ b1b,
                                const float* __restrict__ w2W, const float* __restrict__ w2b,
                                const float* __restrict__ b2W, const float* __restrict__ b2b,
                                const float* __restrict__ w3W, const float* __restrict__ w3b,
                                const float* __restrict__ b3W, const float* __restrict__ b3b)
{
    const int c = blockIdx.x * 256 + threadIdx.x;
    if (c >= DTOT) return;
    const float* W; const float* bias; int local, width;
    if      (c < 192)  { W = w1W; bias = w1b; local = c;        width = 192;  }
    else if (c < 256)  { W = b1W; bias = b1b; local = c - 192;  width = 64;   }
    else if (c < 4352) { W = w2W; bias = w2b; local = c - 256;  width = 4096; }
    else if (c < 4416) { W = b2W; bias = b2b; local = c - 4352; width = 64;   }
    else if (c < 4608) { W = w3W; bias = w3b; local = c - 4416; width = 192;  }
    else               { W = b3W; bias = b3b; local = c - 4608; width = 3;    }
    #pragma unroll
    for (int k = 0; k < 25; k++) g_Wp[k * DTOT + c] = W[k * width + local];
    g_Wp[25 * DTOT + c] = bias[local];
}

// ---------------- M = W' W'^T (26 x 26) --------------------------------------
__global__ void compute_M_kernel()
{
    __shared__ float sm[128];
    const int a = blockIdx.x / RK;
    const int b = blockIdx.x % RK;
    const float* ra = g_Wp + (long)a * DTOT;
    const float* rb = g_Wp + (long)b * DTOT;
    float s = 0.f;
    for (int c = threadIdx.x; c < DTOT; c += 128) s += ra[c] * rb[c];
    sm[threadIdx.x] = s;
    __syncthreads();
    for (int off = 64; off > 0; off >>= 1) {
        if (threadIdx.x < off) sm[threadIdx.x] += sm[threadIdx.x + off];
        __syncthreads();
    }
    if (threadIdx.x == 0) g_M[a * RK + b] = sm[0];
}

// ---------------- N', U = N'M, rnG -------------------------------------------
__global__ void np_u_kernel(const float* __restrict__ n)
{
    __shared__ float Ms[RK * RK];
    for (int idx = threadIdx.x; idx < RK * RK; idx += 256) Ms[idx] = g_M[idx];
    __syncthreads();
    const long s = (long)blockIdx.x * 256 + threadIdx.x;
    float np[RK];
    #pragma unroll
    for (int k = 0; k < 25; k++) np[k] = n[s * 25 + k];
    np[25] = 1.f;
    float rn = 0.f;
    #pragma unroll
    for (int a = 0; a < RK; a++) {
        float u = 0.f;
        #pragma unroll
        for (int b = 0; b < RK; b++) u += np[b] * Ms[b * RK + a];
        g_U[s * RK + a]  = u;
        g_Np[s * RK + a] = np[a];
        rn += u * np[a];
    }
    g_rnG[s] = rn;
}

// ---------------- P' = prior @ W'^T and rnP ----------------------------------
#define PP_ROWS 64
#define PP_KC   128
__global__ __launch_bounds__(256)
void pp_kernel(const float* __restrict__ prior)
{
    __shared__ float sp[PP_ROWS * 129];
    __shared__ float sw[RK * PP_KC];
    const int t = threadIdx.x;
    const long row0 = (long)blockIdx.x * PP_ROWS;
    const int r = t & 63, grp = t >> 6;     // grp uniform per warp
    float acc[7];
    #pragma unroll
    for (int m = 0; m < 7; m++) acc[m] = 0.f;

    for (int k0 = 0; k0 < DTOT; k0 += PP_KC) {
        for (int idx = t; idx < PP_ROWS * PP_KC; idx += 256) {
            const int rr = idx >> 7, c = idx & 127;
            sp[rr * 129 + c] = (k0 + c < DTOT) ? prior[(row0 + rr) * DTOT + k0 + c] : 0.f;
        }
        for (int idx = t; idx < RK * PP_KC; idx += 256) {
            const int a = idx >> 7, c = idx & 127;
            sw[a * PP_KC + c] = (k0 + c < DTOT) ? g_Wp[(long)a * DTOT + k0 + c] : 0.f;
        }
        __syncthreads();
        if (grp < 3) {
            #pragma unroll 4
            for (int c = 0; c < PP_KC; c++) {
                const float v = sp[r * 129 + c];
                #pragma unroll
                for (int m = 0; m < 7; m++)
                    acc[m] = fmaf(v, sw[(grp * 7 + m) * PP_KC + c], acc[m]);
            }
        } else {
            #pragma unroll 4
            for (int c = 0; c < PP_KC; c++) {
                const float v = sp[r * 129 + c];
                #pragma unroll
                for (int m = 0; m < 5; m++)
                    acc[m] = fmaf(v, sw[(21 + m) * PP_KC + c], acc[m]);
                acc[5] = fmaf(v, v, acc[5]);
            }
        }
        __syncthreads();
    }
    if (grp < 3) {
        #pragma unroll
        for (int m = 0; m < 7; m++) g_Pp[(row0 + r) * RK + grp * 7 + m] = acc[m];
    } else {
        #pragma unroll
        for (int m = 0; m < 5; m++) g_Pp[(row0 + r) * RK + 21 + m] = acc[m];
        g_rnP[row0 + r] = acc[5];
    }
}

// ---------------- fused K=26 GEMM + min (both passes, one launch) ------------
#define MT 128
#define NTILE (BATCH / MT)                 // 64
#define NP0 (NTILE * NTILE)                // 4096
#define NP1 (NTILE * (NTILE + 1) / 2)      // 2080

__global__ __launch_bounds__(256, 2)
void minmin_kernel()
{
    __shared__ float At[RK * 132];
    __shared__ float Bt[RK * 132];
    __shared__ float rnA[MT], rnB[MT];

    const int bid = blockIdx.x;
    const int pass = (bid >= NP0);
    int ib, jb;
    if (!pass) { ib = bid >> 6; jb = bid & 63; }
    else {
        const int t0 = bid - NP0;
        jb = (int)((sqrtf(8.f * (float)t0 + 1.f) - 1.f) * 0.5f);
        while ((jb + 1) * (jb + 2) / 2 <= t0) jb++;
        while (jb * (jb + 1) / 2 > t0) jb--;
        ib = t0 - jb * (jb + 1) / 2;
    }
    const long i0 = (long)ib * MT;
    const long j0 = (long)jb * MT;
    const float* __restrict__ Asrc = pass ? g_U : g_Pp;
    const float* __restrict__ rnAs = pass ? g_rnG : g_rnP;
    unsigned* colmin                = pass ? g_minG : g_minP;

    const int t = threadIdx.x;
    const int tx = t & 15, ty = t >> 4;

    for (int idx = t; idx < MT * RK; idx += 256) {
        const int i = idx / RK, k = idx % RK;
        At[k * 132 + i] = Asrc[i0 * RK + idx];          // coalesced global read
        Bt[k * 132 + i] = g_Np[j0 * RK + idx];
    }
    if (t < MT) rnA[t] = rnAs[i0 + t];
    else if (pass && t < 2 * MT) rnB[t - MT] = g_rnG[j0 + (t - MT)];
    __syncthreads();

    // 8x8 accumulators as f32x2 pairs (j-columns paired)
    unsigned long long acc[8][4];
    #pragma unroll
    for (int u = 0; u < 8; u++)
        #pragma unroll
        for (int p = 0; p < 4; p++) acc[u][p] = 0ULL;

    #pragma unroll
    for (int k = 0; k < RK; k++) {
        const float4 a0 = *reinterpret_cast<const float4*>(&At[k * 132 + ty * 8]);
        const float4 a1 = *reinterpret_cast<const float4*>(&At[k * 132 + ty * 8 + 4]);
        const float4 b0 = *reinterpret_cast<const float4*>(&Bt[k * 132 + tx * 8]);
        const float4 b1 = *reinterpret_cast<const float4*>(&Bt[k * 132 + tx * 8 + 4]);
        unsigned long long bb[4];
        asm("mov.b64 %0, {%1, %2};" : "=l"(bb[0]) : "f"(b0.x), "f"(b0.y));
        asm("mov.b64 %0, {%1, %2};" : "=l"(bb[1]) : "f"(b0.z), "f"(b0.w));
        asm("mov.b64 %0, {%1, %2};" : "=l"(bb[2]) : "f"(b1.x), "f"(b1.y));
        asm("mov.b64 %0, {%1, %2};" : "=l"(bb[3]) : "f"(b1.z), "f"(b1.w));
        const float av8[8] = {a0.x, a0.y, a0.z, a0.w, a1.x, a1.y, a1.z, a1.w};
        #pragma unroll
        for (int u = 0; u < 8; u++) {
            unsigned long long aa;
            asm("mov.b64 %0, {%1, %1};" : "=l"(aa) : "f"(av8[u]));
            #pragma unroll
            for (int p = 0; p < 4; p++)
                asm("fma.rn.f32x2 %0, %1, %2, %0;"
                    : "+l"(acc[u][p]) : "l"(aa), "l"(bb[p]));
        }
    }
    __syncthreads();     // done reading At/Bt; reuse them as reduce buffers

    float vmin[8], rmin[8];
    #pragma unroll
    for (int q = 0; q < 8; q++) { vmin[q] = 1e30f; rmin[q] = 1e30f; }

    #pragma unroll
    for (int u = 0; u < 8; u++) {
        const long ig = i0 + ty * 8 + u;
        const float rn = rnA[ty * 8 + u];
        #pragma unroll
        for (int p = 0; p < 4; p++) {
            float lo, hi;
            asm("mov.b64 {%0, %1}, %2;" : "=f"(lo), "=f"(hi) : "l"(acc[u][p]));
            float v0 = fmaf(-2.f, lo, rn);
            float v1 = fmaf(-2.f, hi, rn);
            if (pass) {
                const long jg = j0 + tx * 8 + 2 * p;
                float w0 = fmaf(-2.f, lo, rnB[tx * 8 + 2 * p]);
                float w1 = fmaf(-2.f, hi, rnB[tx * 8 + 2 * p + 1]);
                if (ig == jg)     { v0 = 1e30f; w0 = 1e30f; }
                if (ig == jg + 1) { v1 = 1e30f; w1 = 1e30f; }
                rmin[u] = fminf(rmin[u], fminf(w0, w1));
            }
            vmin[2 * p]     = fminf(vmin[2 * p], v0);
            vmin[2 * p + 1] = fminf(vmin[2 * p + 1], v1);
        }
    }

    float* redc = At;     // 16 x 128
    float* redr = Bt;     // 16 x 128
    #pragma unroll
    for (int c = 0; c < 8; c++) redc[ty * 128 + tx * 8 + c] = vmin[c];
    if (pass) {
        #pragma unroll
        for (int u = 0; u < 8; u++) redr[tx * 128 + ty * 8 + u] = rmin[u];
    }
    __syncthreads();
    if (t < MT) {
        float m = redc[t];
        #pragma unroll
        for (int q = 1; q < 16; q++) m = fminf(m, redc[q * 128 + t]);
        atomicMin(&colmin[j0 + t], fkey(m));
        if (pass) {
            float m2 = redr[t];
            #pragma unroll
            for (int q = 1; q < 16; q++) m2 = fminf(m2, redr[q * 128 + t]);
            atomicMin(&colmin[i0 + t], fkey(m2));
        }
    }
}

// ---------------- batched decode (64 samples / block) -------------------------
#define DS 64
#define DEC_SMEM_FLOATS (64*26 + 64*4 + 64*65 + 64*65 + 4096 + 25*192 + 192 + 25*64 + 64 + 192)
__global__ __launch_bounds__(256)
void decode_batch_kernel(const float* __restrict__ n,
                         const float* __restrict__ z,
                         const float* __restrict__ znext,
                         float* __restrict__ out,
                         const float* __restrict__ w1W, const float* __restrict__ w1b,
                         const float* __restrict__ b1W, const float* __restrict__ b1b,
                         const float* __restrict__ w2W, const float* __restrict__ w2b,
                         const float* __restrict__ b2W, const float* __restrict__ b2b,
                         const float* __restrict__ w3W, const float* __restrict__ w3b,
                         const float* __restrict__ b3W, const float* __restrict__ b3b)
{
    extern __shared__ float smf[];
    float* nn   = smf;                 // 64*26
    float* z3   = nn + 64 * 26;        // 64*4
    float* h1   = z3 + 64 * 4;         // 64*65
    float* h2   = h1 + 64 * 65;        // 64*65
    float* w2r  = h2 + 64 * 65;        // 4096
    float* s1W  = w2r + 4096;          // 25*192
    float* s1b  = s1W + 25 * 192;      // 192
    float* sb1W = s1b + 192;           // 25*64
    float* sb1b = sb1W + 25 * 64;      // 64
    float* zh   = sb1b + 64;           // 192

    const int t = threadIdx.x;
    const long b0 = (long)blockIdx.x * DS;

    for (int idx = t; idx < 64 * 25; idx += 256) {
        const int s = idx / 25, k = idx % 25;
        nn[s * 26 + k] = n[(b0 + s) * 25 + k];
    }
    for (int idx = t; idx < 64 * 3; idx += 256)
        z3[(idx / 3) * 4 + (idx % 3)] = z[b0 * 3 + idx];
    for (int idx = t; idx < 25 * 192; idx += 256) s1W[idx] = w1W[idx];
    for (int idx = t; idx < 192; idx += 256) s1b[idx] = w1b[idx];
    for (int idx = t; idx < 25 * 64; idx += 256) sb1W[idx] = b1W[idx];
    for (int idx = t; idx < 64; idx += 256) sb1b[idx] = b1b[idx];
    __syncthreads();

    // stage A: h1
    for (int idx = t; idx < 4096; idx += 256) {
        const int s = idx >> 6, u = idx & 63;
        const float z0 = z3[s * 4], z1 = z3[s * 4 + 1], z2 = z3[s * 4 + 2];
        float acc = sb1b[u] + s1b[u * 3] * z0 + s1b[u * 3 + 1] * z1 + s1b[u * 3 + 2] * z2;
        #pragma unroll
        for (int k = 0; k < 25; k++)
            acc += nn[s * 26 + k] * (s1W[k * 192 + u * 3] * z0
                                   + s1W[k * 192 + u * 3 + 1] * z1
                                   + s1W[k * 192 + u * 3 + 2] * z2
                                   + sb1W[k * 64 + u]);
        h1[s * 65 + u] = (acc > 0.f) ? acc : expm1f(acc);
    }
    __syncthreads();

    // stage B: h2 — each thread owns (s, 16 i's); w2W streamed through smem
    const int s = t & 63, ig = t >> 6;
    float acc[16];
    #pragma unroll
    for (int m = 0; m < 16; m++) acc[m] = 0.f;

    for (int k = 0; k < 26; k++) {
        const float* src = (k < 25) ? (w2W + (long)k * 4096) : w2b;
        __syncthreads();
        for (int q = t; q < 1024; q += 256)
            reinterpret_cast<float4*>(w2r)[q] = reinterpret_cast<const float4*>(src)[q];
        __syncthreads();
        const float coef = (k < 25) ? nn[s * 26 + k] : 1.f;
        float tk[16];
        #pragma unroll
        for (int m = 0; m < 16; m++) tk[m] = 0.f;
        for (int j = 0; j < 64; j++) {
            const float lh = h1[s * 65 + j];
            const int base = ig * 1024 + j;
            #pragma unroll
            for (int m = 0; m < 16; m++) tk[m] = fmaf(w2r[base + m * 64], lh, tk[m]);
        }
        #pragma unroll
        for (int m = 0; m < 16; m++) acc[m] = fmaf(coef, tk[m], acc[m]);
    }
    #pragma unroll
    for (int m = 0; m < 16; m++) {
        const int i = ig * 16 + m;
        float b2 = b2b[i];
        #pragma unroll
        for (int k = 0; k < 25; k++) b2 += nn[s * 26 + k] * b2W[k * 64 + i];
        const float v = acc[m] + b2;
        h2[s * 65 + i] = (v > 0.f) ? v : expm1f(v);
    }
    __syncthreads();

    // stage C: z_hat (192 outputs)
    if (t < 192) {
        const int ss = t / 3, d = t % 3;
        float a3 = b3b[d];
        #pragma unroll
        for (int k = 0; k < 25; k++) a3 += nn[ss * 26 + k] * b3W[k * 3 + d];
        for (int k = 0; k < 26; k++) {
            const float* row = (k < 25) ? (w3W + (long)k * 192 + d * 64) : (w3b + d * 64);
            const float coef = (k < 25) ? nn[ss * 26 + k] : 1.f;
            float tk = 0.f;
            #pragma unroll 8
            for (int j = 0; j < 64; j++) tk = fmaf(row[j], h2[ss * 65 + j], tk);
            a3 = fmaf(coef, tk, a3);
        }
        out[2 + (b0 + ss) * 3 + d] = a3;
        zh[ss * 3 + d] = a3;
    }
    __syncthreads();
    if (t < 64) {
        const float d0 = zh[t * 3]     - znext[(b0 + t) * 3];
        const float d1 = zh[t * 3 + 1] - znext[(b0 + t) * 3 + 1];
        const float d2 = zh[t * 3 + 2] - znext[(b0 + t) * 3 + 2];
        g_recon[b0 + t] = d0 * d0 + d1 * d1 + d2 * d2;
    }
}

// ---------------- final scalar reductions -------------------------------------
__global__ void finalize_kernel(float* __restrict__ out)
{
    __shared__ float s1[1024], s2[1024];
    const int t = threadIdx.x;
    float rsum = 0.f, ksum = 0.f;
    for (int j = t; j < BATCH; j += 1024) {
        rsum += g_recon[j];
        float rn = g_rnG[j];
        float wp = sqrtf(fmaxf(funkey(g_minP[j]) + rn, 0.f) + 1e-8f);
        float ww = sqrtf(fmaxf(funkey(g_minG[j]) + rn, 0.f) + 1e-8f);
        ksum += logf(wp / (ww + 1e-8f) + 1e-8f);
    }
    s1[t] = rsum; s2[t] = ksum;
    __syncthreads();
    for (int off = 512; off > 0; off >>= 1) {
        if (t < off) { s1[t] += s1[t + off]; s2[t] += s2[t + off]; }
        __syncthreads();
    }
    if (t == 0) {
        out[0] = s1[0] / (float)BATCH;
        out[1] = s2[0] / (float)BATCH * (float)DTOT
               + logf((float)BATCH / (float)(BATCH - 1));
    }
}

// ---------------- launch -------------------------------------------------------
extern "C" void kernel_launch(void* const* d_in, const int* in_sizes, int n_in,
                              void* d_out, int out_size)
{
    (void)in_sizes; (void)n_in; (void)out_size;
    const float* z     = (const float*)d_in[0];
    const float* znext = (const float*)d_in[1];
    const float* n     = (const float*)d_in[2];
    const float* prior = (const float*)d_in[3];
    const float* w1W = (const float*)d_in[4];  const float* w1b = (const float*)d_in[5];
    const float* b1W = (const float*)d_in[6];  const float* b1b = (const float*)d_in[7];
    const float* w2W = (const float*)d_in[8];  const float* w2b = (const float*)d_in[9];
    const float* b2W = (const float*)d_in[10]; const float* b2b = (const float*)d_in[11];
    const float* w3W = (const float*)d_in[12]; const float* w3b = (const float*)d_in[13];
    const float* b3W = (const float*)d_in[14]; const float* b3b = (const float*)d_in[15];
    float* out = (float*)d_out;

    cudaFuncSetAttribute(decode_batch_kernel,
                         cudaFuncAttributeMaxDynamicSharedMemorySize,
                         DEC_SMEM_FLOATS * (int)sizeof(float));

    init_min_kernel<<<(BATCH + 255) / 256, 256>>>();
    build_Wp_kernel<<<(DTOT + 255) / 256, 256>>>(
        w1W, w1b, b1W, b1b, w2W, w2b, b2W, b2b, w3W, w3b, b3W, b3b);
    compute_M_kernel<<<RK * RK, 128>>>();
    np_u_kernel<<<BATCH / 256, 256>>>(n);
    pp_kernel<<<BATCH / PP_ROWS, 256>>>(prior);
    decode_batch_kernel<<<BATCH / DS, 256, DEC_SMEM_FLOATS * sizeof(float)>>>(
        n, z, znext, out,
        w1W, w1b, b1W, b1b, w2W, w2b, b2W, b2b, w3W, w3b, b3W, b3b);

    minmin_kernel<<<NP0 + NP1, 256>>>();

    finalize_kernel<<<1, 1024>>>(out);
}

// round 10
// speedup vs baseline: 12.8879x; 1.1788x over previous
#include <cuda_runtime.h>
#include <math.h>
#include <stdint.h>

#define BATCH 8192
#define DTOT  4611
#define RK    26               // rank of G: 25 noise dims + bias

// ---------------- static device scratch -------------------------------------
__device__ float g_Wp[RK * DTOT];      // W' (26 x 4611)
__device__ float g_M[RK * RK];         // W' W'^T
__device__ float g_Pp[(size_t)BATCH * RK];   // prior @ W'^T
__device__ float g_Np[(size_t)BATCH * RK];   // n' = [n, 1]
__device__ float g_U[(size_t)BATCH * RK];    // N' M
__device__ float    g_rnP[BATCH];
__device__ float    g_rnG[BATCH];
__device__ unsigned g_minP[BATCH];
__device__ unsigned g_minG[BATCH];
__device__ float    g_recon[BATCH];

__device__ __forceinline__ unsigned fkey(float f) {
    unsigned u = __float_as_uint(f);
    return (u & 0x80000000u) ? ~u : (u | 0x80000000u);
}
__device__ __forceinline__ float funkey(unsigned k) {
    unsigned u = (k & 0x80000000u) ? (k ^ 0x80000000u) : ~k;
    return __uint_as_float(u);
}

// ---------------- K1: build W' + init mins -----------------------------------
__global__ void build_Wp_kernel(const float* __restrict__ w1W, const float* __restrict__ w1b,
                                const float* __restrict__ b1W, const float* __restrict__ b1b,
                                const float* __restrict__ w2W, const float* __restrict__ w2b,
                                const float* __restrict__ b2W, const float* __restrict__ b2b,
                                const float* __restrict__ w3W, const float* __restrict__ w3b,
                                const float* __restrict__ b3W, const float* __restrict__ b3b)
{
    const int c = blockIdx.x * 256 + threadIdx.x;          // grid 32 x 256 = 8192
    if (c < BATCH) { g_minP[c] = 0xFFFFFFFFu; g_minG[c] = 0xFFFFFFFFu; }
    if (c >= DTOT) return;
    const float* W; const float* bias; int local, width;
    if      (c < 192)  { W = w1W; bias = w1b; local = c;        width = 192;  }
    else if (c < 256)  { W = b1W; bias = b1b; local = c - 192;  width = 64;   }
    else if (c < 4352) { W = w2W; bias = w2b; local = c - 256;  width = 4096; }
    else if (c < 4416) { W = b2W; bias = b2b; local = c - 4352; width = 64;   }
    else if (c < 4608) { W = w3W; bias = w3b; local = c - 4416; width = 192;  }
    else               { W = b3W; bias = b3b; local = c - 4608; width = 3;    }
    #pragma unroll
    for (int k = 0; k < 25; k++) g_Wp[k * DTOT + c] = W[k * width + local];
    g_Wp[25 * DTOT + c] = bias[local];
}

// ---------------- K2: M = W' W'^T (26 x 26) -----------------------------------
__global__ void compute_M_kernel()
{
    __shared__ float sm[128];
    const int a = blockIdx.x / RK;
    const int b = blockIdx.x % RK;
    const float* ra = g_Wp + (long)a * DTOT;
    const float* rb = g_Wp + (long)b * DTOT;
    float s = 0.f;
    for (int c = threadIdx.x; c < DTOT; c += 128) s += ra[c] * rb[c];
    sm[threadIdx.x] = s;
    __syncthreads();
    for (int off = 64; off > 0; off >>= 1) {
        if (threadIdx.x < off) sm[threadIdx.x] += sm[threadIdx.x + off];
        __syncthreads();
    }
    if (threadIdx.x == 0) g_M[a * RK + b] = sm[0];
}

// ---------------- K3: fused mid-stage — decode | pp | np_u ---------------------
#define NDEC 256          // decode blocks: 32 samples each
#define NPP  256          // pp blocks: 32 prior rows each
#define NNP  32           // np_u blocks: 256 samples each
#define PP_KC 128
#define DEC_SMEM_FLOATS 16160

__device__ void decode_part(int bid, int t,
                            float* smf,
                            const float* __restrict__ n,
                            const float* __restrict__ z,
                            const float* __restrict__ znext,
                            float* __restrict__ out,
                            const float* __restrict__ w1W, const float* __restrict__ w1b,
                            const float* __restrict__ b1W, const float* __restrict__ b1b,
                            const float* __restrict__ w2W, const float* __restrict__ w2b,
                            const float* __restrict__ b2W, const float* __restrict__ b2b,
                            const float* __restrict__ w3W, const float* __restrict__ w3b,
                            const float* __restrict__ b3W, const float* __restrict__ b3b)
{
    float* nn   = smf;                 // 32*26
    float* z3   = nn + 32 * 26;        // 32*4
    float* h1   = z3 + 32 * 4;         // 32*68
    float* h2   = h1 + 32 * 68;        // 32*68
    float* w2r  = h2 + 32 * 68;        // 4096
    float* s1W  = w2r + 4096;          // 25*192
    float* s1b  = s1W + 25 * 192;      // 192
    float* sb1W = s1b + 192;           // 25*64
    float* sb1b = sb1W + 25 * 64;      // 64
    float* zh   = sb1b + 64;           // 96

    const long b0 = (long)bid * 32;

    for (int idx = t; idx < 32 * 25; idx += 256) {
        const int s = idx / 25, k = idx % 25;
        nn[s * 26 + k] = n[(b0 + s) * 25 + k];
    }
    for (int idx = t; idx < 32 * 3; idx += 256)
        z3[(idx / 3) * 4 + (idx % 3)] = z[b0 * 3 + idx];
    for (int idx = t; idx < 25 * 192; idx += 256) s1W[idx] = w1W[idx];
    for (int idx = t; idx < 192; idx += 256) s1b[idx] = w1b[idx];
    for (int idx = t; idx < 25 * 64; idx += 256) sb1W[idx] = b1W[idx];
    for (int idx = t; idx < 64; idx += 256) sb1b[idx] = b1b[idx];
    __syncthreads();

    // stage A: h1 (32*64 outputs)
    for (int idx = t; idx < 2048; idx += 256) {
        const int s = idx >> 6, u = idx & 63;
        const float z0 = z3[s * 4], z1 = z3[s * 4 + 1], z2 = z3[s * 4 + 2];
        float acc = sb1b[u] + s1b[u * 3] * z0 + s1b[u * 3 + 1] * z1 + s1b[u * 3 + 2] * z2;
        #pragma unroll
        for (int k = 0; k < 25; k++)
            acc += nn[s * 26 + k] * (s1W[k * 192 + u * 3] * z0
                                   + s1W[k * 192 + u * 3 + 1] * z1
                                   + s1W[k * 192 + u * 3 + 2] * z2
                                   + sb1W[k * 64 + u]);
        h1[s * 68 + u] = (acc > 0.f) ? acc : expm1f(acc);
    }
    __syncthreads();

    // stage B: h2 — thread owns (s, 8 consecutive i's); w2W streamed via smem
    const int s = t & 31, ig = t >> 5;     // ig warp-uniform
    float acc[8];
    #pragma unroll
    for (int m = 0; m < 8; m++) acc[m] = 0.f;

    for (int k = 0; k < 26; k++) {
        const float* src = (k < 25) ? (w2W + (long)k * 4096) : w2b;
        __syncthreads();
        for (int q = t; q < 1024; q += 256)
            reinterpret_cast<float4*>(w2r)[q] = reinterpret_cast<const float4*>(src)[q];
        __syncthreads();
        const float coef = (k < 25) ? nn[s * 26 + k] : 1.f;
        float tk[8];
        #pragma unroll
        for (int m = 0; m < 8; m++) tk[m] = 0.f;
        #pragma unroll 4
        for (int j4 = 0; j4 < 16; j4++) {
            const float4 h4 = *reinterpret_cast<const float4*>(&h1[s * 68 + j4 * 4]);
            #pragma unroll
            for (int m = 0; m < 8; m++) {
                const float4 w4 = *reinterpret_cast<const float4*>(
                    &w2r[(ig * 8 + m) * 64 + j4 * 4]);       // warp-broadcast
                tk[m] = fmaf(w4.x, h4.x, tk[m]);
                tk[m] = fmaf(w4.y, h4.y, tk[m]);
                tk[m] = fmaf(w4.z, h4.z, tk[m]);
                tk[m] = fmaf(w4.w, h4.w, tk[m]);
            }
        }
        #pragma unroll
        for (int m = 0; m < 8; m++) acc[m] = fmaf(coef, tk[m], acc[m]);
    }
    #pragma unroll
    for (int m = 0; m < 8; m++) {
        const int i = ig * 8 + m;
        float b2 = b2b[i];
        #pragma unroll
        for (int k = 0; k < 25; k++) b2 += nn[s * 26 + k] * b2W[k * 64 + i];
        const float v = acc[m] + b2;
        h2[s * 68 + i] = (v > 0.f) ? v : expm1f(v);
    }
    __syncthreads();

    // stage C: z_hat (32*3 outputs)
    if (t < 96) {
        const int ss = t / 3, d = t % 3;
        float a3 = b3b[d];
        #pragma unroll
        for (int k = 0; k < 25; k++) a3 += nn[ss * 26 + k] * b3W[k * 3 + d];
        for (int k = 0; k < 26; k++) {
            const float* row = (k < 25) ? (w3W + (long)k * 192 + d * 64) : (w3b + d * 64);
            const float coef = (k < 25) ? nn[ss * 26 + k] : 1.f;
            float tk = 0.f;
            #pragma unroll 8
            for (int j = 0; j < 64; j++) tk = fmaf(row[j], h2[ss * 68 + j], tk);
            a3 = fmaf(coef, tk, a3);
        }
        out[2 + (b0 + ss) * 3 + d] = a3;
        zh[ss * 3 + d] = a3;
    }
    __syncthreads();
    if (t < 32) {
        const float d0 = zh[t * 3]     - znext[(b0 + t) * 3];
        const float d1 = zh[t * 3 + 1] - znext[(b0 + t) * 3 + 1];
        const float d2 = zh[t * 3 + 2] - znext[(b0 + t) * 3 + 2];
        g_recon[b0 + t] = d0 * d0 + d1 * d1 + d2 * d2;
    }
}

__device__ void pp_part(int pbid, int t, float* smf, const float* __restrict__ prior)
{
    float* sp = smf;                   // 32 x 132
    float* sw = sp + 32 * 132;         // 26 x 128

    const long row0 = (long)pbid * 32;
    const int r = t & 31;
    const int grp = t >> 5;            // warp-uniform, 0..7

    // acc2[q] accumulates output m = 4*grp + q (m<26: P' col; m==26: rnP)
    unsigned long long acc2[4];
    #pragma unroll
    for (int q = 0; q < 4; q++) acc2[q] = 0ULL;

    for (int k0 = 0; k0 < DTOT; k0 += PP_KC) {
        for (int idx = t; idx < 32 * PP_KC; idx += 256) {
            const int rr = idx >> 7, c = idx & 127;
            sp[rr * 132 + c] = (k0 + c < DTOT) ? prior[(row0 + rr) * DTOT + k0 + c] : 0.f;
        }
        for (int idx = t; idx < RK * PP_KC; idx += 256) {
            const int m = idx >> 7, c = idx & 127;
            sw[m * 128 + c] = (k0 + c < DTOT) ? g_Wp[(long)m * DTOT + k0 + c] : 0.f;
        }
        __syncthreads();

        #pragma unroll 4
        for (int c4 = 0; c4 < 32; c4++) {
            const float4 sp4 = *reinterpret_cast<const float4*>(&sp[r * 132 + c4 * 4]);
            unsigned long long s01, s23;
            asm("mov.b64 %0, {%1, %2};" : "=l"(s01) : "f"(sp4.x), "f"(sp4.y));
            asm("mov.b64 %0, {%1, %2};" : "=l"(s23) : "f"(sp4.z), "f"(sp4.w));
            #pragma unroll
            for (int q = 0; q < 4; q++) {
                const int m = 4 * grp + q;
                if (m > 26) continue;
                float4 w4;
                if (m < 26)
                    w4 = *reinterpret_cast<const float4*>(&sw[m * 128 + c4 * 4]);
                else
                    w4 = sp4;          // norm: v*v
                unsigned long long w01, w23;
                asm("mov.b64 %0, {%1, %2};" : "=l"(w01) : "f"(w4.x), "f"(w4.y));
                asm("mov.b64 %0, {%1, %2};" : "=l"(w23) : "f"(w4.z), "f"(w4.w));
                asm("fma.rn.f32x2 %0, %1, %2, %0;" : "+l"(acc2[q]) : "l"(s01), "l"(w01));
                asm("fma.rn.f32x2 %0, %1, %2, %0;" : "+l"(acc2[q]) : "l"(s23), "l"(w23));
            }
        }
        __syncthreads();
    }

    #pragma unroll
    for (int q = 0; q < 4; q++) {
        const int m = 4 * grp + q;
        if (m > 26) continue;
        float lo, hi;
        asm("mov.b64 {%0, %1}, %2;" : "=f"(lo), "=f"(hi) : "l"(acc2[q]));
        const float sum = lo + hi;
        if (m < 26) g_Pp[(row0 + r) * RK + m] = sum;
        else        g_rnP[row0 + r] = sum;
    }
}

__device__ void np_part(int nbid, int t, float* smf, const float* __restrict__ n)
{
    float* Ms  = smf;                  // 676
    float* nsh = Ms + 676;             // 256 x 26

    for (int idx = t; idx < RK * RK; idx += 256) Ms[idx] = g_M[idx];
    const long s0 = (long)nbid * 256;
    for (int idx = t; idx < 256 * 25; idx += 256) {
        const int s = idx / 25, k = idx % 25;
        nsh[s * 26 + k] = n[(s0 + s) * 25 + k];
    }
    for (int idx = t; idx < 256; idx += 256) nsh[idx * 26 + 25] = 1.f;
    __syncthreads();

    const long s = s0 + t;
    float rn = 0.f;
    #pragma unroll 2
    for (int a = 0; a < RK; a++) {
        float u = 0.f;
        #pragma unroll
        for (int b = 0; b < RK; b++) u = fmaf(nsh[t * 26 + b], Ms[b * RK + a], u);
        g_U[s * RK + a]  = u;
        const float npv = nsh[t * 26 + a];
        g_Np[s * RK + a] = npv;
        rn = fmaf(u, npv, rn);
    }
    g_rnG[s] = rn;
}

__global__ __launch_bounds__(256)
void fused_mid_kernel(const float* __restrict__ n,
                      const float* __restrict__ z,
                      const float* __restrict__ znext,
                      const float* __restrict__ prior,
                      float* __restrict__ out,
                      const float* __restrict__ w1W, const float* __restrict__ w1b,
                      const float* __restrict__ b1W, const float* __restrict__ b1b,
                      const float* __restrict__ w2W, const float* __restrict__ w2b,
                      const float* __restrict__ b2W, const float* __restrict__ b2b,
                      const float* __restrict__ w3W, const float* __restrict__ w3b,
                      const float* __restrict__ b3W, const float* __restrict__ b3b)
{
    extern __shared__ float smf[];
    const int bid = blockIdx.x;
    const int t = threadIdx.x;
    if (bid < NDEC) {
        decode_part(bid, t, smf, n, z, znext, out,
                    w1W, w1b, b1W, b1b, w2W, w2b, b2W, b2b, w3W, w3b, b3W, b3b);
    } else if (bid < NDEC + NPP) {
        pp_part(bid - NDEC, t, smf, prior);
    } else {
        np_part(bid - NDEC - NPP, t, smf, n);
    }
}

// ---------------- K4: fused K=26 GEMM + min (both passes) ---------------------
#define MT 128
#define NTILE (BATCH / MT)                 // 64
#define NP0 (NTILE * NTILE)                // 4096
#define NP1 (NTILE * (NTILE + 1) / 2)      // 2080

__global__ __launch_bounds__(256, 2)
void minmin_kernel()
{
    __shared__ float At[RK * 132];
    __shared__ float Bt[RK * 132];
    __shared__ float rnA[MT], rnB[MT];

    const int bid = blockIdx.x;
    const int pass = (bid >= NP0);
    int ib, jb;
    if (!pass) { ib = bid >> 6; jb = bid & 63; }
    else {
        const int t0 = bid - NP0;
        jb = (int)((sqrtf(8.f * (float)t0 + 1.f) - 1.f) * 0.5f);
        while ((jb + 1) * (jb + 2) / 2 <= t0) jb++;
        while (jb * (jb + 1) / 2 > t0) jb--;
        ib = t0 - jb * (jb + 1) / 2;
    }
    const long i0 = (long)ib * MT;
    const long j0 = (long)jb * MT;
    const float* __restrict__ Asrc = pass ? g_U : g_Pp;
    const float* __restrict__ rnAs = pass ? g_rnG : g_rnP;
    unsigned* colmin                = pass ? g_minG : g_minP;

    const int t = threadIdx.x;
    const int tx = t & 15, ty = t >> 4;

    for (int idx = t; idx < MT * RK; idx += 256) {
        const int i = idx / RK, k = idx % RK;
        At[k * 132 + i] = Asrc[i0 * RK + idx];
        Bt[k * 132 + i] = g_Np[j0 * RK + idx];
    }
    if (t < MT) rnA[t] = rnAs[i0 + t];
    else if (pass && t < 2 * MT) rnB[t - MT] = g_rnG[j0 + (t - MT)];
    __syncthreads();

    unsigned long long acc[8][4];
    #pragma unroll
    for (int u = 0; u < 8; u++)
        #pragma unroll
        for (int p = 0; p < 4; p++) acc[u][p] = 0ULL;

    #pragma unroll
    for (int k = 0; k < RK; k++) {
        const float4 a0 = *reinterpret_cast<const float4*>(&At[k * 132 + ty * 8]);
        const float4 a1 = *reinterpret_cast<const float4*>(&At[k * 132 + ty * 8 + 4]);
        const float4 b0 = *reinterpret_cast<const float4*>(&Bt[k * 132 + tx * 8]);
        const float4 b1 = *reinterpret_cast<const float4*>(&Bt[k * 132 + tx * 8 + 4]);
        unsigned long long bb[4];
        asm("mov.b64 %0, {%1, %2};" : "=l"(bb[0]) : "f"(b0.x), "f"(b0.y));
        asm("mov.b64 %0, {%1, %2};" : "=l"(bb[1]) : "f"(b0.z), "f"(b0.w));
        asm("mov.b64 %0, {%1, %2};" : "=l"(bb[2]) : "f"(b1.x), "f"(b1.y));
        asm("mov.b64 %0, {%1, %2};" : "=l"(bb[3]) : "f"(b1.z), "f"(b1.w));
        const float av8[8] = {a0.x, a0.y, a0.z, a0.w, a1.x, a1.y, a1.z, a1.w};
        #pragma unroll
        for (int u = 0; u < 8; u++) {
            unsigned long long aa;
            asm("mov.b64 %0, {%1, %1};" : "=l"(aa) : "f"(av8[u]));
            #pragma unroll
            for (int p = 0; p < 4; p++)
                asm("fma.rn.f32x2 %0, %1, %2, %0;"
                    : "+l"(acc[u][p]) : "l"(aa), "l"(bb[p]));
        }
    }
    __syncthreads();

    float vmin[8], rmin[8];
    #pragma unroll
    for (int q = 0; q < 8; q++) { vmin[q] = 1e30f; rmin[q] = 1e30f; }

    #pragma unroll
    for (int u = 0; u < 8; u++) {
        const long ig = i0 + ty * 8 + u;
        const float rn = rnA[ty * 8 + u];
        #pragma unroll
        for (int p = 0; p < 4; p++) {
            float lo, hi;
            asm("mov.b64 {%0, %1}, %2;" : "=f"(lo), "=f"(hi) : "l"(acc[u][p]));
            float v0 = fmaf(-2.f, lo, rn);
            float v1 = fmaf(-2.f, hi, rn);
            if (pass) {
                const long jg = j0 + tx * 8 + 2 * p;
                float w0 = fmaf(-2.f, lo, rnB[tx * 8 + 2 * p]);
                float w1 = fmaf(-2.f, hi, rnB[tx * 8 + 2 * p + 1]);
                if (ig == jg)     { v0 = 1e30f; w0 = 1e30f; }
                if (ig == jg + 1) { v1 = 1e30f; w1 = 1e30f; }
                rmin[u] = fminf(rmin[u], fminf(w0, w1));
            }
            vmin[2 * p]     = fminf(vmin[2 * p], v0);
            vmin[2 * p + 1] = fminf(vmin[2 * p + 1], v1);
        }
    }

    float* redc = At;
    float* redr = Bt;
    #pragma unroll
    for (int c = 0; c < 8; c++) redc[ty * 128 + tx * 8 + c] = vmin[c];
    if (pass) {
        #pragma unroll
        for (int u = 0; u < 8; u++) redr[tx * 128 + ty * 8 + u] = rmin[u];
    }
    __syncthreads();
    if (t < MT) {
        float m = redc[t];
        #pragma unroll
        for (int q = 1; q < 16; q++) m = fminf(m, redc[q * 128 + t]);
        atomicMin(&colmin[j0 + t], fkey(m));
        if (pass) {
            float m2 = redr[t];
            #pragma unroll
            for (int q = 1; q < 16; q++) m2 = fminf(m2, redr[q * 128 + t]);
            atomicMin(&colmin[i0 + t], fkey(m2));
        }
    }
}

// ---------------- K5: final scalar reductions ----------------------------------
__global__ void finalize_kernel(float* __restrict__ out)
{
    __shared__ float s1[1024], s2[1024];
    const int t = threadIdx.x;
    float rsum = 0.f, ksum = 0.f;
    for (int j = t; j < BATCH; j += 1024) {
        rsum += g_recon[j];
        float rn = g_rnG[j];
        float wp = sqrtf(fmaxf(funkey(g_minP[j]) + rn, 0.f) + 1e-8f);
        float ww = sqrtf(fmaxf(funkey(g_minG[j]) + rn, 0.f) + 1e-8f);
        ksum += logf(wp / (ww + 1e-8f) + 1e-8f);
    }
    s1[t] = rsum; s2[t] = ksum;
    __syncthreads();
    for (int off = 512; off > 0; off >>= 1) {
        if (t < off) { s1[t] += s1[t + off]; s2[t] += s2[t + off]; }
        __syncthreads();
    }
    if (t == 0) {
        out[0] = s1[0] / (float)BATCH;
        out[1] = s2[0] / (float)BATCH * (float)DTOT
               + logf((float)BATCH / (float)(BATCH - 1));
    }
}

// ---------------- launch --------------------------------------------------------
extern "C" void kernel_launch(void* const* d_in, const int* in_sizes, int n_in,
                              void* d_out, int out_size)
{
    (void)in_sizes; (void)n_in; (void)out_size;
    const float* z     = (const float*)d_in[0];
    const float* znext = (const float*)d_in[1];
    const float* n     = (const float*)d_in[2];
    const float* prior = (const float*)d_in[3];
    const float* w1W = (const float*)d_in[4];  const float* w1b = (const float*)d_in[5];
    const float* b1W = (const float*)d_in[6];  const float* b1b = (const float*)d_in[7];
    const float* w2W = (const float*)d_in[8];  const float* w2b = (const float*)d_in[9];
    const float* b2W = (const float*)d_in[10]; const float* b2b = (const float*)d_in[11];
    const float* w3W = (const float*)d_in[12]; const float* w3b = (const float*)d_in[13];
    const float* b3W = (const float*)d_in[14]; const float* b3b = (const float*)d_in[15];
    float* out = (float*)d_out;

    cudaFuncSetAttribute(fused_mid_kernel,
                         cudaFuncAttributeMaxDynamicSharedMemorySize,
                         DEC_SMEM_FLOATS * (int)sizeof(float));

    build_Wp_kernel<<<32, 256>>>(
        w1W, w1b, b1W, b1b, w2W, w2b, b2W, b2b, w3W, w3b, b3W, b3b);
    compute_M_kernel<<<RK * RK, 128>>>();
    fused_mid_kernel<<<NDEC + NPP + NNP, 256, DEC_SMEM_FLOATS * sizeof(float)>>>(
        n, z, znext, prior, out,
        w1W, w1b, b1W, b1b, w2W, w2b, b2W, b2b, w3W, w3b, b3W, b3b);
    minmin_kernel<<<NP0 + NP1, 256>>>();
    finalize_kernel<<<1, 1024>>>(out);
}

// round 11
// speedup vs baseline: 14.8336x; 1.1510x over previous
#include <cuda_runtime.h>
#include <cuda_fp16.h>
#include <math.h>
#include <stdint.h>

#define BATCH 8192
#define DTOT  4611
#define RK    26               // rank of G: 25 noise dims + bias
#define KP    32               // fp16 K padded

// ---------------- static device scratch -------------------------------------
__device__ float g_Wp[RK * DTOT];      // W' (26 x 4611)
__device__ float g_M[RK * RK];         // W' W'^T
__device__ __half g_Uhi[(size_t)BATCH * KP];   // hi/lo splits, K padded to 32
__device__ __half g_Ulo[(size_t)BATCH * KP];
__device__ __half g_Nhi[(size_t)BATCH * KP];
__device__ __half g_Nlo[(size_t)BATCH * KP];
__device__ __half g_Phi[(size_t)BATCH * KP];
__device__ __half g_Plo[(size_t)BATCH * KP];
__device__ float    g_rnP[BATCH];
__device__ float    g_rnG[BATCH];
__device__ unsigned g_minP[BATCH];
__device__ unsigned g_minG[BATCH];
__device__ float    g_recon[BATCH];

__device__ __forceinline__ unsigned fkey(float f) {
    unsigned u = __float_as_uint(f);
    return (u & 0x80000000u) ? ~u : (u | 0x80000000u);
}
__device__ __forceinline__ float funkey(unsigned k) {
    unsigned u = (k & 0x80000000u) ? (k ^ 0x80000000u) : ~k;
    return __uint_as_float(u);
}

__device__ __forceinline__ uint32_t smem_u32(const void* p) {
    uint32_t a;
    asm("{ .reg .u64 t; cvta.to.shared.u64 t, %1; cvt.u32.u64 %0, t; }" : "=r"(a) : "l"(p));
    return a;
}
__device__ __forceinline__ void ldsm_x4(uint32_t& r0, uint32_t& r1, uint32_t& r2,
                                        uint32_t& r3, uint32_t addr) {
    asm volatile("ldmatrix.sync.aligned.m8n8.x4.shared.b16 {%0,%1,%2,%3}, [%4];"
                 : "=r"(r0), "=r"(r1), "=r"(r2), "=r"(r3) : "r"(addr));
}
__device__ __forceinline__ void mma16816(float* d, const uint32_t* a,
                                         uint32_t b0, uint32_t b1) {
    asm volatile("mma.sync.aligned.m16n8k16.row.col.f32.f16.f16.f32 "
                 "{%0,%1,%2,%3}, {%4,%5,%6,%7}, {%8,%9}, {%0,%1,%2,%3};"
                 : "+f"(d[0]), "+f"(d[1]), "+f"(d[2]), "+f"(d[3])
                 : "r"(a[0]), "r"(a[1]), "r"(a[2]), "r"(a[3]), "r"(b0), "r"(b1));
}

// ---------------- K1: build W' + init mins -----------------------------------
__global__ void build_Wp_kernel(const float* __restrict__ w1W, const float* __restrict__ w1b,
                                const float* __restrict__ b1W, const float* __restrict__ b1b,
                                const float* __restrict__ w2W, const float* __restrict__ w2b,
                                const float* __restrict__ b2W, const float* __restrict__ b2b,
                                const float* __restrict__ w3W, const float* __restrict__ w3b,
                                const float* __restrict__ b3W, const float* __restrict__ b3b)
{
    const int c = blockIdx.x * 256 + threadIdx.x;          // grid 32 x 256 = 8192
    if (c < BATCH) { g_minP[c] = 0xFFFFFFFFu; g_minG[c] = 0xFFFFFFFFu; }
    if (c >= DTOT) return;
    const float* W; const float* bias; int local, width;
    if      (c < 192)  { W = w1W; bias = w1b; local = c;        width = 192;  }
    else if (c < 256)  { W = b1W; bias = b1b; local = c - 192;  width = 64;   }
    else if (c < 4352) { W = w2W; bias = w2b; local = c - 256;  width = 4096; }
    else if (c < 4416) { W = b2W; bias = b2b; local = c - 4352; width = 64;   }
    else if (c < 4608) { W = w3W; bias = w3b; local = c - 4416; width = 192;  }
    else               { W = b3W; bias = b3b; local = c - 4608; width = 3;    }
    #pragma unroll
    for (int k = 0; k < 25; k++) g_Wp[k * DTOT + c] = W[k * width + local];
    g_Wp[25 * DTOT + c] = bias[local];
}

// ---------------- K2: M = W' W'^T (26 x 26) -----------------------------------
__global__ void compute_M_kernel()
{
    __shared__ float sm[128];
    const int a = blockIdx.x / RK;
    const int b = blockIdx.x % RK;
    const float* ra = g_Wp + (long)a * DTOT;
    const float* rb = g_Wp + (long)b * DTOT;
    float s = 0.f;
    for (int c = threadIdx.x; c < DTOT; c += 128) s += ra[c] * rb[c];
    sm[threadIdx.x] = s;
    __syncthreads();
    for (int off = 64; off > 0; off >>= 1) {
        if (threadIdx.x < off) sm[threadIdx.x] += sm[threadIdx.x + off];
        __syncthreads();
    }
    if (threadIdx.x == 0) g_M[a * RK + b] = sm[0];
}

// ---------------- K3: fused mid-stage — decode | pp | np_u ---------------------
#define NDEC 256          // decode blocks: 32 samples each
#define NPP  256          // pp blocks: 32 prior rows each
#define NNP  32           // np_u blocks: 256 samples each
#define PP_KC 128
#define DEC_SMEM_FLOATS 16160

__device__ void decode_part(int bid, int t,
                            float* smf,
                            const float* __restrict__ n,
                            const float* __restrict__ z,
                            const float* __restrict__ znext,
                            float* __restrict__ out,
                            const float* __restrict__ w1W, const float* __restrict__ w1b,
                            const float* __restrict__ b1W, const float* __restrict__ b1b,
                            const float* __restrict__ w2W, const float* __restrict__ w2b,
                            const float* __restrict__ b2W, const float* __restrict__ b2b,
                            const float* __restrict__ w3W, const float* __restrict__ w3b,
                            const float* __restrict__ b3W, const float* __restrict__ b3b)
{
    float* nn   = smf;                 // 32*26
    float* z3   = nn + 32 * 26;        // 32*4
    float* h1   = z3 + 32 * 4;         // 32*68
    float* h2   = h1 + 32 * 68;        // 32*68
    float* w2r  = h2 + 32 * 68;        // 4096
    float* s1W  = w2r + 4096;          // 25*192
    float* s1b  = s1W + 25 * 192;      // 192
    float* sb1W = s1b + 192;           // 25*64
    float* sb1b = sb1W + 25 * 64;      // 64
    float* zh   = sb1b + 64;           // 96

    const long b0 = (long)bid * 32;

    for (int idx = t; idx < 32 * 25; idx += 256) {
        const int s = idx / 25, k = idx % 25;
        nn[s * 26 + k] = n[(b0 + s) * 25 + k];
    }
    for (int idx = t; idx < 32 * 3; idx += 256)
        z3[(idx / 3) * 4 + (idx % 3)] = z[b0 * 3 + idx];
    for (int idx = t; idx < 25 * 192; idx += 256) s1W[idx] = w1W[idx];
    for (int idx = t; idx < 192; idx += 256) s1b[idx] = w1b[idx];
    for (int idx = t; idx < 25 * 64; idx += 256) sb1W[idx] = b1W[idx];
    for (int idx = t; idx < 64; idx += 256) sb1b[idx] = b1b[idx];
    __syncthreads();

    // stage A: h1 (32*64 outputs)
    for (int idx = t; idx < 2048; idx += 256) {
        const int s = idx >> 6, u = idx & 63;
        const float z0 = z3[s * 4], z1 = z3[s * 4 + 1], z2 = z3[s * 4 + 2];
        float acc = sb1b[u] + s1b[u * 3] * z0 + s1b[u * 3 + 1] * z1 + s1b[u * 3 + 2] * z2;
        #pragma unroll
        for (int k = 0; k < 25; k++)
            acc += nn[s * 26 + k] * (s1W[k * 192 + u * 3] * z0
                                   + s1W[k * 192 + u * 3 + 1] * z1
                                   + s1W[k * 192 + u * 3 + 2] * z2
                                   + sb1W[k * 64 + u]);
        h1[s * 68 + u] = (acc > 0.f) ? acc : expm1f(acc);
    }
    __syncthreads();

    // stage B: h2 — thread owns (s, 8 consecutive i's); w2W streamed via smem
    const int s = t & 31, ig = t >> 5;
    float acc[8];
    #pragma unroll
    for (int m = 0; m < 8; m++) acc[m] = 0.f;

    for (int k = 0; k < 26; k++) {
        const float* src = (k < 25) ? (w2W + (long)k * 4096) : w2b;
        __syncthreads();
        for (int q = t; q < 1024; q += 256)
            reinterpret_cast<float4*>(w2r)[q] = reinterpret_cast<const float4*>(src)[q];
        __syncthreads();
        const float coef = (k < 25) ? nn[s * 26 + k] : 1.f;
        float tk[8];
        #pragma unroll
        for (int m = 0; m < 8; m++) tk[m] = 0.f;
        #pragma unroll 4
        for (int j4 = 0; j4 < 16; j4++) {
            const float4 h4 = *reinterpret_cast<const float4*>(&h1[s * 68 + j4 * 4]);
            #pragma unroll
            for (int m = 0; m < 8; m++) {
                const float4 w4 = *reinterpret_cast<const float4*>(
                    &w2r[(ig * 8 + m) * 64 + j4 * 4]);
                tk[m] = fmaf(w4.x, h4.x, tk[m]);
                tk[m] = fmaf(w4.y, h4.y, tk[m]);
                tk[m] = fmaf(w4.z, h4.z, tk[m]);
                tk[m] = fmaf(w4.w, h4.w, tk[m]);
            }
        }
        #pragma unroll
        for (int m = 0; m < 8; m++) acc[m] = fmaf(coef, tk[m], acc[m]);
    }
    #pragma unroll
    for (int m = 0; m < 8; m++) {
        const int i = ig * 8 + m;
        float b2 = b2b[i];
        #pragma unroll
        for (int k = 0; k < 25; k++) b2 += nn[s * 26 + k] * b2W[k * 64 + i];
        const float v = acc[m] + b2;
        h2[s * 68 + i] = (v > 0.f) ? v : expm1f(v);
    }
    __syncthreads();

    // stage C: z_hat (32*3 outputs)
    if (t < 96) {
        const int ss = t / 3, d = t % 3;
        float a3 = b3b[d];
        #pragma unroll
        for (int k = 0; k < 25; k++) a3 += nn[ss * 26 + k] * b3W[k * 3 + d];
        for (int k = 0; k < 26; k++) {
            const float* row = (k < 25) ? (w3W + (long)k * 192 + d * 64) : (w3b + d * 64);
            const float coef = (k < 25) ? nn[ss * 26 + k] : 1.f;
            float tk = 0.f;
            #pragma unroll 8
            for (int j = 0; j < 64; j++) tk = fmaf(row[j], h2[ss * 68 + j], tk);
            a3 = fmaf(coef, tk, a3);
        }
        out[2 + (b0 + ss) * 3 + d] = a3;
        zh[ss * 3 + d] = a3;
    }
    __syncthreads();
    if (t < 32) {
        const float d0 = zh[t * 3]     - znext[(b0 + t) * 3];
        const float d1 = zh[t * 3 + 1] - znext[(b0 + t) * 3 + 1];
        const float d2 = zh[t * 3 + 2] - znext[(b0 + t) * 3 + 2];
        g_recon[b0 + t] = d0 * d0 + d1 * d1 + d2 * d2;
    }
}

__device__ void pp_part(int pbid, int t, float* smf, const float* __restrict__ prior)
{
    float* sp = smf;                   // 32 x 132
    float* sw = sp + 32 * 132;         // 26 x 128

    const long row0 = (long)pbid * 32;
    const int r = t & 31;
    const int grp = t >> 5;            // warp-uniform, 0..7

    unsigned long long acc2[4];
    #pragma unroll
    for (int q = 0; q < 4; q++) acc2[q] = 0ULL;

    for (int k0 = 0; k0 < DTOT; k0 += PP_KC) {
        for (int idx = t; idx < 32 * PP_KC; idx += 256) {
            const int rr = idx >> 7, c = idx & 127;
            sp[rr * 132 + c] = (k0 + c < DTOT) ? prior[(row0 + rr) * DTOT + k0 + c] : 0.f;
        }
        for (int idx = t; idx < RK * PP_KC; idx += 256) {
            const int m = idx >> 7, c = idx & 127;
            sw[m * 128 + c] = (k0 + c < DTOT) ? g_Wp[(long)m * DTOT + k0 + c] : 0.f;
        }
        __syncthreads();

        #pragma unroll 4
        for (int c4 = 0; c4 < 32; c4++) {
            const float4 sp4 = *reinterpret_cast<const float4*>(&sp[r * 132 + c4 * 4]);
            unsigned long long s01, s23;
            asm("mov.b64 %0, {%1, %2};" : "=l"(s01) : "f"(sp4.x), "f"(sp4.y));
            asm("mov.b64 %0, {%1, %2};" : "=l"(s23) : "f"(sp4.z), "f"(sp4.w));
            #pragma unroll
            for (int q = 0; q < 4; q++) {
                const int m = 4 * grp + q;
                if (m > 26) continue;
                float4 w4;
                if (m < 26)
                    w4 = *reinterpret_cast<const float4*>(&sw[m * 128 + c4 * 4]);
                else
                    w4 = sp4;          // norm: v*v
                unsigned long long w01, w23;
                asm("mov.b64 %0, {%1, %2};" : "=l"(w01) : "f"(w4.x), "f"(w4.y));
                asm("mov.b64 %0, {%1, %2};" : "=l"(w23) : "f"(w4.z), "f"(w4.w));
                asm("fma.rn.f32x2 %0, %1, %2, %0;" : "+l"(acc2[q]) : "l"(s01), "l"(w01));
                asm("fma.rn.f32x2 %0, %1, %2, %0;" : "+l"(acc2[q]) : "l"(s23), "l"(w23));
            }
        }
        __syncthreads();
    }

    #pragma unroll
    for (int q = 0; q < 4; q++) {
        const int m = 4 * grp + q;
        if (m > 26) continue;
        float lo, hi;
        asm("mov.b64 {%0, %1}, %2;" : "=f"(lo), "=f"(hi) : "l"(acc2[q]));
        const float sum = lo + hi;
        if (m < 26) {
            const __half h = __float2half_rn(sum);
            g_Phi[(row0 + r) * KP + m] = h;
            g_Plo[(row0 + r) * KP + m] = __float2half_rn(sum - __half2float(h));
        } else {
            g_rnP[row0 + r] = sum;
        }
    }
    // zero-pad k = 26..31
    if (t < 192) {
        const int rr = t / 6, kp = 26 + t % 6;
        g_Phi[(row0 + rr) * KP + kp] = __float2half_rn(0.f);
        g_Plo[(row0 + rr) * KP + kp] = __float2half_rn(0.f);
    }
}

__device__ void np_part(int nbid, int t, float* smf, const float* __restrict__ n)
{
    float* Ms  = smf;                  // 676
    float* nsh = Ms + 676;             // 256 x 26

    for (int idx = t; idx < RK * RK; idx += 256) Ms[idx] = g_M[idx];
    const long s0 = (long)nbid * 256;
    for (int idx = t; idx < 256 * 25; idx += 256) {
        const int s = idx / 25, k = idx % 25;
        nsh[s * 26 + k] = n[(s0 + s) * 25 + k];
    }
    for (int idx = t; idx < 256; idx += 256) nsh[idx * 26 + 25] = 1.f;
    __syncthreads();

    const long s = s0 + t;
    float rn = 0.f;
    #pragma unroll 2
    for (int a = 0; a < RK; a++) {
        float u = 0.f;
        #pragma unroll
        for (int b = 0; b < RK; b++) u = fmaf(nsh[t * 26 + b], Ms[b * RK + a], u);
        const __half uh = __float2half_rn(u);
        g_Uhi[s * KP + a] = uh;
        g_Ulo[s * KP + a] = __float2half_rn(u - __half2float(uh));
        const float npv = nsh[t * 26 + a];
        const __half nh = __float2half_rn(npv);
        g_Nhi[s * KP + a] = nh;
        g_Nlo[s * KP + a] = __float2half_rn(npv - __half2float(nh));
        rn = fmaf(u, npv, rn);
    }
    #pragma unroll
    for (int a = RK; a < KP; a++) {
        const __half zz = __float2half_rn(0.f);
        g_Uhi[s * KP + a] = zz; g_Ulo[s * KP + a] = zz;
        g_Nhi[s * KP + a] = zz; g_Nlo[s * KP + a] = zz;
    }
    g_rnG[s] = rn;
}

__global__ __launch_bounds__(256)
void fused_mid_kernel(const float* __restrict__ n,
                      const float* __restrict__ z,
                      const float* __restrict__ znext,
                      const float* __restrict__ prior,
                      float* __restrict__ out,
                      const float* __restrict__ w1W, const float* __restrict__ w1b,
                      const float* __restrict__ b1W, const float* __restrict__ b1b,
                      const float* __restrict__ w2W, const float* __restrict__ w2b,
                      const float* __restrict__ b2W, const float* __restrict__ b2b,
                      const float* __restrict__ w3W, const float* __restrict__ w3b,
                      const float* __restrict__ b3W, const float* __restrict__ b3b)
{
    extern __shared__ float smf[];
    const int bid = blockIdx.x;
    const int t = threadIdx.x;
    if (bid < NDEC) {
        decode_part(bid, t, smf, n, z, znext, out,
                    w1W, w1b, b1W, b1b, w2W, w2b, b2W, b2b, w3W, w3b, b3W, b3b);
    } else if (bid < NDEC + NPP) {
        pp_part(bid - NDEC, t, smf, prior);
    } else {
        np_part(bid - NDEC - NPP, t, smf, n);
    }
}

// ---------------- K4: HMMA fp16-split min-GEMM (both passes) -------------------
#define MT 128
#define NTILE (BATCH / MT)                 // 64
#define NP0 (NTILE * NTILE)                // 4096
#define NP1 (NTILE * (NTILE + 1) / 2)      // 2080
#define ROWH 40                            // padded row stride in halves (80 B)

__global__ __launch_bounds__(256, 2)
void minmin_kernel()
{
    __shared__ __align__(16) __half Ah[MT * ROWH];
    __shared__ __align__(16) __half Al[MT * ROWH];
    __shared__ __align__(16) __half Bh[MT * ROWH];
    __shared__ __align__(16) __half Bl[MT * ROWH];
    __shared__ float rnA[MT], rnB[MT];
    __shared__ float cbuf[2 * MT];
    __shared__ float rbuf[MT * 4];

    const int bid = blockIdx.x;
    const int pass = (bid >= NP0);
    int ib, jb;
    if (!pass) { ib = bid >> 6; jb = bid & 63; }
    else {
        const int t0 = bid - NP0;
        jb = (int)((sqrtf(8.f * (float)t0 + 1.f) - 1.f) * 0.5f);
        while ((jb + 1) * (jb + 2) / 2 <= t0) jb++;
        while (jb * (jb + 1) / 2 > t0) jb--;
        ib = t0 - jb * (jb + 1) / 2;
    }
    const long i0 = (long)ib * MT;
    const long j0 = (long)jb * MT;
    const __half* __restrict__ Ahg = pass ? g_Uhi : g_Phi;
    const __half* __restrict__ Alg = pass ? g_Ulo : g_Plo;
    const float* __restrict__ rnAs = pass ? g_rnG : g_rnP;
    unsigned* colmin                = pass ? g_minG : g_minP;

    const int t = threadIdx.x;

    // one-shot tile load: 128 rows x 32 halves (64 B = 4 x 16 B chunks), pad-40 rows
    for (int u = t; u < 512; u += 256) {
        const int r = u >> 2, c = u & 3;
        const long ga = (i0 + r) * KP + c * 8;
        const long gb = (j0 + r) * KP + c * 8;
        char* da = reinterpret_cast<char*>(Ah) + r * 80 + c * 16;
        char* db = reinterpret_cast<char*>(Bh) + r * 80 + c * 16;
        *reinterpret_cast<uint4*>(da) = *reinterpret_cast<const uint4*>(Ahg + ga);
        *reinterpret_cast<uint4*>(reinterpret_cast<char*>(Al) + r * 80 + c * 16)
            = *reinterpret_cast<const uint4*>(Alg + ga);
        *reinterpret_cast<uint4*>(db) = *reinterpret_cast<const uint4*>(g_Nhi + gb);
        *reinterpret_cast<uint4*>(reinterpret_cast<char*>(Bl) + r * 80 + c * 16)
            = *reinterpret_cast<const uint4*>(g_Nlo + gb);
    }
    if (t < MT) rnA[t] = rnAs[i0 + t];
    else rnB[t - MT] = g_rnG[j0 + (t - MT)];
    __syncthreads();

    const uint32_t sAh = smem_u32(Ah), sAl = smem_u32(Al);
    const uint32_t sBh = smem_u32(Bh), sBl = smem_u32(Bl);
    const int lane = t & 31, wid = t >> 5;
    const int wm = wid >> 2;               // 0..1 (64 rows)
    const int wn = wid & 3;                // 0..3 (32 cols)
    const int arow = wm * 64 + (lane & 7) + ((lane >> 3) & 1) * 8;
    const int ahalf = (lane >> 4) & 1;
    const int brow = wn * 32 + (lane & 7) + ((lane >> 4) & 1) * 8;
    const int bhalf = (lane >> 3) & 1;

    float d[4][4][4];
    #pragma unroll
    for (int mi = 0; mi < 4; mi++)
        #pragma unroll
        for (int ni = 0; ni < 4; ni++)
            #pragma unroll
            for (int q = 0; q < 4; q++) d[mi][ni][q] = 0.f;

    #pragma unroll
    for (int ks = 0; ks < 2; ks++) {
        const uint32_t ach = (uint32_t)((ks * 2 + ahalf) * 16);
        const uint32_t bch = (uint32_t)((ks * 2 + bhalf) * 16);
        uint32_t af[4][4], bfh[2][4], bfl[2][4];
        #pragma unroll
        for (int mi = 0; mi < 4; mi++)
            ldsm_x4(af[mi][0], af[mi][1], af[mi][2], af[mi][3],
                    sAh + (uint32_t)((arow + mi * 16) * 80) + ach);
        #pragma unroll
        for (int nb = 0; nb < 2; nb++)
            ldsm_x4(bfh[nb][0], bfh[nb][1], bfh[nb][2], bfh[nb][3],
                    sBh + (uint32_t)((brow + nb * 16) * 80) + bch);
        #pragma unroll
        for (int nb = 0; nb < 2; nb++)
            ldsm_x4(bfl[nb][0], bfl[nb][1], bfl[nb][2], bfl[nb][3],
                    sBl + (uint32_t)((brow + nb * 16) * 80) + bch);
        // hi*hi and hi*lo
        #pragma unroll
        for (int mi = 0; mi < 4; mi++)
            #pragma unroll
            for (int nb = 0; nb < 2; nb++) {
                mma16816(d[mi][nb * 2],     af[mi], bfh[nb][0], bfh[nb][1]);
                mma16816(d[mi][nb * 2 + 1], af[mi], bfh[nb][2], bfh[nb][3]);
                mma16816(d[mi][nb * 2],     af[mi], bfl[nb][0], bfl[nb][1]);
                mma16816(d[mi][nb * 2 + 1], af[mi], bfl[nb][2], bfl[nb][3]);
            }
        // lo*hi
        #pragma unroll
        for (int mi = 0; mi < 4; mi++)
            ldsm_x4(af[mi][0], af[mi][1], af[mi][2], af[mi][3],
                    sAl + (uint32_t)((arow + mi * 16) * 80) + ach);
        #pragma unroll
        for (int mi = 0; mi < 4; mi++)
            #pragma unroll
            for (int nb = 0; nb < 2; nb++) {
                mma16816(d[mi][nb * 2],     af[mi], bfh[nb][0], bfh[nb][1]);
                mma16816(d[mi][nb * 2 + 1], af[mi], bfh[nb][2], bfh[nb][3]);
            }
    }

    // ---------------- epilogue -------------------------------------------------
    const int g = lane >> 2, tig = lane & 3;
    float cmin[4][2], rmin[4][2];
    #pragma unroll
    for (int q = 0; q < 4; q++) { cmin[q][0] = 1e30f; cmin[q][1] = 1e30f;
                                  rmin[q][0] = 1e30f; rmin[q][1] = 1e30f; }

    #pragma unroll
    for (int mi = 0; mi < 4; mi++) {
        const int r0 = wm * 64 + mi * 16 + g;
        const long ig0 = i0 + r0;
        const long ig1 = ig0 + 8;
        const float rn0 = rnA[r0];
        const float rn1 = rnA[r0 + 8];
        #pragma unroll
        for (int ni = 0; ni < 4; ni++) {
            const float d0 = d[mi][ni][0], d1 = d[mi][ni][1];
            const float d2 = d[mi][ni][2], d3 = d[mi][ni][3];
            float v0 = fmaf(-2.f, d0, rn0);
            float v1 = fmaf(-2.f, d1, rn0);
            float v2 = fmaf(-2.f, d2, rn1);
            float v3 = fmaf(-2.f, d3, rn1);
            if (pass) {
                const int cc = wn * 32 + ni * 8 + 2 * tig;
                const long jg = j0 + cc;
                float w0 = fmaf(-2.f, d0, rnB[cc]);
                float w1 = fmaf(-2.f, d1, rnB[cc + 1]);
                float w2 = fmaf(-2.f, d2, rnB[cc]);
                float w3 = fmaf(-2.f, d3, rnB[cc + 1]);
                if (ig0 == jg)     { v0 = 1e30f; w0 = 1e30f; }
                if (ig0 == jg + 1) { v1 = 1e30f; w1 = 1e30f; }
                if (ig1 == jg)     { v2 = 1e30f; w2 = 1e30f; }
                if (ig1 == jg + 1) { v3 = 1e30f; w3 = 1e30f; }
                rmin[mi][0] = fminf(rmin[mi][0], fminf(w0, w1));
                rmin[mi][1] = fminf(rmin[mi][1], fminf(w2, w3));
            }
            cmin[ni][0] = fminf(cmin[ni][0], fminf(v0, v2));
            cmin[ni][1] = fminf(cmin[ni][1], fminf(v1, v3));
        }
    }

    // column-min: reduce across g-lanes (bits 2..4)
    #pragma unroll
    for (int off = 4; off <= 16; off <<= 1)
        #pragma unroll
        for (int ni = 0; ni < 4; ni++) {
            cmin[ni][0] = fminf(cmin[ni][0], __shfl_xor_sync(0xFFFFFFFFu, cmin[ni][0], off));
            cmin[ni][1] = fminf(cmin[ni][1], __shfl_xor_sync(0xFFFFFFFFu, cmin[ni][1], off));
        }
    if (pass) {
        // row-min: reduce across tig-lanes (bits 0..1)
        #pragma unroll
        for (int off = 1; off <= 2; off <<= 1)
            #pragma unroll
            for (int mi = 0; mi < 4; mi++) {
                rmin[mi][0] = fminf(rmin[mi][0], __shfl_xor_sync(0xFFFFFFFFu, rmin[mi][0], off));
                rmin[mi][1] = fminf(rmin[mi][1], __shfl_xor_sync(0xFFFFFFFFu, rmin[mi][1], off));
            }
    }

    if (lane < 4) {
        #pragma unroll
        for (int ni = 0; ni < 4; ni++) {
            const int col = wn * 32 + ni * 8 + 2 * lane;
            cbuf[wm * MT + col]     = cmin[ni][0];
            cbuf[wm * MT + col + 1] = cmin[ni][1];
        }
    }
    if (pass && tig == 0) {
        #pragma unroll
        for (int mi = 0; mi < 4; mi++) {
            const int r0 = wm * 64 + mi * 16 + g;
            rbuf[r0 * 4 + wn]       = rmin[mi][0];
            rbuf[(r0 + 8) * 4 + wn] = rmin[mi][1];
        }
    }
    __syncthreads();

    if (t < MT) {
        atomicMin(&colmin[j0 + t], fkey(fminf(cbuf[t], cbuf[MT + t])));
        if (pass) {
            const float m2 = fminf(fminf(rbuf[t * 4], rbuf[t * 4 + 1]),
                                   fminf(rbuf[t * 4 + 2], rbuf[t * 4 + 3]));
            atomicMin(&colmin[i0 + t], fkey(m2));
        }
    }
}

// ---------------- K5: final scalar reductions ----------------------------------
__global__ void finalize_kernel(float* __restrict__ out)
{
    __shared__ float s1[1024], s2[1024];
    const int t = threadIdx.x;
    float rsum = 0.f, ksum = 0.f;
    for (int j = t; j < BATCH; j += 1024) {
        rsum += g_recon[j];
        float rn = g_rnG[j];
        float wp = sqrtf(fmaxf(funkey(g_minP[j]) + rn, 0.f) + 1e-8f);
        float ww = sqrtf(fmaxf(funkey(g_minG[j]) + rn, 0.f) + 1e-8f);
        ksum += logf(wp / (ww + 1e-8f) + 1e-8f);
    }
    s1[t] = rsum; s2[t] = ksum;
    __syncthreads();
    for (int off = 512; off > 0; off >>= 1) {
        if (t < off) { s1[t] += s1[t + off]; s2[t] += s2[t + off]; }
        __syncthreads();
    }
    if (t == 0) {
        out[0] = s1[0] / (float)BATCH;
        out[1] = s2[0] / (float)BATCH * (float)DTOT
               + logf((float)BATCH / (float)(BATCH - 1));
    }
}

// ---------------- launch --------------------------------------------------------
extern "C" void kernel_launch(void* const* d_in, const int* in_sizes, int n_in,
                              void* d_out, int out_size)
{
    (void)in_sizes; (void)n_in; (void)out_size;
    const float* z     = (const float*)d_in[0];
    const float* znext = (const float*)d_in[1];
    const float* n     = (const float*)d_in[2];
    const float* prior = (const float*)d_in[3];
    const float* w1W = (const float*)d_in[4];  const float* w1b = (const float*)d_in[5];
    const float* b1W = (const float*)d_in[6];  const float* b1b = (const float*)d_in[7];
    const float* w2W = (const float*)d_in[8];  const float* w2b = (const float*)d_in[9];
    const float* b2W = (const float*)d_in[10]; const float* b2b = (const float*)d_in[11];
    const float* w3W = (const float*)d_in[12]; const float* w3b = (const float*)d_in[13];
    const float* b3W = (const float*)d_in[14]; const float* b3b = (const float*)d_in[15];
    float* out = (float*)d_out;

    cudaFuncSetAttribute(fused_mid_kernel,
                         cudaFuncAttributeMaxDynamicSharedMemorySize,
                         DEC_SMEM_FLOATS * (int)sizeof(float));

    build_Wp_kernel<<<32, 256>>>(
        w1W, w1b, b1W, b1b, w2W, w2b, b2W, b2b, w3W, w3b, b3W, b3b);
    compute_M_kernel<<<RK * RK, 128>>>();
    fused_mid_kernel<<<NDEC + NPP + NNP, 256, DEC_SMEM_FLOATS * sizeof(float)>>>(
        n, z, znext, prior, out,
        w1W, w1b, b1W, b1b, w2W, w2b, b2W, b2b, w3W, w3b, b3W, b3b);
    minmin_kernel<<<NP0 + NP1, 256>>>();
    finalize_kernel<<<1, 1024>>>(out);
}

// round 12
// speedup vs baseline: 15.5620x; 1.0491x over previous
#include <cuda_runtime.h>
#include <cuda_fp16.h>
#include <math.h>
#include <stdint.h>

#define BATCH 8192
#define DTOT  4611
#define RK    26               // rank of G: 25 noise dims + bias
#define KP    32               // fp16 K padded

// ---------------- static device scratch -------------------------------------
__device__ float g_Wp[RK * DTOT];      // W' (26 x 4611)
__device__ float g_M[RK * RK];         // W' W'^T
__device__ __half g_Uhi[(size_t)BATCH * KP];   // hi/lo splits, K padded to 32
__device__ __half g_Ulo[(size_t)BATCH * KP];
__device__ __half g_Nhi[(size_t)BATCH * KP];
__device__ __half g_Nlo[(size_t)BATCH * KP];
__device__ __half g_Phi[(size_t)BATCH * KP];
__device__ __half g_Plo[(size_t)BATCH * KP];
__device__ float    g_rnP[BATCH];
__device__ float    g_rnG[BATCH];
__device__ unsigned g_minP[BATCH];
__device__ unsigned g_minG[BATCH];
__device__ float    g_recon[BATCH];

__device__ __forceinline__ unsigned fkey(float f) {
    unsigned u = __float_as_uint(f);
    return (u & 0x80000000u) ? ~u : (u | 0x80000000u);
}
__device__ __forceinline__ float funkey(unsigned k) {
    unsigned u = (k & 0x80000000u) ? (k ^ 0x80000000u) : ~k;
    return __uint_as_float(u);
}

__device__ __forceinline__ uint32_t smem_u32(const void* p) {
    uint32_t a;
    asm("{ .reg .u64 t; cvta.to.shared.u64 t, %1; cvt.u32.u64 %0, t; }" : "=r"(a) : "l"(p));
    return a;
}
__device__ __forceinline__ void ldsm_x4(uint32_t& r0, uint32_t& r1, uint32_t& r2,
                                        uint32_t& r3, uint32_t addr) {
    asm volatile("ldmatrix.sync.aligned.m8n8.x4.shared.b16 {%0,%1,%2,%3}, [%4];"
                 : "=r"(r0), "=r"(r1), "=r"(r2), "=r"(r3) : "r"(addr));
}
__device__ __forceinline__ void mma16816(float* d, const uint32_t* a,
                                         uint32_t b0, uint32_t b1) {
    asm volatile("mma.sync.aligned.m16n8k16.row.col.f32.f16.f16.f32 "
                 "{%0,%1,%2,%3}, {%4,%5,%6,%7}, {%8,%9}, {%0,%1,%2,%3};"
                 : "+f"(d[0]), "+f"(d[1]), "+f"(d[2]), "+f"(d[3])
                 : "r"(a[0]), "r"(a[1]), "r"(a[2]), "r"(a[3]), "r"(b0), "r"(b1));
}

// ---------------- K1: build W' + init mins -----------------------------------
__global__ void build_Wp_kernel(const float* __restrict__ w1W, const float* __restrict__ w1b,
                                const float* __restrict__ b1W, const float* __restrict__ b1b,
                                const float* __restrict__ w2W, const float* __restrict__ w2b,
                                const float* __restrict__ b2W, const float* __restrict__ b2b,
                                const float* __restrict__ w3W, const float* __restrict__ w3b,
                                const float* __restrict__ b3W, const float* __restrict__ b3b)
{
    const int c = blockIdx.x * 256 + threadIdx.x;          // grid 32 x 256 = 8192
    if (c < BATCH) { g_minP[c] = 0xFFFFFFFFu; g_minG[c] = 0xFFFFFFFFu; }
    if (c >= DTOT) return;
    const float* W; const float* bias; int local, width;
    if      (c < 192)  { W = w1W; bias = w1b; local = c;        width = 192;  }
    else if (c < 256)  { W = b1W; bias = b1b; local = c - 192;  width = 64;   }
    else if (c < 4352) { W = w2W; bias = w2b; local = c - 256;  width = 4096; }
    else if (c < 4416) { W = b2W; bias = b2b; local = c - 4352; width = 64;   }
    else if (c < 4608) { W = w3W; bias = w3b; local = c - 4416; width = 192;  }
    else               { W = b3W; bias = b3b; local = c - 4608; width = 3;    }
    #pragma unroll
    for (int k = 0; k < 25; k++) g_Wp[k * DTOT + c] = W[k * width + local];
    g_Wp[25 * DTOT + c] = bias[local];
}

// ---------------- K2: M = W' W'^T (26 x 26) -----------------------------------
__global__ void compute_M_kernel()
{
    __shared__ float sm[128];
    const int a = blockIdx.x / RK;
    const int b = blockIdx.x % RK;
    const float* ra = g_Wp + (long)a * DTOT;
    const float* rb = g_Wp + (long)b * DTOT;
    float s = 0.f;
    for (int c = threadIdx.x; c < DTOT; c += 128) s += ra[c] * rb[c];
    sm[threadIdx.x] = s;
    __syncthreads();
    for (int off = 64; off > 0; off >>= 1) {
        if (threadIdx.x < off) sm[threadIdx.x] += sm[threadIdx.x + off];
        __syncthreads();
    }
    if (threadIdx.x == 0) g_M[a * RK + b] = sm[0];
}

// ---------------- K3: fused mid-stage — decode | pp | np_u ---------------------
#define NDEC 256          // decode blocks: 32 samples each
#define NPP  256          // pp blocks: 32 prior rows each
#define NNP  32           // np_u blocks: 256 samples each
#define PP_KC 128
#define DEC_SMEM_FLOATS 17696

#define CP16(dst, src) \
    asm volatile("cp.async.cg.shared.global [%0], [%1], 16;" \
                 :: "r"(dst), "l"(src) : "memory")

__device__ void decode_part(int bid, int t,
                            float* smf,
                            const float* __restrict__ n,
                            const float* __restrict__ z,
                            const float* __restrict__ znext,
                            float* __restrict__ out,
                            const float* __restrict__ w1W, const float* __restrict__ w1b,
                            const float* __restrict__ b1W, const float* __restrict__ b1b,
                            const float* __restrict__ w2W, const float* __restrict__ w2b,
                            const float* __restrict__ b2W, const float* __restrict__ b2b,
                            const float* __restrict__ w3W, const float* __restrict__ w3b,
                            const float* __restrict__ b3W, const float* __restrict__ b3b)
{
    float* nn   = smf;                 // 832 (32*26)
    float* z3   = nn + 832;            // 128
    float* h1   = z3 + 128;            // 2176 (32*68)
    float* h2   = h1 + 2176;           // 2176
    float* ring = h2 + 2176;           // 12288 (3 x 4096) — stage-A staging reuses this
    float* zh   = ring + 12288;        // 96
    // stage-A staging (inside ring, freed before stage B):
    float* s1W  = ring;                // 4800
    float* s1b  = s1W + 4800;          // 192
    float* sb1W = s1b + 192;           // 1600
    float* sb1b = sb1W + 1600;         // 64

    const long b0 = (long)bid * 32;

    for (int idx = t; idx < 32 * 25; idx += 256) {
        const int s = idx / 25, k = idx % 25;
        nn[s * 26 + k] = n[(b0 + s) * 25 + k];
    }
    for (int idx = t; idx < 32 * 3; idx += 256)
        z3[(idx / 3) * 4 + (idx % 3)] = z[b0 * 3 + idx];
    for (int idx = t; idx < 25 * 192; idx += 256) s1W[idx] = w1W[idx];
    for (int idx = t; idx < 192; idx += 256) s1b[idx] = w1b[idx];
    for (int idx = t; idx < 25 * 64; idx += 256) sb1W[idx] = b1W[idx];
    for (int idx = t; idx < 64; idx += 256) sb1b[idx] = b1b[idx];
    __syncthreads();

    // stage A: h1 (32*64 outputs)
    for (int idx = t; idx < 2048; idx += 256) {
        const int s = idx >> 6, u = idx & 63;
        const float z0 = z3[s * 4], z1 = z3[s * 4 + 1], z2 = z3[s * 4 + 2];
        float acc = sb1b[u] + s1b[u * 3] * z0 + s1b[u * 3 + 1] * z1 + s1b[u * 3 + 2] * z2;
        #pragma unroll
        for (int k = 0; k < 25; k++)
            acc += nn[s * 26 + k] * (s1W[k * 192 + u * 3] * z0
                                   + s1W[k * 192 + u * 3 + 1] * z1
                                   + s1W[k * 192 + u * 3 + 2] * z2
                                   + sb1W[k * 64 + u]);
        h1[s * 68 + u] = (acc > 0.f) ? acc : expm1f(acc);
    }
    __syncthreads();       // stage-A staging dead; ring reclaimed for w2W stream

    // stage B: h2 — 3-stage cp.async ring over w2W k-slices, f32x2 accumulate.
    const int s = t & 31, ig = t >> 5;
    const uint32_t ringa = smem_u32(ring);

    // prefetch chunks 0, 1
    #pragma unroll
    for (int kk = 0; kk < 2; kk++) {
        const float* src = (kk < 25) ? (w2W + (long)kk * 4096) : w2b;
        #pragma unroll
        for (int q = 0; q < 4; q++) {
            const int idx = t + q * 256;
            CP16(ringa + (uint32_t)(kk * 16384 + idx * 16), src + idx * 4);
        }
        asm volatile("cp.async.commit_group;" ::: "memory");
    }

    unsigned long long acc2[8];
    #pragma unroll
    for (int m = 0; m < 8; m++) acc2[m] = 0ULL;

    for (int k = 0; k < 26; k++) {
        if (k < 25) asm volatile("cp.async.wait_group 1;" ::: "memory");
        else        asm volatile("cp.async.wait_group 0;" ::: "memory");
        __syncthreads();
        if (k + 2 < 26) {
            const float* src = (k + 2 < 25) ? (w2W + (long)(k + 2) * 4096) : w2b;
            #pragma unroll
            for (int q = 0; q < 4; q++) {
                const int idx = t + q * 256;
                CP16(ringa + (uint32_t)(((k + 2) % 3) * 16384 + idx * 16), src + idx * 4);
            }
            asm volatile("cp.async.commit_group;" ::: "memory");
        }

        const float* cur = ring + (k % 3) * 4096;
        const float coef = (k < 25) ? nn[s * 26 + k] : 1.f;
        unsigned long long coef2;
        asm("mov.b64 %0, {%1, %1};" : "=l"(coef2) : "f"(coef));

        unsigned long long tk2[8];
        #pragma unroll
        for (int m = 0; m < 8; m++) tk2[m] = 0ULL;
        #pragma unroll 4
        for (int j4 = 0; j4 < 16; j4++) {
            const float4 h4 = *reinterpret_cast<const float4*>(&h1[s * 68 + j4 * 4]);
            unsigned long long h01, h23;
            asm("mov.b64 %0, {%1, %2};" : "=l"(h01) : "f"(h4.x), "f"(h4.y));
            asm("mov.b64 %0, {%1, %2};" : "=l"(h23) : "f"(h4.z), "f"(h4.w));
            #pragma unroll
            for (int m = 0; m < 8; m++) {
                const float4 w4 = *reinterpret_cast<const float4*>(
                    &cur[(ig * 8 + m) * 64 + j4 * 4]);       // warp-broadcast
                unsigned long long w01, w23;
                asm("mov.b64 %0, {%1, %2};" : "=l"(w01) : "f"(w4.x), "f"(w4.y));
                asm("mov.b64 %0, {%1, %2};" : "=l"(w23) : "f"(w4.z), "f"(w4.w));
                asm("fma.rn.f32x2 %0, %1, %2, %0;" : "+l"(tk2[m]) : "l"(h01), "l"(w01));
                asm("fma.rn.f32x2 %0, %1, %2, %0;" : "+l"(tk2[m]) : "l"(h23), "l"(w23));
            }
        }
        #pragma unroll
        for (int m = 0; m < 8; m++)
            asm("fma.rn.f32x2 %0, %1, %2, %0;" : "+l"(acc2[m]) : "l"(coef2), "l"(tk2[m]));
    }

    #pragma unroll
    for (int m = 0; m < 8; m++) {
        const int i = ig * 8 + m;
        float b2 = b2b[i];
        #pragma unroll
        for (int k = 0; k < 25; k++) b2 += nn[s * 26 + k] * b2W[k * 64 + i];
        float lo, hi;
        asm("mov.b64 {%0, %1}, %2;" : "=f"(lo), "=f"(hi) : "l"(acc2[m]));
        const float v = lo + hi + b2;
        h2[s * 68 + i] = (v > 0.f) ? v : expm1f(v);
    }
    __syncthreads();

    // stage C: z_hat (32*3 outputs)
    if (t < 96) {
        const int ss = t / 3, d = t % 3;
        float a3 = b3b[d];
        #pragma unroll
        for (int k = 0; k < 25; k++) a3 += nn[ss * 26 + k] * b3W[k * 3 + d];
        for (int k = 0; k < 26; k++) {
            const float* row = (k < 25) ? (w3W + (long)k * 192 + d * 64) : (w3b + d * 64);
            const float coef = (k < 25) ? nn[ss * 26 + k] : 1.f;
            float tk = 0.f;
            #pragma unroll 8
            for (int j = 0; j < 64; j++) tk = fmaf(row[j], h2[ss * 68 + j], tk);
            a3 = fmaf(coef, tk, a3);
        }
        out[2 + (b0 + ss) * 3 + d] = a3;
        zh[ss * 3 + d] = a3;
    }
    __syncthreads();
    if (t < 32) {
        const float d0 = zh[t * 3]     - znext[(b0 + t) * 3];
        const float d1 = zh[t * 3 + 1] - znext[(b0 + t) * 3 + 1];
        const float d2 = zh[t * 3 + 2] - znext[(b0 + t) * 3 + 2];
        g_recon[b0 + t] = d0 * d0 + d1 * d1 + d2 * d2;
    }
}

__device__ void pp_part(int pbid, int t, float* smf, const float* __restrict__ prior)
{
    float* sp = smf;                   // 32 x 132
    float* sw = sp + 32 * 132;         // 26 x 128

    const long row0 = (long)pbid * 32;
    const int r = t & 31;
    const int grp = t >> 5;            // warp-uniform, 0..7

    unsigned long long acc2[4];
    #pragma unroll
    for (int q = 0; q < 4; q++) acc2[q] = 0ULL;

    for (int k0 = 0; k0 < DTOT; k0 += PP_KC) {
        for (int idx = t; idx < 32 * PP_KC; idx += 256) {
            const int rr = idx >> 7, c = idx & 127;
            sp[rr * 132 + c] = (k0 + c < DTOT) ? prior[(row0 + rr) * DTOT + k0 + c] : 0.f;
        }
        for (int idx = t; idx < RK * PP_KC; idx += 256) {
            const int m = idx >> 7, c = idx & 127;
            sw[m * 128 + c] = (k0 + c < DTOT) ? g_Wp[(long)m * DTOT + k0 + c] : 0.f;
        }
        __syncthreads();

        #pragma unroll 4
        for (int c4 = 0; c4 < 32; c4++) {
            const float4 sp4 = *reinterpret_cast<const float4*>(&sp[r * 132 + c4 * 4]);
            unsigned long long s01, s23;
            asm("mov.b64 %0, {%1, %2};" : "=l"(s01) : "f"(sp4.x), "f"(sp4.y));
            asm("mov.b64 %0, {%1, %2};" : "=l"(s23) : "f"(sp4.z), "f"(sp4.w));
            #pragma unroll
            for (int q = 0; q < 4; q++) {
                const int m = 4 * grp + q;
                if (m > 26) continue;
                float4 w4;
                if (m < 26)
                    w4 = *reinterpret_cast<const float4*>(&sw[m * 128 + c4 * 4]);
                else
                    w4 = sp4;          // norm: v*v
                unsigned long long w01, w23;
                asm("mov.b64 %0, {%1, %2};" : "=l"(w01) : "f"(w4.x), "f"(w4.y));
                asm("mov.b64 %0, {%1, %2};" : "=l"(w23) : "f"(w4.z), "f"(w4.w));
                asm("fma.rn.f32x2 %0, %1, %2, %0;" : "+l"(acc2[q]) : "l"(s01), "l"(w01));
                asm("fma.rn.f32x2 %0, %1, %2, %0;" : "+l"(acc2[q]) : "l"(s23), "l"(w23));
            }
        }
        __syncthreads();
    }

    #pragma unroll
    for (int q = 0; q < 4; q++) {
        const int m = 4 * grp + q;
        if (m > 26) continue;
        float lo, hi;
        asm("mov.b64 {%0, %1}, %2;" : "=f"(lo), "=f"(hi) : "l"(acc2[q]));
        const float sum = lo + hi;
        if (m < 26) {
            const __half h = __float2half_rn(sum);
            g_Phi[(row0 + r) * KP + m] = h;
            g_Plo[(row0 + r) * KP + m] = __float2half_rn(sum - __half2float(h));
        } else {
            g_rnP[row0 + r] = sum;
        }
    }
    // zero-pad k = 26..31
    if (t < 192) {
        const int rr = t / 6, kp = 26 + t % 6;
        g_Phi[(row0 + rr) * KP + kp] = __float2half_rn(0.f);
        g_Plo[(row0 + rr) * KP + kp] = __float2half_rn(0.f);
    }
}

__device__ void np_part(int nbid, int t, float* smf, const float* __restrict__ n)
{
    float* Ms  = smf;                  // 676
    float* nsh = Ms + 676;             // 256 x 26

    for (int idx = t; idx < RK * RK; idx += 256) Ms[idx] = g_M[idx];
    const long s0 = (long)nbid * 256;
    for (int idx = t; idx < 256 * 25; idx += 256) {
        const int s = idx / 25, k = idx % 25;
        nsh[s * 26 + k] = n[(s0 + s) * 25 + k];
    }
    for (int idx = t; idx < 256; idx += 256) nsh[idx * 26 + 25] = 1.f;
    __syncthreads();

    const long s = s0 + t;
    float rn = 0.f;
    #pragma unroll 2
    for (int a = 0; a < RK; a++) {
        float u = 0.f;
        #pragma unroll
        for (int b = 0; b < RK; b++) u = fmaf(nsh[t * 26 + b], Ms[b * RK + a], u);
        const __half uh = __float2half_rn(u);
        g_Uhi[s * KP + a] = uh;
        g_Ulo[s * KP + a] = __float2half_rn(u - __half2float(uh));
        const float npv = nsh[t * 26 + a];
        const __half nh = __float2half_rn(npv);
        g_Nhi[s * KP + a] = nh;
        g_Nlo[s * KP + a] = __float2half_rn(npv - __half2float(nh));
        rn = fmaf(u, npv, rn);
    }
    #pragma unroll
    for (int a = RK; a < KP; a++) {
        const __half zz = __float2half_rn(0.f);
        g_Uhi[s * KP + a] = zz; g_Ulo[s * KP + a] = zz;
        g_Nhi[s * KP + a] = zz; g_Nlo[s * KP + a] = zz;
    }
    g_rnG[s] = rn;
}

__global__ __launch_bounds__(256)
void fused_mid_kernel(const float* __restrict__ n,
                      const float* __restrict__ z,
                      const float* __restrict__ znext,
                      const float* __restrict__ prior,
                      float* __restrict__ out,
                      const float* __restrict__ w1W, const float* __restrict__ w1b,
                      const float* __restrict__ b1W, const float* __restrict__ b1b,
                      const float* __restrict__ w2W, const float* __restrict__ w2b,
                      const float* __restrict__ b2W, const float* __restrict__ b2b,
                      const float* __restrict__ w3W, const float* __restrict__ w3b,
                      const float* __restrict__ b3W, const float* __restrict__ b3b)
{
    extern __shared__ float smf[];
    const int bid = blockIdx.x;
    const int t = threadIdx.x;
    if (bid < NDEC) {
        decode_part(bid, t, smf, n, z, znext, out,
                    w1W, w1b, b1W, b1b, w2W, w2b, b2W, b2b, w3W, w3b, b3W, b3b);
    } else if (bid < NDEC + NPP) {
        pp_part(bid - NDEC, t, smf, prior);
    } else {
        np_part(bid - NDEC - NPP, t, smf, n);
    }
}

// ---------------- K4: HMMA fp16-split min-GEMM (both passes) -------------------
#define MT 128
#define NTILE (BATCH / MT)                 // 64
#define NP0 (NTILE * NTILE)                // 4096
#define NP1 (NTILE * (NTILE + 1) / 2)      // 2080
#define ROWH 40                            // padded row stride in halves (80 B)

__global__ __launch_bounds__(256, 2)
void minmin_kernel()
{
    __shared__ __align__(16) __half Ah[MT * ROWH];
    __shared__ __align__(16) __half Al[MT * ROWH];
    __shared__ __align__(16) __half Bh[MT * ROWH];
    __shared__ __align__(16) __half Bl[MT * ROWH];
    __shared__ float rnA[MT], rnB[MT];
    __shared__ float cbuf[2 * MT];
    __shared__ float rbuf[MT * 4];

    const int bid = blockIdx.x;
    const int pass = (bid >= NP0);
    int ib, jb;
    if (!pass) { ib = bid >> 6; jb = bid & 63; }
    else {
        const int t0 = bid - NP0;
        jb = (int)((sqrtf(8.f * (float)t0 + 1.f) - 1.f) * 0.5f);
        while ((jb + 1) * (jb + 2) / 2 <= t0) jb++;
        while (jb * (jb + 1) / 2 > t0) jb--;
        ib = t0 - jb * (jb + 1) / 2;
    }
    const long i0 = (long)ib * MT;
    const long j0 = (long)jb * MT;
    const __half* __restrict__ Ahg = pass ? g_Uhi : g_Phi;
    const __half* __restrict__ Alg = pass ? g_Ulo : g_Plo;
    const float* __restrict__ rnAs = pass ? g_rnG : g_rnP;
    unsigned* colmin                = pass ? g_minG : g_minP;

    const int t = threadIdx.x;

    for (int u = t; u < 512; u += 256) {
        const int r = u >> 2, c = u & 3;
        const long ga = (i0 + r) * KP + c * 8;
        const long gb = (j0 + r) * KP + c * 8;
        *reinterpret_cast<uint4*>(reinterpret_cast<char*>(Ah) + r * 80 + c * 16)
            = *reinterpret_cast<const uint4*>(Ahg + ga);
        *reinterpret_cast<uint4*>(reinterpret_cast<char*>(Al) + r * 80 + c * 16)
            = *reinterpret_cast<const uint4*>(Alg + ga);
        *reinterpret_cast<uint4*>(reinterpret_cast<char*>(Bh) + r * 80 + c * 16)
            = *reinterpret_cast<const uint4*>(g_Nhi + gb);
        *reinterpret_cast<uint4*>(reinterpret_cast<char*>(Bl) + r * 80 + c * 16)
            = *reinterpret_cast<const uint4*>(g_Nlo + gb);
    }
    if (t < MT) rnA[t] = rnAs[i0 + t];
    else rnB[t - MT] = g_rnG[j0 + (t - MT)];
    __syncthreads();

    const uint32_t sAh = smem_u32(Ah), sAl = smem_u32(Al);
    const uint32_t sBh = smem_u32(Bh), sBl = smem_u32(Bl);
    const int lane = t & 31, wid = t >> 5;
    const int wm = wid >> 2;               // 0..1 (64 rows)
    const int wn = wid & 3;                // 0..3 (32 cols)
    const int arow = wm * 64 + (lane & 7) + ((lane >> 3) & 1) * 8;
    const int ahalf = (lane >> 4) & 1;
    const int brow = wn * 32 + (lane & 7) + ((lane >> 4) & 1) * 8;
    const int bhalf = (lane >> 3) & 1;

    float d[4][4][4];
    #pragma unroll
    for (int mi = 0; mi < 4; mi++)
        #pragma unroll
        for (int ni = 0; ni < 4; ni++)
            #pragma unroll
            for (int q = 0; q < 4; q++) d[mi][ni][q] = 0.f;

    #pragma unroll
    for (int ks = 0; ks < 2; ks++) {
        const uint32_t ach = (uint32_t)((ks * 2 + ahalf) * 16);
        const uint32_t bch = (uint32_t)((ks * 2 + bhalf) * 16);
        uint32_t af[4][4], bfh[2][4], bfl[2][4];
        #pragma unroll
        for (int mi = 0; mi < 4; mi++)
            ldsm_x4(af[mi][0], af[mi][1], af[mi][2], af[mi][3],
                    sAh + (uint32_t)((arow + mi * 16) * 80) + ach);
        #pragma unroll
        for (int nb = 0; nb < 2; nb++)
            ldsm_x4(bfh[nb][0], bfh[nb][1], bfh[nb][2], bfh[nb][3],
                    sBh + (uint32_t)((brow + nb * 16) * 80) + bch);
        #pragma unroll
        for (int nb = 0; nb < 2; nb++)
            ldsm_x4(bfl[nb][0], bfl[nb][1], bfl[nb][2], bfl[nb][3],
                    sBl + (uint32_t)((brow + nb * 16) * 80) + bch);
        #pragma unroll
        for (int mi = 0; mi < 4; mi++)
            #pragma unroll
            for (int nb = 0; nb < 2; nb++) {
                mma16816(d[mi][nb * 2],     af[mi], bfh[nb][0], bfh[nb][1]);
                mma16816(d[mi][nb * 2 + 1], af[mi], bfh[nb][2], bfh[nb][3]);
                mma16816(d[mi][nb * 2],     af[mi], bfl[nb][0], bfl[nb][1]);
                mma16816(d[mi][nb * 2 + 1], af[mi], bfl[nb][2], bfl[nb][3]);
            }
        #pragma unroll
        for (int mi = 0; mi < 4; mi++)
            ldsm_x4(af[mi][0], af[mi][1], af[mi][2], af[mi][3],
                    sAl + (uint32_t)((arow + mi * 16) * 80) + ach);
        #pragma unroll
        for (int mi = 0; mi < 4; mi++)
            #pragma unroll
            for (int nb = 0; nb < 2; nb++) {
                mma16816(d[mi][nb * 2],     af[mi], bfh[nb][0], bfh[nb][1]);
                mma16816(d[mi][nb * 2 + 1], af[mi], bfh[nb][2], bfh[nb][3]);
            }
    }

    // ---------------- epilogue -------------------------------------------------
    const int g = lane >> 2, tig = lane & 3;
    float cmin[4][2], rmin[4][2];
    #pragma unroll
    for (int q = 0; q < 4; q++) { cmin[q][0] = 1e30f; cmin[q][1] = 1e30f;
                                  rmin[q][0] = 1e30f; rmin[q][1] = 1e30f; }

    #pragma unroll
    for (int mi = 0; mi < 4; mi++) {
        const int r0 = wm * 64 + mi * 16 + g;
        const long ig0 = i0 + r0;
        const long ig1 = ig0 + 8;
        const float rn0 = rnA[r0];
        const float rn1 = rnA[r0 + 8];
        #pragma unroll
        for (int ni = 0; ni < 4; ni++) {
            const float d0 = d[mi][ni][0], d1 = d[mi][ni][1];
            const float d2 = d[mi][ni][2], d3 = d[mi][ni][3];
            float v0 = fmaf(-2.f, d0, rn0);
            float v1 = fmaf(-2.f, d1, rn0);
            float v2 = fmaf(-2.f, d2, rn1);
            float v3 = fmaf(-2.f, d3, rn1);
            if (pass) {
                const int cc = wn * 32 + ni * 8 + 2 * tig;
                const long jg = j0 + cc;
                float w0 = fmaf(-2.f, d0, rnB[cc]);
                float w1 = fmaf(-2.f, d1, rnB[cc + 1]);
                float w2 = fmaf(-2.f, d2, rnB[cc]);
                float w3 = fmaf(-2.f, d3, rnB[cc + 1]);
                if (ig0 == jg)     { v0 = 1e30f; w0 = 1e30f; }
                if (ig0 == jg + 1) { v1 = 1e30f; w1 = 1e30f; }
                if (ig1 == jg)     { v2 = 1e30f; w2 = 1e30f; }
                if (ig1 == jg + 1) { v3 = 1e30f; w3 = 1e30f; }
                rmin[mi][0] = fminf(rmin[mi][0], fminf(w0, w1));
                rmin[mi][1] = fminf(rmin[mi][1], fminf(w2, w3));
            }
            cmin[ni][0] = fminf(cmin[ni][0], fminf(v0, v2));
            cmin[ni][1] = fminf(cmin[ni][1], fminf(v1, v3));
        }
    }

    #pragma unroll
    for (int off = 4; off <= 16; off <<= 1)
        #pragma unroll
        for (int ni = 0; ni < 4; ni++) {
            cmin[ni][0] = fminf(cmin[ni][0], __shfl_xor_sync(0xFFFFFFFFu, cmin[ni][0], off));
            cmin[ni][1] = fminf(cmin[ni][1], __shfl_xor_sync(0xFFFFFFFFu, cmin[ni][1], off));
        }
    if (pass) {
        #pragma unroll
        for (int off = 1; off <= 2; off <<= 1)
            #pragma unroll
            for (int mi = 0; mi < 4; mi++) {
                rmin[mi][0] = fminf(rmin[mi][0], __shfl_xor_sync(0xFFFFFFFFu, rmin[mi][0], off));
                rmin[mi][1] = fminf(rmin[mi][1], __shfl_xor_sync(0xFFFFFFFFu, rmin[mi][1], off));
            }
    }

    if (lane < 4) {
        #pragma unroll
        for (int ni = 0; ni < 4; ni++) {
            const int col = wn * 32 + ni * 8 + 2 * lane;
            cbuf[wm * MT + col]     = cmin[ni][0];
            cbuf[wm * MT + col + 1] = cmin[ni][1];
        }
    }
    if (pass && tig == 0) {
        #pragma unroll
        for (int mi = 0; mi < 4; mi++) {
            const int r0 = wm * 64 + mi * 16 + g;
            rbuf[r0 * 4 + wn]       = rmin[mi][0];
            rbuf[(r0 + 8) * 4 + wn] = rmin[mi][1];
        }
    }
    __syncthreads();

    if (t < MT) {
        atomicMin(&colmin[j0 + t], fkey(fminf(cbuf[t], cbuf[MT + t])));
        if (pass) {
            const float m2 = fminf(fminf(rbuf[t * 4], rbuf[t * 4 + 1]),
                                   fminf(rbuf[t * 4 + 2], rbuf[t * 4 + 3]));
            atomicMin(&colmin[i0 + t], fkey(m2));
        }
    }
}

// ---------------- K5: final scalar reductions ----------------------------------
__global__ void finalize_kernel(float* __restrict__ out)
{
    __shared__ float s1[1024], s2[1024];
    const int t = threadIdx.x;
    float rsum = 0.f, ksum = 0.f;
    for (int j = t; j < BATCH; j += 1024) {
        rsum += g_recon[j];
        float rn = g_rnG[j];
        float wp = sqrtf(fmaxf(funkey(g_minP[j]) + rn, 0.f) + 1e-8f);
        float ww = sqrtf(fmaxf(funkey(g_minG[j]) + rn, 0.f) + 1e-8f);
        ksum += logf(wp / (ww + 1e-8f) + 1e-8f);
    }
    s1[t] = rsum; s2[t] = ksum;
    __syncthreads();
    for (int off = 512; off > 0; off >>= 1) {
        if (t < off) { s1[t] += s1[t + off]; s2[t] += s2[t + off]; }
        __syncthreads();
    }
    if (t == 0) {
        out[0] = s1[0] / (float)BATCH;
        out[1] = s2[0] / (float)BATCH * (float)DTOT
               + logf((float)BATCH / (float)(BATCH - 1));
    }
}

// ---------------- launch --------------------------------------------------------
extern "C" void kernel_launch(void* const* d_in, const int* in_sizes, int n_in,
                              void* d_out, int out_size)
{
    (void)in_sizes; (void)n_in; (void)out_size;
    const float* z     = (const float*)d_in[0];
    const float* znext = (const float*)d_in[1];
    const float* n     = (const float*)d_in[2];
    const float* prior = (const float*)d_in[3];
    const float* w1W = (const float*)d_in[4];  const float* w1b = (const float*)d_in[5];
    const float* b1W = (const float*)d_in[6];  const float* b1b = (const float*)d_in[7];
    const float* w2W = (const float*)d_in[8];  const float* w2b = (const float*)d_in[9];
    const float* b2W = (const float*)d_in[10]; const float* b2b = (const float*)d_in[11];
    const float* w3W = (const float*)d_in[12]; const float* w3b = (const float*)d_in[13];
    const float* b3W = (const float*)d_in[14]; const float* b3b = (const float*)d_in[15];
    float* out = (float*)d_out;

    cudaFuncSetAttribute(fused_mid_kernel,
                         cudaFuncAttributeMaxDynamicSharedMemorySize,
                         DEC_SMEM_FLOATS * (int)sizeof(float));

    build_Wp_kernel<<<32, 256>>>(
        w1W, w1b, b1W, b1b, w2W, w2b, b2W, b2b, w3W, w3b, b3W, b3b);
    compute_M_kernel<<<RK * RK, 128>>>();
    fused_mid_kernel<<<NDEC + NPP + NNP, 256, DEC_SMEM_FLOATS * sizeof(float)>>>(
        n, z, znext, prior, out,
        w1W, w1b, b1W, b1b, w2W, w2b, b2W, b2b, w3W, w3b, b3W, b3b);
    minmin_kernel<<<NP0 + NP1, 256>>>();
    finalize_kernel<<<1, 1024>>>(out);
}

// round 13
// speedup vs baseline: 16.6465x; 1.0697x over previous
#include <cuda_runtime.h>
#include <cuda_fp16.h>
#include <math.h>
#include <stdint.h>

#define BATCH 8192
#define DTOT  4611
#define RK    26               // rank of G: 25 noise dims + bias
#define KP    32               // fp16 K padded

// ---------------- static device scratch -------------------------------------
__device__ float g_Wp[RK * DTOT];      // W' (26 x 4611)
__device__ float g_M[RK * RK];         // W' W'^T
__device__ __half g_Uhi[(size_t)BATCH * KP];   // hi/lo splits, K padded to 32
__device__ __half g_Ulo[(size_t)BATCH * KP];
__device__ __half g_Nhi[(size_t)BATCH * KP];
__device__ __half g_Nlo[(size_t)BATCH * KP];
__device__ __half g_Phi[(size_t)BATCH * KP];
__device__ __half g_Plo[(size_t)BATCH * KP];
__device__ float    g_rnP[BATCH];
__device__ float    g_rnG[BATCH];
__device__ unsigned g_minP[BATCH];
__device__ unsigned g_minG[BATCH];
__device__ float    g_recon[BATCH];

__device__ __forceinline__ unsigned fkey(float f) {
    unsigned u = __float_as_uint(f);
    return (u & 0x80000000u) ? ~u : (u | 0x80000000u);
}
__device__ __forceinline__ float funkey(unsigned k) {
    unsigned u = (k & 0x80000000u) ? (k ^ 0x80000000u) : ~k;
    return __uint_as_float(u);
}

__device__ __forceinline__ uint32_t smem_u32(const void* p) {
    uint32_t a;
    asm("{ .reg .u64 t; cvta.to.shared.u64 t, %1; cvt.u32.u64 %0, t; }" : "=r"(a) : "l"(p));
    return a;
}
__device__ __forceinline__ void ldsm_x4(uint32_t& r0, uint32_t& r1, uint32_t& r2,
                                        uint32_t& r3, uint32_t addr) {
    asm volatile("ldmatrix.sync.aligned.m8n8.x4.shared.b16 {%0,%1,%2,%3}, [%4];"
                 : "=r"(r0), "=r"(r1), "=r"(r2), "=r"(r3) : "r"(addr));
}
__device__ __forceinline__ void mma16816(float* d, const uint32_t* a,
                                         uint32_t b0, uint32_t b1) {
    asm volatile("mma.sync.aligned.m16n8k16.row.col.f32.f16.f16.f32 "
                 "{%0,%1,%2,%3}, {%4,%5,%6,%7}, {%8,%9}, {%0,%1,%2,%3};"
                 : "+f"(d[0]), "+f"(d[1]), "+f"(d[2]), "+f"(d[3])
                 : "r"(a[0]), "r"(a[1]), "r"(a[2]), "r"(a[3]), "r"(b0), "r"(b1));
}

// ---------------- K1: build W' + init mins -----------------------------------
__global__ void build_Wp_kernel(const float* __restrict__ w1W, const float* __restrict__ w1b,
                                const float* __restrict__ b1W, const float* __restrict__ b1b,
                                const float* __restrict__ w2W, const float* __restrict__ w2b,
                                const float* __restrict__ b2W, const float* __restrict__ b2b,
                                const float* __restrict__ w3W, const float* __restrict__ w3b,
                                const float* __restrict__ b3W, const float* __restrict__ b3b)
{
    const int c = blockIdx.x * 256 + threadIdx.x;          // grid 32 x 256 = 8192
    if (c < BATCH) { g_minP[c] = 0xFFFFFFFFu; g_minG[c] = 0xFFFFFFFFu; }
    if (c >= DTOT) return;
    const float* W; const float* bias; int local, width;
    if      (c < 192)  { W = w1W; bias = w1b; local = c;        width = 192;  }
    else if (c < 256)  { W = b1W; bias = b1b; local = c - 192;  width = 64;   }
    else if (c < 4352) { W = w2W; bias = w2b; local = c - 256;  width = 4096; }
    else if (c < 4416) { W = b2W; bias = b2b; local = c - 4352; width = 64;   }
    else if (c < 4608) { W = w3W; bias = w3b; local = c - 4416; width = 192;  }
    else               { W = b3W; bias = b3b; local = c - 4608; width = 3;    }
    #pragma unroll
    for (int k = 0; k < 25; k++) g_Wp[k * DTOT + c] = W[k * width + local];
    g_Wp[25 * DTOT + c] = bias[local];
}

// ---------------- K2: M = W' W'^T (26 x 26) -----------------------------------
__global__ void compute_M_kernel()
{
    __shared__ float sm[128];
    const int a = blockIdx.x / RK;
    const int b = blockIdx.x % RK;
    const float* ra = g_Wp + (long)a * DTOT;
    const float* rb = g_Wp + (long)b * DTOT;
    float s = 0.f;
    for (int c = threadIdx.x; c < DTOT; c += 128) s += ra[c] * rb[c];
    sm[threadIdx.x] = s;
    __syncthreads();
    for (int off = 64; off > 0; off >>= 1) {
        if (threadIdx.x < off) sm[threadIdx.x] += sm[threadIdx.x + off];
        __syncthreads();
    }
    if (threadIdx.x == 0) g_M[a * RK + b] = sm[0];
}

// ---------------- K3: fused mid-stage — decode | pp | np_u ---------------------
#define NDEC 256          // decode blocks: 32 samples each
#define NPP  256          // pp blocks: 32 prior rows each
#define NNP  32           // np_u blocks: 256 samples each
#define DEC_SMEM_FLOATS 17696

#define CP16(dst, src) \
    asm volatile("cp.async.cg.shared.global [%0], [%1], 16;" \
                 :: "r"(dst), "l"(src) : "memory")
#define CP4(dst, src) \
    asm volatile("cp.async.ca.shared.global [%0], [%1], 4;" \
                 :: "r"(dst), "l"(src) : "memory")

__device__ void decode_part(int bid, int t,
                            float* smf,
                            const float* __restrict__ n,
                            const float* __restrict__ z,
                            const float* __restrict__ znext,
                            float* __restrict__ out,
                            const float* __restrict__ w1W, const float* __restrict__ w1b,
                            const float* __restrict__ b1W, const float* __restrict__ b1b,
                            const float* __restrict__ w2W, const float* __restrict__ w2b,
                            const float* __restrict__ b2W, const float* __restrict__ b2b,
                            const float* __restrict__ w3W, const float* __restrict__ w3b,
                            const float* __restrict__ b3W, const float* __restrict__ b3b)
{
    float* nn   = smf;                 // 832 (32*26)
    float* z3   = nn + 832;            // 128
    float* h1   = z3 + 128;            // 2176 (32*68)
    float* h2   = h1 + 2176;           // 2176
    float* ring = h2 + 2176;           // 12288 (3 x 4096) — stage-A staging reuses this
    float* zh   = ring + 12288;        // 96
    // stage-A staging (inside ring, freed before stage B):
    float* s1W  = ring;                // 4800
    float* s1b  = s1W + 4800;          // 192
    float* sb1W = s1b + 192;           // 1600
    float* sb1b = sb1W + 1600;         // 64

    const long b0 = (long)bid * 32;

    for (int idx = t; idx < 32 * 25; idx += 256) {
        const int s = idx / 25, k = idx % 25;
        nn[s * 26 + k] = n[(b0 + s) * 25 + k];
    }
    for (int idx = t; idx < 32 * 3; idx += 256)
        z3[(idx / 3) * 4 + (idx % 3)] = z[b0 * 3 + idx];
    for (int idx = t; idx < 25 * 192; idx += 256) s1W[idx] = w1W[idx];
    for (int idx = t; idx < 192; idx += 256) s1b[idx] = w1b[idx];
    for (int idx = t; idx < 25 * 64; idx += 256) sb1W[idx] = b1W[idx];
    for (int idx = t; idx < 64; idx += 256) sb1b[idx] = b1b[idx];
    __syncthreads();

    // stage A: h1 (32*64 outputs)
    for (int idx = t; idx < 2048; idx += 256) {
        const int s = idx >> 6, u = idx & 63;
        const float z0 = z3[s * 4], z1 = z3[s * 4 + 1], z2 = z3[s * 4 + 2];
        float acc = sb1b[u] + s1b[u * 3] * z0 + s1b[u * 3 + 1] * z1 + s1b[u * 3 + 2] * z2;
        #pragma unroll
        for (int k = 0; k < 25; k++)
            acc += nn[s * 26 + k] * (s1W[k * 192 + u * 3] * z0
                                   + s1W[k * 192 + u * 3 + 1] * z1
                                   + s1W[k * 192 + u * 3 + 2] * z2
                                   + sb1W[k * 64 + u]);
        h1[s * 68 + u] = (acc > 0.f) ? acc : expm1f(acc);
    }
    __syncthreads();       // stage-A staging dead; ring reclaimed for w2W stream

    // stage B: h2 — 3-stage cp.async ring over w2W k-slices, f32x2 accumulate.
    const int s = t & 31, ig = t >> 5;
    const uint32_t ringa = smem_u32(ring);

    // prefetch chunks 0, 1
    #pragma unroll
    for (int kk = 0; kk < 2; kk++) {
        const float* src = (kk < 25) ? (w2W + (long)kk * 4096) : w2b;
        #pragma unroll
        for (int q = 0; q < 4; q++) {
            const int idx = t + q * 256;
            CP16(ringa + (uint32_t)(kk * 16384 + idx * 16), src + idx * 4);
        }
        asm volatile("cp.async.commit_group;" ::: "memory");
    }

    unsigned long long acc2[8];
    #pragma unroll
    for (int m = 0; m < 8; m++) acc2[m] = 0ULL;

    for (int k = 0; k < 26; k++) {
        if (k < 25) asm volatile("cp.async.wait_group 1;" ::: "memory");
        else        asm volatile("cp.async.wait_group 0;" ::: "memory");
        __syncthreads();
        if (k + 2 < 26) {
            const float* src = (k + 2 < 25) ? (w2W + (long)(k + 2) * 4096) : w2b;
            #pragma unroll
            for (int q = 0; q < 4; q++) {
                const int idx = t + q * 256;
                CP16(ringa + (uint32_t)(((k + 2) % 3) * 16384 + idx * 16), src + idx * 4);
            }
            asm volatile("cp.async.commit_group;" ::: "memory");
        }

        const float* cur = ring + (k % 3) * 4096;
        const float coef = (k < 25) ? nn[s * 26 + k] : 1.f;
        unsigned long long coef2;
        asm("mov.b64 %0, {%1, %1};" : "=l"(coef2) : "f"(coef));

        unsigned long long tk2[8];
        #pragma unroll
        for (int m = 0; m < 8; m++) tk2[m] = 0ULL;
        #pragma unroll 4
        for (int j4 = 0; j4 < 16; j4++) {
            const float4 h4 = *reinterpret_cast<const float4*>(&h1[s * 68 + j4 * 4]);
            unsigned long long h01, h23;
            asm("mov.b64 %0, {%1, %2};" : "=l"(h01) : "f"(h4.x), "f"(h4.y));
            asm("mov.b64 %0, {%1, %2};" : "=l"(h23) : "f"(h4.z), "f"(h4.w));
            #pragma unroll
            for (int m = 0; m < 8; m++) {
                const float4 w4 = *reinterpret_cast<const float4*>(
                    &cur[(ig * 8 + m) * 64 + j4 * 4]);       // warp-broadcast
                unsigned long long w01, w23;
                asm("mov.b64 %0, {%1, %2};" : "=l"(w01) : "f"(w4.x), "f"(w4.y));
                asm("mov.b64 %0, {%1, %2};" : "=l"(w23) : "f"(w4.z), "f"(w4.w));
                asm("fma.rn.f32x2 %0, %1, %2, %0;" : "+l"(tk2[m]) : "l"(h01), "l"(w01));
                asm("fma.rn.f32x2 %0, %1, %2, %0;" : "+l"(tk2[m]) : "l"(h23), "l"(w23));
            }
        }
        #pragma unroll
        for (int m = 0; m < 8; m++)
            asm("fma.rn.f32x2 %0, %1, %2, %0;" : "+l"(acc2[m]) : "l"(coef2), "l"(tk2[m]));
    }

    #pragma unroll
    for (int m = 0; m < 8; m++) {
        const int i = ig * 8 + m;
        float b2 = b2b[i];
        #pragma unroll
        for (int k = 0; k < 25; k++) b2 += nn[s * 26 + k] * b2W[k * 64 + i];
        float lo, hi;
        asm("mov.b64 {%0, %1}, %2;" : "=f"(lo), "=f"(hi) : "l"(acc2[m]));
        const float v = lo + hi + b2;
        h2[s * 68 + i] = (v > 0.f) ? v : expm1f(v);
    }
    __syncthreads();

    // stage C: z_hat (32*3 outputs)
    if (t < 96) {
        const int ss = t / 3, d = t % 3;
        float a3 = b3b[d];
        #pragma unroll
        for (int k = 0; k < 25; k++) a3 += nn[ss * 26 + k] * b3W[k * 3 + d];
        for (int k = 0; k < 26; k++) {
            const float* row = (k < 25) ? (w3W + (long)k * 192 + d * 64) : (w3b + d * 64);
            const float coef = (k < 25) ? nn[ss * 26 + k] : 1.f;
            float tk = 0.f;
            #pragma unroll 8
            for (int j = 0; j < 64; j++) tk = fmaf(row[j], h2[ss * 68 + j], tk);
            a3 = fmaf(coef, tk, a3);
        }
        out[2 + (b0 + ss) * 3 + d] = a3;
        zh[ss * 3 + d] = a3;
    }
    __syncthreads();
    if (t < 32) {
        const float d0 = zh[t * 3]     - znext[(b0 + t) * 3];
        const float d1 = zh[t * 3 + 1] - znext[(b0 + t) * 3 + 1];
        const float d2 = zh[t * 3 + 2] - znext[(b0 + t) * 3 + 2];
        g_recon[b0 + t] = d0 * d0 + d1 * d1 + d2 * d2;
    }
}

// pp: 3-stage cp.async ring, chunk width 96, single sync per chunk.
#define PPKC 96
#define PPSP 100                        // padded sp row stride (floats)
#define PPSTG (32 * PPSP + RK * PPKC)   // 5696 floats per stage
#define PPNCH ((DTOT + PPKC - 1) / PPKC)  // 49

__device__ void pp_issue_chunk(uint32_t stga, int ch, long row0, int t,
                               const float* __restrict__ prior, float* stg)
{
    const int k0 = ch * PPKC;
    for (int idx = t; idx < 32 * PPKC; idx += 256) {
        const int rr = idx / PPKC, c = idx % PPKC;
        if (k0 + c < DTOT)
            CP4(stga + (uint32_t)((rr * PPSP + c) * 4),
                prior + (row0 + rr) * (long)DTOT + k0 + c);
        else
            stg[rr * PPSP + c] = 0.f;
    }
    const uint32_t swa = stga + (uint32_t)(32 * PPSP * 4);
    float* sw = stg + 32 * PPSP;
    for (int idx = t; idx < RK * PPKC; idx += 256) {
        const int m = idx / PPKC, c = idx % PPKC;
        if (k0 + c < DTOT)
            CP4(swa + (uint32_t)((m * PPKC + c) * 4),
                g_Wp + (long)m * DTOT + k0 + c);
        else
            sw[m * PPKC + c] = 0.f;
    }
    asm volatile("cp.async.commit_group;" ::: "memory");
}

__device__ void pp_part(int pbid, int t, float* smf, const float* __restrict__ prior)
{
    const long row0 = (long)pbid * 32;
    const int r = t & 31;
    const int grp = t >> 5;            // warp-uniform, 0..7
    const uint32_t smfa = smem_u32(smf);

    // prefetch chunks 0, 1
    pp_issue_chunk(smfa, 0, row0, t, prior, smf);
    pp_issue_chunk(smfa + (uint32_t)(PPSTG * 4), 1, row0, t, prior, smf + PPSTG);

    unsigned long long acc2[4];
    #pragma unroll
    for (int q = 0; q < 4; q++) acc2[q] = 0ULL;

    for (int ch = 0; ch < PPNCH; ch++) {
        if (ch + 1 < PPNCH) asm volatile("cp.async.wait_group 1;" ::: "memory");
        else                asm volatile("cp.async.wait_group 0;" ::: "memory");
        __syncthreads();   // chunk ch visible; all warps done computing ch-1
        if (ch + 2 < PPNCH) {
            const int st = (ch + 2) % 3;
            pp_issue_chunk(smfa + (uint32_t)(st * PPSTG * 4), ch + 2, row0, t,
                           prior, smf + st * PPSTG);
        }

        const float* sp = smf + (ch % 3) * PPSTG;
        const float* sw = sp + 32 * PPSP;

        #pragma unroll 4
        for (int c4 = 0; c4 < PPKC / 4; c4++) {
            const float4 sp4 = *reinterpret_cast<const float4*>(&sp[r * PPSP + c4 * 4]);
            unsigned long long s01, s23;
            asm("mov.b64 %0, {%1, %2};" : "=l"(s01) : "f"(sp4.x), "f"(sp4.y));
            asm("mov.b64 %0, {%1, %2};" : "=l"(s23) : "f"(sp4.z), "f"(sp4.w));
            #pragma unroll
            for (int q = 0; q < 4; q++) {
                const int m = 4 * grp + q;
                if (m > 26) continue;
                float4 w4;
                if (m < 26)
                    w4 = *reinterpret_cast<const float4*>(&sw[m * PPKC + c4 * 4]);
                else
                    w4 = sp4;          // norm: v*v
                unsigned long long w01, w23;
                asm("mov.b64 %0, {%1, %2};" : "=l"(w01) : "f"(w4.x), "f"(w4.y));
                asm("mov.b64 %0, {%1, %2};" : "=l"(w23) : "f"(w4.z), "f"(w4.w));
                asm("fma.rn.f32x2 %0, %1, %2, %0;" : "+l"(acc2[q]) : "l"(s01), "l"(w01));
                asm("fma.rn.f32x2 %0, %1, %2, %0;" : "+l"(acc2[q]) : "l"(s23), "l"(w23));
            }
        }
    }

    #pragma unroll
    for (int q = 0; q < 4; q++) {
        const int m = 4 * grp + q;
        if (m > 26) continue;
        float lo, hi;
        asm("mov.b64 {%0, %1}, %2;" : "=f"(lo), "=f"(hi) : "l"(acc2[q]));
        const float sum = lo + hi;
        if (m < 26) {
            const __half h = __float2half_rn(sum);
            g_Phi[(row0 + r) * KP + m] = h;
            g_Plo[(row0 + r) * KP + m] = __float2half_rn(sum - __half2float(h));
        } else {
            g_rnP[row0 + r] = sum;
        }
    }
    // zero-pad k = 26..31
    if (t < 192) {
        const int rr = t / 6, kp = 26 + t % 6;
        g_Phi[(row0 + rr) * KP + kp] = __float2half_rn(0.f);
        g_Plo[(row0 + rr) * KP + kp] = __float2half_rn(0.f);
    }
}

__device__ void np_part(int nbid, int t, float* smf, const float* __restrict__ n)
{
    float* Ms  = smf;                  // 676
    float* nsh = Ms + 676;             // 256 x 26

    for (int idx = t; idx < RK * RK; idx += 256) Ms[idx] = g_M[idx];
    const long s0 = (long)nbid * 256;
    for (int idx = t; idx < 256 * 25; idx += 256) {
        const int s = idx / 25, k = idx % 25;
        nsh[s * 26 + k] = n[(s0 + s) * 25 + k];
    }
    for (int idx = t; idx < 256; idx += 256) nsh[idx * 26 + 25] = 1.f;
    __syncthreads();

    const long s = s0 + t;
    float rn = 0.f;
    #pragma unroll 2
    for (int a = 0; a < RK; a++) {
        float u = 0.f;
        #pragma unroll
        for (int b = 0; b < RK; b++) u = fmaf(nsh[t * 26 + b], Ms[b * RK + a], u);
        const __half uh = __float2half_rn(u);
        g_Uhi[s * KP + a] = uh;
        g_Ulo[s * KP + a] = __float2half_rn(u - __half2float(uh));
        const float npv = nsh[t * 26 + a];
        const __half nh = __float2half_rn(npv);
        g_Nhi[s * KP + a] = nh;
        g_Nlo[s * KP + a] = __float2half_rn(npv - __half2float(nh));
        rn = fmaf(u, npv, rn);
    }
    #pragma unroll
    for (int a = RK; a < KP; a++) {
        const __half zz = __float2half_rn(0.f);
        g_Uhi[s * KP + a] = zz; g_Ulo[s * KP + a] = zz;
        g_Nhi[s * KP + a] = zz; g_Nlo[s * KP + a] = zz;
    }
    g_rnG[s] = rn;
}

// 3 blocks/SM: regs capped (~85) so occupancy is smem-bound (3 x 70.8 KB).
__global__ __launch_bounds__(256, 3)
void fused_mid_kernel(const float* __restrict__ n,
                      const float* __restrict__ z,
                      const float* __restrict__ znext,
                      const float* __restrict__ prior,
                      float* __restrict__ out,
                      const float* __restrict__ w1W, const float* __restrict__ w1b,
                      const float* __restrict__ b1W, const float* __restrict__ b1b,
                      const float* __restrict__ w2W, const float* __restrict__ w2b,
                      const float* __restrict__ b2W, const float* __restrict__ b2b,
                      const float* __restrict__ w3W, const float* __restrict__ w3b,
                      const float* __restrict__ b3W, const float* __restrict__ b3b)
{
    extern __shared__ float smf[];
    const int bid = blockIdx.x;
    const int t = threadIdx.x;
    if (bid < NDEC) {
        decode_part(bid, t, smf, n, z, znext, out,
                    w1W, w1b, b1W, b1b, w2W, w2b, b2W, b2b, w3W, w3b, b3W, b3b);
    } else if (bid < NDEC + NPP) {
        pp_part(bid - NDEC, t, smf, prior);
    } else {
        np_part(bid - NDEC - NPP, t, smf, n);
    }
}

// ---------------- K4: HMMA fp16-split min-GEMM (both passes) -------------------
#define MT 128
#define NTILE (BATCH / MT)                 // 64
#define NP0 (NTILE * NTILE)                // 4096
#define NP1 (NTILE * (NTILE + 1) / 2)      // 2080
#define ROWH 40                            // padded row stride in halves (80 B)

__global__ __launch_bounds__(256, 2)
void minmin_kernel()
{
    __shared__ __align__(16) __half Ah[MT * ROWH];
    __shared__ __align__(16) __half Al[MT * ROWH];
    __shared__ __align__(16) __half Bh[MT * ROWH];
    __shared__ __align__(16) __half Bl[MT * ROWH];
    __shared__ float rnA[MT], rnB[MT];
    __shared__ float cbuf[2 * MT];
    __shared__ float rbuf[MT * 4];

    const int bid = blockIdx.x;
    const int pass = (bid >= NP0);
    int ib, jb;
    if (!pass) { ib = bid >> 6; jb = bid & 63; }
    else {
        const int t0 = bid - NP0;
        jb = (int)((sqrtf(8.f * (float)t0 + 1.f) - 1.f) * 0.5f);
        while ((jb + 1) * (jb + 2) / 2 <= t0) jb++;
        while (jb * (jb + 1) / 2 > t0) jb--;
        ib = t0 - jb * (jb + 1) / 2;
    }
    const long i0 = (long)ib * MT;
    const long j0 = (long)jb * MT;
    const __half* __restrict__ Ahg = pass ? g_Uhi : g_Phi;
    const __half* __restrict__ Alg = pass ? g_Ulo : g_Plo;
    const float* __restrict__ rnAs = pass ? g_rnG : g_rnP;
    unsigned* colmin                = pass ? g_minG : g_minP;

    const int t = threadIdx.x;

    for (int u = t; u < 512; u += 256) {
        const int r = u >> 2, c = u & 3;
        const long ga = (i0 + r) * KP + c * 8;
        const long gb = (j0 + r) * KP + c * 8;
        *reinterpret_cast<uint4*>(reinterpret_cast<char*>(Ah) + r * 80 + c * 16)
            = *reinterpret_cast<const uint4*>(Ahg + ga);
        *reinterpret_cast<uint4*>(reinterpret_cast<char*>(Al) + r * 80 + c * 16)
            = *reinterpret_cast<const uint4*>(Alg + ga);
        *reinterpret_cast<uint4*>(reinterpret_cast<char*>(Bh) + r * 80 + c * 16)
            = *reinterpret_cast<const uint4*>(g_Nhi + gb);
        *reinterpret_cast<uint4*>(reinterpret_cast<char*>(Bl) + r * 80 + c * 16)
            = *reinterpret_cast<const uint4*>(g_Nlo + gb);
    }
    if (t < MT) rnA[t] = rnAs[i0 + t];
    else rnB[t - MT] = g_rnG[j0 + (t - MT)];
    __syncthreads();

    const uint32_t sAh = smem_u32(Ah), sAl = smem_u32(Al);
    const uint32_t sBh = smem_u32(Bh), sBl = smem_u32(Bl);
    const int lane = t & 31, wid = t >> 5;
    const int wm = wid >> 2;               // 0..1 (64 rows)
    const int wn = wid & 3;                // 0..3 (32 cols)
    const int arow = wm * 64 + (lane & 7) + ((lane >> 3) & 1) * 8;
    const int ahalf = (lane >> 4) & 1;
    const int brow = wn * 32 + (lane & 7) + ((lane >> 4) & 1) * 8;
    const int bhalf = (lane >> 3) & 1;

    float d[4][4][4];
    #pragma unroll
    for (int mi = 0; mi < 4; mi++)
        #pragma unroll
        for (int ni = 0; ni < 4; ni++)
            #pragma unroll
            for (int q = 0; q < 4; q++) d[mi][ni][q] = 0.f;

    #pragma unroll
    for (int ks = 0; ks < 2; ks++) {
        const uint32_t ach = (uint32_t)((ks * 2 + ahalf) * 16);
        const uint32_t bch = (uint32_t)((ks * 2 + bhalf) * 16);
        uint32_t af[4][4], bfh[2][4], bfl[2][4];
        #pragma unroll
        for (int mi = 0; mi < 4; mi++)
            ldsm_x4(af[mi][0], af[mi][1], af[mi][2], af[mi][3],
                    sAh + (uint32_t)((arow + mi * 16) * 80) + ach);
        #pragma unroll
        for (int nb = 0; nb < 2; nb++)
            ldsm_x4(bfh[nb][0], bfh[nb][1], bfh[nb][2], bfh[nb][3],
                    sBh + (uint32_t)((brow + nb * 16) * 80) + bch);
        #pragma unroll
        for (int nb = 0; nb < 2; nb++)
            ldsm_x4(bfl[nb][0], bfl[nb][1], bfl[nb][2], bfl[nb][3],
                    sBl + (uint32_t)((brow + nb * 16) * 80) + bch);
        #pragma unroll
        for (int mi = 0; mi < 4; mi++)
            #pragma unroll
            for (int nb = 0; nb < 2; nb++) {
                mma16816(d[mi][nb * 2],     af[mi], bfh[nb][0], bfh[nb][1]);
                mma16816(d[mi][nb * 2 + 1], af[mi], bfh[nb][2], bfh[nb][3]);
                mma16816(d[mi][nb * 2],     af[mi], bfl[nb][0], bfl[nb][1]);
                mma16816(d[mi][nb * 2 + 1], af[mi], bfl[nb][2], bfl[nb][3]);
            }
        #pragma unroll
        for (int mi = 0; mi < 4; mi++)
            ldsm_x4(af[mi][0], af[mi][1], af[mi][2], af[mi][3],
                    sAl + (uint32_t)((arow + mi * 16) * 80) + ach);
        #pragma unroll
        for (int mi = 0; mi < 4; mi++)
            #pragma unroll
            for (int nb = 0; nb < 2; nb++) {
                mma16816(d[mi][nb * 2],     af[mi], bfh[nb][0], bfh[nb][1]);
                mma16816(d[mi][nb * 2 + 1], af[mi], bfh[nb][2], bfh[nb][3]);
            }
    }

    // ---------------- epilogue -------------------------------------------------
    const int g = lane >> 2, tig = lane & 3;
    float cmin[4][2], rmin[4][2];
    #pragma unroll
    for (int q = 0; q < 4; q++) { cmin[q][0] = 1e30f; cmin[q][1] = 1e30f;
                                  rmin[q][0] = 1e30f; rmin[q][1] = 1e30f; }

    #pragma unroll
    for (int mi = 0; mi < 4; mi++) {
        const int r0 = wm * 64 + mi * 16 + g;
        const long ig0 = i0 + r0;
        const long ig1 = ig0 + 8;
        const float rn0 = rnA[r0];
        const float rn1 = rnA[r0 + 8];
        #pragma unroll
        for (int ni = 0; ni < 4; ni++) {
            const float d0 = d[mi][ni][0], d1 = d[mi][ni][1];
            const float d2 = d[mi][ni][2], d3 = d[mi][ni][3];
            float v0 = fmaf(-2.f, d0, rn0);
            float v1 = fmaf(-2.f, d1, rn0);
            float v2 = fmaf(-2.f, d2, rn1);
            float v3 = fmaf(-2.f, d3, rn1);
            if (pass) {
                const int cc = wn * 32 + ni * 8 + 2 * tig;
                const long jg = j0 + cc;
                float w0 = fmaf(-2.f, d0, rnB[cc]);
                float w1 = fmaf(-2.f, d1, rnB[cc + 1]);
                float w2 = fmaf(-2.f, d2, rnB[cc]);
                float w3 = fmaf(-2.f, d3, rnB[cc + 1]);
                if (ig0 == jg)     { v0 = 1e30f; w0 = 1e30f; }
                if (ig0 == jg + 1) { v1 = 1e30f; w1 = 1e30f; }
                if (ig1 == jg)     { v2 = 1e30f; w2 = 1e30f; }
                if (ig1 == jg + 1) { v3 = 1e30f; w3 = 1e30f; }
                rmin[mi][0] = fminf(rmin[mi][0], fminf(w0, w1));
                rmin[mi][1] = fminf(rmin[mi][1], fminf(w2, w3));
            }
            cmin[ni][0] = fminf(cmin[ni][0], fminf(v0, v2));
            cmin[ni][1] = fminf(cmin[ni][1], fminf(v1, v3));
        }
    }

    #pragma unroll
    for (int off = 4; off <= 16; off <<= 1)
        #pragma unroll
        for (int ni = 0; ni < 4; ni++) {
            cmin[ni][0] = fminf(cmin[ni][0], __shfl_xor_sync(0xFFFFFFFFu, cmin[ni][0], off));
            cmin[ni][1] = fminf(cmin[ni][1], __shfl_xor_sync(0xFFFFFFFFu, cmin[ni][1], off));
        }
    if (pass) {
        #pragma unroll
        for (int off = 1; off <= 2; off <<= 1)
            #pragma unroll
            for (int mi = 0; mi < 4; mi++) {
                rmin[mi][0] = fminf(rmin[mi][0], __shfl_xor_sync(0xFFFFFFFFu, rmin[mi][0], off));
                rmin[mi][1] = fminf(rmin[mi][1], __shfl_xor_sync(0xFFFFFFFFu, rmin[mi][1], off));
            }
    }

    if (lane < 4) {
        #pragma unroll
        for (int ni = 0; ni < 4; ni++) {
            const int col = wn * 32 + ni * 8 + 2 * lane;
            cbuf[wm * MT + col]     = cmin[ni][0];
            cbuf[wm * MT + col + 1] = cmin[ni][1];
        }
    }
    if (pass && tig == 0) {
        #pragma unroll
        for (int mi = 0; mi < 4; mi++) {
            const int r0 = wm * 64 + mi * 16 + g;
            rbuf[r0 * 4 + wn]       = rmin[mi][0];
            rbuf[(r0 + 8) * 4 + wn] = rmin[mi][1];
        }
    }
    __syncthreads();

    if (t < MT) {
        atomicMin(&colmin[j0 + t], fkey(fminf(cbuf[t], cbuf[MT + t])));
        if (pass) {
            const float m2 = fminf(fminf(rbuf[t * 4], rbuf[t * 4 + 1]),
                                   fminf(rbuf[t * 4 + 2], rbuf[t * 4 + 3]));
            atomicMin(&colmin[i0 + t], fkey(m2));
        }
    }
}

// ---------------- K5: final scalar reductions ----------------------------------
__global__ void finalize_kernel(float* __restrict__ out)
{
    __shared__ float s1[1024], s2[1024];
    const int t = threadIdx.x;
    float rsum = 0.f, ksum = 0.f;
    for (int j = t; j < BATCH; j += 1024) {
        rsum += g_recon[j];
        float rn = g_rnG[j];
        float wp = sqrtf(fmaxf(funkey(g_minP[j]) + rn, 0.f) + 1e-8f);
        float ww = sqrtf(fmaxf(funkey(g_minG[j]) + rn, 0.f) + 1e-8f);
        ksum += logf(wp / (ww + 1e-8f) + 1e-8f);
    }
    s1[t] = rsum; s2[t] = ksum;
    __syncthreads();
    for (int off = 512; off > 0; off >>= 1) {
        if (t < off) { s1[t] += s1[t + off]; s2[t] += s2[t + off]; }
        __syncthreads();
    }
    if (t == 0) {
        out[0] = s1[0] / (float)BATCH;
        out[1] = s2[0] / (float)BATCH * (float)DTOT
               + logf((float)BATCH / (float)(BATCH - 1));
    }
}

// ---------------- launch --------------------------------------------------------
extern "C" void kernel_launch(void* const* d_in, const int* in_sizes, int n_in,
                              void* d_out, int out_size)
{
    (void)in_sizes; (void)n_in; (void)out_size;
    const float* z     = (const float*)d_in[0];
    const float* znext = (const float*)d_in[1];
    const float* n     = (const float*)d_in[2];
    const float* prior = (const float*)d_in[3];
    const float* w1W = (const float*)d_in[4];  const float* w1b = (const float*)d_in[5];
    const float* b1W = (const float*)d_in[6];  const float* b1b = (const float*)d_in[7];
    const float* w2W = (const float*)d_in[8];  const float* w2b = (const float*)d_in[9];
    const float* b2W = (const float*)d_in[10]; const float* b2b = (const float*)d_in[11];
    const float* w3W = (const float*)d_in[12]; const float* w3b = (const float*)d_in[13];
    const float* b3W = (const float*)d_in[14]; const float* b3b = (const float*)d_in[15];
    float* out = (float*)d_out;

    cudaFuncSetAttribute(fused_mid_kernel,
                         cudaFuncAttributeMaxDynamicSharedMemorySize,
                         DEC_SMEM_FLOATS * (int)sizeof(float));

    build_Wp_kernel<<<32, 256>>>(
        w1W, w1b, b1W, b1b, w2W, w2b, b2W, b2b, w3W, w3b, b3W, b3b);
    compute_M_kernel<<<RK * RK, 128>>>();
    fused_mid_kernel<<<NDEC + NPP + NNP, 256, DEC_SMEM_FLOATS * sizeof(float)>>>(
        n, z, znext, prior, out,
        w1W, w1b, b1W, b1b, w2W, w2b, b2W, b2b, w3W, w3b, b3W, b3b);
    minmin_kernel<<<NP0 + NP1, 256>>>();
    finalize_kernel<<<1, 1024>>>(out);
}

// round 14
// speedup vs baseline: 16.7435x; 1.0058x over previous
#include <cuda_runtime.h>
#include <cuda_fp16.h>
#include <math.h>
#include <stdint.h>

#define BATCH 8192
#define DTOT  4611
#define RK    26               // rank of G: 25 noise dims + bias
#define KP    32               // fp16 K padded

// ---------------- static device scratch -------------------------------------
__device__ float g_Wp[RK * DTOT];      // W' (26 x 4611)
__device__ float g_M[RK * RK];         // W' W'^T
__device__ __half g_Uhi[(size_t)BATCH * KP];   // hi/lo splits, K padded to 32
__device__ __half g_Ulo[(size_t)BATCH * KP];
__device__ __half g_Nhi[(size_t)BATCH * KP];
__device__ __half g_Nlo[(size_t)BATCH * KP];
__device__ __half g_Phi[(size_t)BATCH * KP];
__device__ __half g_Plo[(size_t)BATCH * KP];
__device__ float    g_rnP[BATCH];
__device__ float    g_rnG[BATCH];
__device__ unsigned g_minP[BATCH];
__device__ unsigned g_minG[BATCH];
__device__ float    g_recon[BATCH];

__device__ __forceinline__ unsigned fkey(float f) {
    unsigned u = __float_as_uint(f);
    return (u & 0x80000000u) ? ~u : (u | 0x80000000u);
}
__device__ __forceinline__ float funkey(unsigned k) {
    unsigned u = (k & 0x80000000u) ? (k ^ 0x80000000u) : ~k;
    return __uint_as_float(u);
}

__device__ __forceinline__ uint32_t smem_u32(const void* p) {
    uint32_t a;
    asm("{ .reg .u64 t; cvta.to.shared.u64 t, %1; cvt.u32.u64 %0, t; }" : "=r"(a) : "l"(p));
    return a;
}
__device__ __forceinline__ void ldsm_x4(uint32_t& r0, uint32_t& r1, uint32_t& r2,
                                        uint32_t& r3, uint32_t addr) {
    asm volatile("ldmatrix.sync.aligned.m8n8.x4.shared.b16 {%0,%1,%2,%3}, [%4];"
                 : "=r"(r0), "=r"(r1), "=r"(r2), "=r"(r3) : "r"(addr));
}
__device__ __forceinline__ void mma16816(float* d, const uint32_t* a,
                                         uint32_t b0, uint32_t b1) {
    asm volatile("mma.sync.aligned.m16n8k16.row.col.f32.f16.f16.f32 "
                 "{%0,%1,%2,%3}, {%4,%5,%6,%7}, {%8,%9}, {%0,%1,%2,%3};"
                 : "+f"(d[0]), "+f"(d[1]), "+f"(d[2]), "+f"(d[3])
                 : "r"(a[0]), "r"(a[1]), "r"(a[2]), "r"(a[3]), "r"(b0), "r"(b1));
}

// raw-weight selector: segment for column c of W'
__device__ __forceinline__ void wp_sel(int c,
                                       const float* w1W, const float* w1b,
                                       const float* b1W, const float* b1b,
                                       const float* w2W, const float* w2b,
                                       const float* b2W, const float* b2b,
                                       const float* w3W, const float* w3b,
                                       const float* b3W, const float* b3b,
                                       const float** W, const float** bias,
                                       int* local, int* width)
{
    if      (c < 192)  { *W = w1W; *bias = w1b; *local = c;        *width = 192;  }
    else if (c < 256)  { *W = b1W; *bias = b1b; *local = c - 192;  *width = 64;   }
    else if (c < 4352) { *W = w2W; *bias = w2b; *local = c - 256;  *width = 4096; }
    else if (c < 4416) { *W = b2W; *bias = b2b; *local = c - 4352; *width = 64;   }
    else if (c < 4608) { *W = w3W; *bias = w3b; *local = c - 4416; *width = 192;  }
    else               { *W = b3W; *bias = b3b; *local = c - 4608; *width = 3;    }
}

// ---------------- K1: prep — build W' + init mins | compute M (raw) -----------
// blocks 0..31: build g_Wp + init colmins; blocks 32..707: M[a][b] from raw
__global__ __launch_bounds__(256)
void prep_kernel(const float* __restrict__ w1W, const float* __restrict__ w1b,
                 const float* __restrict__ b1W, const float* __restrict__ b1b,
                 const float* __restrict__ w2W, const float* __restrict__ w2b,
                 const float* __restrict__ b2W, const float* __restrict__ b2b,
                 const float* __restrict__ w3W, const float* __restrict__ w3b,
                 const float* __restrict__ b3W, const float* __restrict__ b3b)
{
    if (blockIdx.x < 32) {
        const int c = blockIdx.x * 256 + threadIdx.x;
        if (c < BATCH) { g_minP[c] = 0xFFFFFFFFu; g_minG[c] = 0xFFFFFFFFu; }
        if (c >= DTOT) return;
        const float* W; const float* bias; int local, width;
        wp_sel(c, w1W, w1b, b1W, b1b, w2W, w2b, b2W, b2b, w3W, w3b, b3W, b3b,
               &W, &bias, &local, &width);
        #pragma unroll
        for (int k = 0; k < 25; k++) g_Wp[k * DTOT + c] = W[k * width + local];
        g_Wp[25 * DTOT + c] = bias[local];
    } else {
        __shared__ float sm[256];
        const int p = blockIdx.x - 32;          // 0..675
        const int a = p / RK, b = p % RK;
        float s = 0.f;
        for (int c = threadIdx.x; c < DTOT; c += 256) {
            const float* W; const float* bias; int local, width;
            wp_sel(c, w1W, w1b, b1W, b1b, w2W, w2b, b2W, b2b, w3W, w3b, b3W, b3b,
                   &W, &bias, &local, &width);
            const float va = (a < 25) ? W[a * width + local] : bias[local];
            const float vb = (b < 25) ? W[b * width + local] : bias[local];
            s += va * vb;
        }
        sm[threadIdx.x] = s;
        __syncthreads();
        for (int off = 128; off > 0; off >>= 1) {
            if (threadIdx.x < off) sm[threadIdx.x] += sm[threadIdx.x + off];
            __syncthreads();
        }
        if (threadIdx.x == 0) g_M[a * RK + b] = sm[0];
    }
}

// ---------------- K2: fused mid-stage — decode | pp | np_u ---------------------
#define NDEC 256          // decode blocks: 32 samples each
#define NPP  256          // pp blocks: 32 prior rows each
#define NNP  32           // np_u blocks: 256 samples each
#define DEC_SMEM_FLOATS 17696

#define CP16(dst, src) \
    asm volatile("cp.async.cg.shared.global [%0], [%1], 16;" \
                 :: "r"(dst), "l"(src) : "memory")
#define CP4(dst, src) \
    asm volatile("cp.async.ca.shared.global [%0], [%1], 4;" \
                 :: "r"(dst), "l"(src) : "memory")

__device__ void decode_part(int bid, int t,
                            float* smf,
                            const float* __restrict__ n,
                            const float* __restrict__ z,
                            const float* __restrict__ znext,
                            float* __restrict__ out,
                            const float* __restrict__ w1W, const float* __restrict__ w1b,
                            const float* __restrict__ b1W, const float* __restrict__ b1b,
                            const float* __restrict__ w2W, const float* __restrict__ w2b,
                            const float* __restrict__ b2W, const float* __restrict__ b2b,
                            const float* __restrict__ w3W, const float* __restrict__ w3b,
                            const float* __restrict__ b3W, const float* __restrict__ b3b)
{
    float* nn   = smf;                 // 832 (32*26)
    float* z3   = nn + 832;            // 128
    float* h1   = z3 + 128;            // 2176 (32*68)
    float* h2   = h1 + 2176;           // 2176
    float* ring = h2 + 2176;           // 12288 (3 x 4096) — stage-A staging reuses this
    float* zh   = ring + 12288;        // 96
    // stage-A staging (inside ring, freed before stage B):
    float* s1W  = ring;                // 4800
    float* s1b  = s1W + 4800;          // 192
    float* sb1W = s1b + 192;           // 1600
    float* sb1b = sb1W + 1600;         // 64

    const long b0 = (long)bid * 32;

    for (int idx = t; idx < 32 * 25; idx += 256) {
        const int s = idx / 25, k = idx % 25;
        nn[s * 26 + k] = n[(b0 + s) * 25 + k];
    }
    for (int idx = t; idx < 32 * 3; idx += 256)
        z3[(idx / 3) * 4 + (idx % 3)] = z[b0 * 3 + idx];
    for (int idx = t; idx < 25 * 192; idx += 256) s1W[idx] = w1W[idx];
    for (int idx = t; idx < 192; idx += 256) s1b[idx] = w1b[idx];
    for (int idx = t; idx < 25 * 64; idx += 256) sb1W[idx] = b1W[idx];
    for (int idx = t; idx < 64; idx += 256) sb1b[idx] = b1b[idx];
    __syncthreads();

    // stage A: h1 (32*64 outputs)
    for (int idx = t; idx < 2048; idx += 256) {
        const int s = idx >> 6, u = idx & 63;
        const float z0 = z3[s * 4], z1 = z3[s * 4 + 1], z2 = z3[s * 4 + 2];
        float acc = sb1b[u] + s1b[u * 3] * z0 + s1b[u * 3 + 1] * z1 + s1b[u * 3 + 2] * z2;
        #pragma unroll
        for (int k = 0; k < 25; k++)
            acc += nn[s * 26 + k] * (s1W[k * 192 + u * 3] * z0
                                   + s1W[k * 192 + u * 3 + 1] * z1
                                   + s1W[k * 192 + u * 3 + 2] * z2
                                   + sb1W[k * 64 + u]);
        h1[s * 68 + u] = (acc > 0.f) ? acc : expm1f(acc);
    }
    __syncthreads();       // stage-A staging dead; ring reclaimed for w2W stream

    // stage B: h2 — 3-stage cp.async ring; prescaled-h f32x2 accumulate
    const int s = t & 31, ig = t >> 5;
    const uint32_t ringa = smem_u32(ring);

    // prefetch chunks 0, 1
    #pragma unroll
    for (int kk = 0; kk < 2; kk++) {
        const float* src = (kk < 25) ? (w2W + (long)kk * 4096) : w2b;
        #pragma unroll
        for (int q = 0; q < 4; q++) {
            const int idx = t + q * 256;
            CP16(ringa + (uint32_t)(kk * 16384 + idx * 16), src + idx * 4);
        }
        asm volatile("cp.async.commit_group;" ::: "memory");
    }

    unsigned long long acc2[8];
    #pragma unroll
    for (int m = 0; m < 8; m++) acc2[m] = 0ULL;

    for (int k = 0; k < 26; k++) {
        if (k < 25) asm volatile("cp.async.wait_group 1;" ::: "memory");
        else        asm volatile("cp.async.wait_group 0;" ::: "memory");
        __syncthreads();
        if (k + 2 < 26) {
            const float* src = (k + 2 < 25) ? (w2W + (long)(k + 2) * 4096) : w2b;
            #pragma unroll
            for (int q = 0; q < 4; q++) {
                const int idx = t + q * 256;
                CP16(ringa + (uint32_t)(((k + 2) % 3) * 16384 + idx * 16), src + idx * 4);
            }
            asm volatile("cp.async.commit_group;" ::: "memory");
        }

        const float* cur = ring + (k % 3) * 4096;
        const float coef = (k < 25) ? nn[s * 26 + k] : 1.f;
        unsigned long long coef2;
        asm("mov.b64 %0, {%1, %1};" : "=l"(coef2) : "f"(coef));

        #pragma unroll 4
        for (int j4 = 0; j4 < 16; j4++) {
            const float4 h4 = *reinterpret_cast<const float4*>(&h1[s * 68 + j4 * 4]);
            unsigned long long h01, h23, ch01, ch23;
            asm("mov.b64 %0, {%1, %2};" : "=l"(h01) : "f"(h4.x), "f"(h4.y));
            asm("mov.b64 %0, {%1, %2};" : "=l"(h23) : "f"(h4.z), "f"(h4.w));
            asm("mul.rn.f32x2 %0, %1, %2;" : "=l"(ch01) : "l"(coef2), "l"(h01));
            asm("mul.rn.f32x2 %0, %1, %2;" : "=l"(ch23) : "l"(coef2), "l"(h23));
            #pragma unroll
            for (int m = 0; m < 8; m++) {
                const float4 w4 = *reinterpret_cast<const float4*>(
                    &cur[(ig * 8 + m) * 64 + j4 * 4]);       // warp-broadcast
                unsigned long long w01, w23;
                asm("mov.b64 %0, {%1, %2};" : "=l"(w01) : "f"(w4.x), "f"(w4.y));
                asm("mov.b64 %0, {%1, %2};" : "=l"(w23) : "f"(w4.z), "f"(w4.w));
                asm("fma.rn.f32x2 %0, %1, %2, %0;" : "+l"(acc2[m]) : "l"(ch01), "l"(w01));
                asm("fma.rn.f32x2 %0, %1, %2, %0;" : "+l"(acc2[m]) : "l"(ch23), "l"(w23));
            }
        }
    }

    #pragma unroll
    for (int m = 0; m < 8; m++) {
        const int i = ig * 8 + m;
        float b2 = b2b[i];
        #pragma unroll
        for (int k = 0; k < 25; k++) b2 += nn[s * 26 + k] * b2W[k * 64 + i];
        float lo, hi;
        asm("mov.b64 {%0, %1}, %2;" : "=f"(lo), "=f"(hi) : "l"(acc2[m]));
        const float v = lo + hi + b2;
        h2[s * 68 + i] = (v > 0.f) ? v : expm1f(v);
    }
    __syncthreads();

    // stage C: z_hat (32*3 outputs)
    if (t < 96) {
        const int ss = t / 3, d = t % 3;
        float a3 = b3b[d];
        #pragma unroll
        for (int k = 0; k < 25; k++) a3 += nn[ss * 26 + k] * b3W[k * 3 + d];
        for (int k = 0; k < 26; k++) {
            const float* row = (k < 25) ? (w3W + (long)k * 192 + d * 64) : (w3b + d * 64);
            const float coef = (k < 25) ? nn[ss * 26 + k] : 1.f;
            float tk = 0.f;
            #pragma unroll 8
            for (int j = 0; j < 64; j++) tk = fmaf(row[j], h2[ss * 68 + j], tk);
            a3 = fmaf(coef, tk, a3);
        }
        out[2 + (b0 + ss) * 3 + d] = a3;
        zh[ss * 3 + d] = a3;
    }
    __syncthreads();
    if (t < 32) {
        const float d0 = zh[t * 3]     - znext[(b0 + t) * 3];
        const float d1 = zh[t * 3 + 1] - znext[(b0 + t) * 3 + 1];
        const float d2 = zh[t * 3 + 2] - znext[(b0 + t) * 3 + 2];
        g_recon[b0 + t] = d0 * d0 + d1 * d1 + d2 * d2;
    }
}

// pp: 3-stage cp.async ring, chunk width 96, single sync per chunk.
#define PPKC 96
#define PPSP 100                        // padded sp row stride (floats)
#define PPSTG (32 * PPSP + RK * PPKC)   // 5696 floats per stage
#define PPNCH ((DTOT + PPKC - 1) / PPKC)  // 49

__device__ void pp_issue_chunk(uint32_t stga, int ch, long row0, int t,
                               const float* __restrict__ prior, float* stg)
{
    const int k0 = ch * PPKC;
    for (int idx = t; idx < 32 * PPKC; idx += 256) {
        const int rr = idx / PPKC, c = idx % PPKC;
        if (k0 + c < DTOT)
            CP4(stga + (uint32_t)((rr * PPSP + c) * 4),
                prior + (row0 + rr) * (long)DTOT + k0 + c);
        else
            stg[rr * PPSP + c] = 0.f;
    }
    const uint32_t swa = stga + (uint32_t)(32 * PPSP * 4);
    float* sw = stg + 32 * PPSP;
    for (int idx = t; idx < RK * PPKC; idx += 256) {
        const int m = idx / PPKC, c = idx % PPKC;
        if (k0 + c < DTOT)
            CP4(swa + (uint32_t)((m * PPKC + c) * 4),
                g_Wp + (long)m * DTOT + k0 + c);
        else
            sw[m * PPKC + c] = 0.f;
    }
    asm volatile("cp.async.commit_group;" ::: "memory");
}

__device__ void pp_part(int pbid, int t, float* smf, const float* __restrict__ prior)
{
    const long row0 = (long)pbid * 32;
    const int r = t & 31;
    const int grp = t >> 5;            // warp-uniform, 0..7
    const uint32_t smfa = smem_u32(smf);

    pp_issue_chunk(smfa, 0, row0, t, prior, smf);
    pp_issue_chunk(smfa + (uint32_t)(PPSTG * 4), 1, row0, t, prior, smf + PPSTG);

    unsigned long long acc2[4];
    #pragma unroll
    for (int q = 0; q < 4; q++) acc2[q] = 0ULL;

    for (int ch = 0; ch < PPNCH; ch++) {
        if (ch + 1 < PPNCH) asm volatile("cp.async.wait_group 1;" ::: "memory");
        else                asm volatile("cp.async.wait_group 0;" ::: "memory");
        __syncthreads();
        if (ch + 2 < PPNCH) {
            const int st = (ch + 2) % 3;
            pp_issue_chunk(smfa + (uint32_t)(st * PPSTG * 4), ch + 2, row0, t,
                           prior, smf + st * PPSTG);
        }

        const float* sp = smf + (ch % 3) * PPSTG;
        const float* sw = sp + 32 * PPSP;

        #pragma unroll 4
        for (int c4 = 0; c4 < PPKC / 4; c4++) {
            const float4 sp4 = *reinterpret_cast<const float4*>(&sp[r * PPSP + c4 * 4]);
            unsigned long long s01, s23;
            asm("mov.b64 %0, {%1, %2};" : "=l"(s01) : "f"(sp4.x), "f"(sp4.y));
            asm("mov.b64 %0, {%1, %2};" : "=l"(s23) : "f"(sp4.z), "f"(sp4.w));
            #pragma unroll
            for (int q = 0; q < 4; q++) {
                const int m = 4 * grp + q;
                if (m > 26) continue;
                float4 w4;
                if (m < 26)
                    w4 = *reinterpret_cast<const float4*>(&sw[m * PPKC + c4 * 4]);
                else
                    w4 = sp4;          // norm: v*v
                unsigned long long w01, w23;
                asm("mov.b64 %0, {%1, %2};" : "=l"(w01) : "f"(w4.x), "f"(w4.y));
                asm("mov.b64 %0, {%1, %2};" : "=l"(w23) : "f"(w4.z), "f"(w4.w));
                asm("fma.rn.f32x2 %0, %1, %2, %0;" : "+l"(acc2[q]) : "l"(s01), "l"(w01));
                asm("fma.rn.f32x2 %0, %1, %2, %0;" : "+l"(acc2[q]) : "l"(s23), "l"(w23));
            }
        }
    }

    #pragma unroll
    for (int q = 0; q < 4; q++) {
        const int m = 4 * grp + q;
        if (m > 26) continue;
        float lo, hi;
        asm("mov.b64 {%0, %1}, %2;" : "=f"(lo), "=f"(hi) : "l"(acc2[q]));
        const float sum = lo + hi;
        if (m < 26) {
            const __half h = __float2half_rn(sum);
            g_Phi[(row0 + r) * KP + m] = h;
            g_Plo[(row0 + r) * KP + m] = __float2half_rn(sum - __half2float(h));
        } else {
            g_rnP[row0 + r] = sum;
        }
    }
    if (t < 192) {
        const int rr = t / 6, kp = 26 + t % 6;
        g_Phi[(row0 + rr) * KP + kp] = __float2half_rn(0.f);
        g_Plo[(row0 + rr) * KP + kp] = __float2half_rn(0.f);
    }
}

__device__ void np_part(int nbid, int t, float* smf, const float* __restrict__ n)
{
    float* Ms  = smf;                  // 676
    float* nsh = Ms + 676;             // 256 x 26

    for (int idx = t; idx < RK * RK; idx += 256) Ms[idx] = g_M[idx];
    const long s0 = (long)nbid * 256;
    for (int idx = t; idx < 256 * 25; idx += 256) {
        const int s = idx / 25, k = idx % 25;
        nsh[s * 26 + k] = n[(s0 + s) * 25 + k];
    }
    for (int idx = t; idx < 256; idx += 256) nsh[idx * 26 + 25] = 1.f;
    __syncthreads();

    const long s = s0 + t;
    float rn = 0.f;
    #pragma unroll 2
    for (int a = 0; a < RK; a++) {
        float u = 0.f;
        #pragma unroll
        for (int b = 0; b < RK; b++) u = fmaf(nsh[t * 26 + b], Ms[b * RK + a], u);
        const __half uh = __float2half_rn(u);
        g_Uhi[s * KP + a] = uh;
        g_Ulo[s * KP + a] = __float2half_rn(u - __half2float(uh));
        const float npv = nsh[t * 26 + a];
        const __half nh = __float2half_rn(npv);
        g_Nhi[s * KP + a] = nh;
        g_Nlo[s * KP + a] = __float2half_rn(npv - __half2float(nh));
        rn = fmaf(u, npv, rn);
    }
    #pragma unroll
    for (int a = RK; a < KP; a++) {
        const __half zz = __float2half_rn(0.f);
        g_Uhi[s * KP + a] = zz; g_Ulo[s * KP + a] = zz;
        g_Nhi[s * KP + a] = zz; g_Nlo[s * KP + a] = zz;
    }
    g_rnG[s] = rn;
}

// 3 blocks/SM (regs capped ~84, smem 3 x 70.8 KB)
__global__ __launch_bounds__(256, 3)
void fused_mid_kernel(const float* __restrict__ n,
                      const float* __restrict__ z,
                      const float* __restrict__ znext,
                      const float* __restrict__ prior,
                      float* __restrict__ out,
                      const float* __restrict__ w1W, const float* __restrict__ w1b,
                      const float* __restrict__ b1W, const float* __restrict__ b1b,
                      const float* __restrict__ w2W, const float* __restrict__ w2b,
                      const float* __restrict__ b2W, const float* __restrict__ b2b,
                      const float* __restrict__ w3W, const float* __restrict__ w3b,
                      const float* __restrict__ b3W, const float* __restrict__ b3b)
{
    extern __shared__ float smf[];
    const int bid = blockIdx.x;
    const int t = threadIdx.x;
    if (bid < NDEC) {
        decode_part(bid, t, smf, n, z, znext, out,
                    w1W, w1b, b1W, b1b, w2W, w2b, b2W, b2b, w3W, w3b, b3W, b3b);
    } else if (bid < NDEC + NPP) {
        pp_part(bid - NDEC, t, smf, prior);
    } else {
        np_part(bid - NDEC - NPP, t, smf, n);
    }
}

// ---------------- K3: HMMA fp16-split min-GEMM (both passes) -------------------
#define MT 128
#define NTILE (BATCH / MT)                 // 64
#define NP0 (NTILE * NTILE)                // 4096
#define NP1 (NTILE * (NTILE + 1) / 2)      // 2080
#define ROWH 40                            // padded row stride in halves (80 B)

__global__ __launch_bounds__(256, 2)
void minmin_kernel()
{
    __shared__ __align__(16) __half Ah[MT * ROWH];
    __shared__ __align__(16) __half Al[MT * ROWH];
    __shared__ __align__(16) __half Bh[MT * ROWH];
    __shared__ __align__(16) __half Bl[MT * ROWH];
    __shared__ float rnA[MT], rnB[MT];
    __shared__ float cbuf[2 * MT];
    __shared__ float rbuf[MT * 4];

    const int bid = blockIdx.x;
    const int pass = (bid >= NP0);
    int ib, jb;
    if (!pass) { ib = bid >> 6; jb = bid & 63; }
    else {
        const int t0 = bid - NP0;
        jb = (int)((sqrtf(8.f * (float)t0 + 1.f) - 1.f) * 0.5f);
        while ((jb + 1) * (jb + 2) / 2 <= t0) jb++;
        while (jb * (jb + 1) / 2 > t0) jb--;
        ib = t0 - jb * (jb + 1) / 2;
    }
    const long i0 = (long)ib * MT;
    const long j0 = (long)jb * MT;
    const __half* __restrict__ Ahg = pass ? g_Uhi : g_Phi;
    const __half* __restrict__ Alg = pass ? g_Ulo : g_Plo;
    const float* __restrict__ rnAs = pass ? g_rnG : g_rnP;
    unsigned* colmin                = pass ? g_minG : g_minP;

    const int t = threadIdx.x;

    for (int u = t; u < 512; u += 256) {
        const int r = u >> 2, c = u & 3;
        const long ga = (i0 + r) * KP + c * 8;
        const long gb = (j0 + r) * KP + c * 8;
        *reinterpret_cast<uint4*>(reinterpret_cast<char*>(Ah) + r * 80 + c * 16)
            = *reinterpret_cast<const uint4*>(Ahg + ga);
        *reinterpret_cast<uint4*>(reinterpret_cast<char*>(Al) + r * 80 + c * 16)
            = *reinterpret_cast<const uint4*>(Alg + ga);
        *reinterpret_cast<uint4*>(reinterpret_cast<char*>(Bh) + r * 80 + c * 16)
            = *reinterpret_cast<const uint4*>(g_Nhi + gb);
        *reinterpret_cast<uint4*>(reinterpret_cast<char*>(Bl) + r * 80 + c * 16)
            = *reinterpret_cast<const uint4*>(g_Nlo + gb);
    }
    if (t < MT) rnA[t] = rnAs[i0 + t];
    else rnB[t - MT] = g_rnG[j0 + (t - MT)];
    __syncthreads();

    const uint32_t sAh = smem_u32(Ah), sAl = smem_u32(Al);
    const uint32_t sBh = smem_u32(Bh), sBl = smem_u32(Bl);
    const int lane = t & 31, wid = t >> 5;
    const int wm = wid >> 2;               // 0..1 (64 rows)
    const int wn = wid & 3;                // 0..3 (32 cols)
    const int arow = wm * 64 + (lane & 7) + ((lane >> 3) & 1) * 8;
    const int ahalf = (lane >> 4) & 1;
    const int brow = wn * 32 + (lane & 7) + ((lane >> 4) & 1) * 8;
    const int bhalf = (lane >> 3) & 1;

    float d[4][4][4];
    #pragma unroll
    for (int mi = 0; mi < 4; mi++)
        #pragma unroll
        for (int ni = 0; ni < 4; ni++)
            #pragma unroll
            for (int q = 0; q < 4; q++) d[mi][ni][q] = 0.f;

    #pragma unroll
    for (int ks = 0; ks < 2; ks++) {
        const uint32_t ach = (uint32_t)((ks * 2 + ahalf) * 16);
        const uint32_t bch = (uint32_t)((ks * 2 + bhalf) * 16);
        uint32_t af[4][4], bfh[2][4], bfl[2][4];
        #pragma unroll
        for (int mi = 0; mi < 4; mi++)
            ldsm_x4(af[mi][0], af[mi][1], af[mi][2], af[mi][3],
                    sAh + (uint32_t)((arow + mi * 16) * 80) + ach);
        #pragma unroll
        for (int nb = 0; nb < 2; nb++)
            ldsm_x4(bfh[nb][0], bfh[nb][1], bfh[nb][2], bfh[nb][3],
                    sBh + (uint32_t)((brow + nb * 16) * 80) + bch);
        #pragma unroll
        for (int nb = 0; nb < 2; nb++)
            ldsm_x4(bfl[nb][0], bfl[nb][1], bfl[nb][2], bfl[nb][3],
                    sBl + (uint32_t)((brow + nb * 16) * 80) + bch);
        #pragma unroll
        for (int mi = 0; mi < 4; mi++)
            #pragma unroll
            for (int nb = 0; nb < 2; nb++) {
                mma16816(d[mi][nb * 2],     af[mi], bfh[nb][0], bfh[nb][1]);
                mma16816(d[mi][nb * 2 + 1], af[mi], bfh[nb][2], bfh[nb][3]);
                mma16816(d[mi][nb * 2],     af[mi], bfl[nb][0], bfl[nb][1]);
                mma16816(d[mi][nb * 2 + 1], af[mi], bfl[nb][2], bfl[nb][3]);
            }
        #pragma unroll
        for (int mi = 0; mi < 4; mi++)
            ldsm_x4(af[mi][0], af[mi][1], af[mi][2], af[mi][3],
                    sAl + (uint32_t)((arow + mi * 16) * 80) + ach);
        #pragma unroll
        for (int mi = 0; mi < 4; mi++)
            #pragma unroll
            for (int nb = 0; nb < 2; nb++) {
                mma16816(d[mi][nb * 2],     af[mi], bfh[nb][0], bfh[nb][1]);
                mma16816(d[mi][nb * 2 + 1], af[mi], bfh[nb][2], bfh[nb][3]);
            }
    }

    // ---------------- epilogue -------------------------------------------------
    const int g = lane >> 2, tig = lane & 3;
    float cmin[4][2], rmin[4][2];
    #pragma unroll
    for (int q = 0; q < 4; q++) { cmin[q][0] = 1e30f; cmin[q][1] = 1e30f;
                                  rmin[q][0] = 1e30f; rmin[q][1] = 1e30f; }

    #pragma unroll
    for (int mi = 0; mi < 4; mi++) {
        const int r0 = wm * 64 + mi * 16 + g;
        const long ig0 = i0 + r0;
        const long ig1 = ig0 + 8;
        const float rn0 = rnA[r0];
        const float rn1 = rnA[r0 + 8];
        #pragma unroll
        for (int ni = 0; ni < 4; ni++) {
            const float d0 = d[mi][ni][0], d1 = d[mi][ni][1];
            const float d2 = d[mi][ni][2], d3 = d[mi][ni][3];
            float v0 = fmaf(-2.f, d0, rn0);
            float v1 = fmaf(-2.f, d1, rn0);
            float v2 = fmaf(-2.f, d2, rn1);
            float v3 = fmaf(-2.f, d3, rn1);
            if (pass) {
                const int cc = wn * 32 + ni * 8 + 2 * tig;
                const long jg = j0 + cc;
                float w0 = fmaf(-2.f, d0, rnB[cc]);
                float w1 = fmaf(-2.f, d1, rnB[cc + 1]);
                float w2 = fmaf(-2.f, d2, rnB[cc]);
                float w3 = fmaf(-2.f, d3, rnB[cc + 1]);
                if (ig0 == jg)     { v0 = 1e30f; w0 = 1e30f; }
                if (ig0 == jg + 1) { v1 = 1e30f; w1 = 1e30f; }
                if (ig1 == jg)     { v2 = 1e30f; w2 = 1e30f; }
                if (ig1 == jg + 1) { v3 = 1e30f; w3 = 1e30f; }
                rmin[mi][0] = fminf(rmin[mi][0], fminf(w0, w1));
                rmin[mi][1] = fminf(rmin[mi][1], fminf(w2, w3));
            }
            cmin[ni][0] = fminf(cmin[ni][0], fminf(v0, v2));
            cmin[ni][1] = fminf(cmin[ni][1], fminf(v1, v3));
        }
    }

    #pragma unroll
    for (int off = 4; off <= 16; off <<= 1)
        #pragma unroll
        for (int ni = 0; ni < 4; ni++) {
            cmin[ni][0] = fminf(cmin[ni][0], __shfl_xor_sync(0xFFFFFFFFu, cmin[ni][0], off));
            cmin[ni][1] = fminf(cmin[ni][1], __shfl_xor_sync(0xFFFFFFFFu, cmin[ni][1], off));
        }
    if (pass) {
        #pragma unroll
        for (int off = 1; off <= 2; off <<= 1)
            #pragma unroll
            for (int mi = 0; mi < 4; mi++) {
                rmin[mi][0] = fminf(rmin[mi][0], __shfl_xor_sync(0xFFFFFFFFu, rmin[mi][0], off));
                rmin[mi][1] = fminf(rmin[mi][1], __shfl_xor_sync(0xFFFFFFFFu, rmin[mi][1], off));
            }
    }

    if (lane < 4) {
        #pragma unroll
        for (int ni = 0; ni < 4; ni++) {
            const int col = wn * 32 + ni * 8 + 2 * lane;
            cbuf[wm * MT + col]     = cmin[ni][0];
            cbuf[wm * MT + col + 1] = cmin[ni][1];
        }
    }
    if (pass && tig == 0) {
        #pragma unroll
        for (int mi = 0; mi < 4; mi++) {
            const int r0 = wm * 64 + mi * 16 + g;
            rbuf[r0 * 4 + wn]       = rmin[mi][0];
            rbuf[(r0 + 8) * 4 + wn] = rmin[mi][1];
        }
    }
    __syncthreads();

    if (t < MT) {
        atomicMin(&colmin[j0 + t], fkey(fminf(cbuf[t], cbuf[MT + t])));
        if (pass) {
            const float m2 = fminf(fminf(rbuf[t * 4], rbuf[t * 4 + 1]),
                                   fminf(rbuf[t * 4 + 2], rbuf[t * 4 + 3]));
            atomicMin(&colmin[i0 + t], fkey(m2));
        }
    }
}

// ---------------- K4: final scalar reductions ----------------------------------
__global__ void finalize_kernel(float* __restrict__ out)
{
    __shared__ float s1[1024], s2[1024];
    const int t = threadIdx.x;
    float rsum = 0.f, ksum = 0.f;
    for (int j = t; j < BATCH; j += 1024) {
        rsum += g_recon[j];
        float rn = g_rnG[j];
        float wp = sqrtf(fmaxf(funkey(g_minP[j]) + rn, 0.f) + 1e-8f);
        float ww = sqrtf(fmaxf(funkey(g_minG[j]) + rn, 0.f) + 1e-8f);
        ksum += logf(wp / (ww + 1e-8f) + 1e-8f);
    }
    s1[t] = rsum; s2[t] = ksum;
    __syncthreads();
    for (int off = 512; off > 0; off >>= 1) {
        if (t < off) { s1[t] += s1[t + off]; s2[t] += s2[t + off]; }
        __syncthreads();
    }
    if (t == 0) {
        out[0] = s1[0] / (float)BATCH;
        out[1] = s2[0] / (float)BATCH * (float)DTOT
               + logf((float)BATCH / (float)(BATCH - 1));
    }
}

// ---------------- launch --------------------------------------------------------
extern "C" void kernel_launch(void* const* d_in, const int* in_sizes, int n_in,
                              void* d_out, int out_size)
{
    (void)in_sizes; (void)n_in; (void)out_size;
    const float* z     = (const float*)d_in[0];
    const float* znext = (const float*)d_in[1];
    const float* n     = (const float*)d_in[2];
    const float* prior = (const float*)d_in[3];
    const float* w1W = (const float*)d_in[4];  const float* w1b = (const float*)d_in[5];
    const float* b1W = (const float*)d_in[6];  const float* b1b = (const float*)d_in[7];
    const float* w2W = (const float*)d_in[8];  const float* w2b = (const float*)d_in[9];
    const float* b2W = (const float*)d_in[10]; const float* b2b = (const float*)d_in[11];
    const float* w3W = (const float*)d_in[12]; const float* w3b = (const float*)d_in[13];
    const float* b3W = (const float*)d_in[14]; const float* b3b = (const float*)d_in[15];
    float* out = (float*)d_out;

    cudaFuncSetAttribute(fused_mid_kernel,
                         cudaFuncAttributeMaxDynamicSharedMemorySize,
                         DEC_SMEM_FLOATS * (int)sizeof(float));

    prep_kernel<<<32 + RK * RK, 256>>>(
        w1W, w1b, b1W, b1b, w2W, w2b, b2W, b2b, w3W, w3b, b3W, b3b);
    fused_mid_kernel<<<NDEC + NPP + NNP, 256, DEC_SMEM_FLOATS * sizeof(float)>>>(
        n, z, znext, prior, out,
        w1W, w1b, b1W, b1b, w2W, w2b, b2W, b2b, w3W, w3b, b3W, b3b);
    minmin_kernel<<<NP0 + NP1, 256>>>();
    finalize_kernel<<<1, 1024>>>(out);
}

// round 15
// speedup vs baseline: 16.7918x; 1.0029x over previous
#include <cuda_runtime.h>
#include <cuda_fp16.h>
#include <math.h>
#include <stdint.h>

#define BATCH 8192
#define DTOT  4611
#define RK    26               // rank of G: 25 noise dims + bias
#define KP    32               // fp16 K padded

// ---------------- static device scratch -------------------------------------
__device__ float g_Wp[RK * DTOT];      // W' (26 x 4611)
__device__ float g_M[RK * RK];         // W' W'^T
__device__ __half g_Uhi[(size_t)BATCH * KP];   // hi/lo splits, K padded to 32
__device__ __half g_Ulo[(size_t)BATCH * KP];
__device__ __half g_Nhi[(size_t)BATCH * KP];
__device__ __half g_Nlo[(size_t)BATCH * KP];
__device__ __half g_Phi[(size_t)BATCH * KP];
__device__ __half g_Plo[(size_t)BATCH * KP];
__device__ float    g_rnP[BATCH];
__device__ float    g_rnG[BATCH];
__device__ unsigned g_minP[BATCH];
__device__ unsigned g_minG[BATCH];
__device__ float    g_recon[BATCH];

__device__ __forceinline__ unsigned fkey(float f) {
    unsigned u = __float_as_uint(f);
    return (u & 0x80000000u) ? ~u : (u | 0x80000000u);
}
__device__ __forceinline__ float funkey(unsigned k) {
    unsigned u = (k & 0x80000000u) ? (k ^ 0x80000000u) : ~k;
    return __uint_as_float(u);
}

__device__ __forceinline__ uint32_t smem_u32(const void* p) {
    uint32_t a;
    asm("{ .reg .u64 t; cvta.to.shared.u64 t, %1; cvt.u32.u64 %0, t; }" : "=r"(a) : "l"(p));
    return a;
}
__device__ __forceinline__ void ldsm_x4(uint32_t& r0, uint32_t& r1, uint32_t& r2,
                                        uint32_t& r3, uint32_t addr) {
    asm volatile("ldmatrix.sync.aligned.m8n8.x4.shared.b16 {%0,%1,%2,%3}, [%4];"
                 : "=r"(r0), "=r"(r1), "=r"(r2), "=r"(r3) : "r"(addr));
}
__device__ __forceinline__ void mma16816(float* d, const uint32_t* a,
                                         uint32_t b0, uint32_t b1) {
    asm volatile("mma.sync.aligned.m16n8k16.row.col.f32.f16.f16.f32 "
                 "{%0,%1,%2,%3}, {%4,%5,%6,%7}, {%8,%9}, {%0,%1,%2,%3};"
                 : "+f"(d[0]), "+f"(d[1]), "+f"(d[2]), "+f"(d[3])
                 : "r"(a[0]), "r"(a[1]), "r"(a[2]), "r"(a[3]), "r"(b0), "r"(b1));
}

// raw-weight selector: segment for column c of W'
__device__ __forceinline__ void wp_sel(int c,
                                       const float* w1W, const float* w1b,
                                       const float* b1W, const float* b1b,
                                       const float* w2W, const float* w2b,
                                       const float* b2W, const float* b2b,
                                       const float* w3W, const float* w3b,
                                       const float* b3W, const float* b3b,
                                       const float** W, const float** bias,
                                       int* local, int* width)
{
    if      (c < 192)  { *W = w1W; *bias = w1b; *local = c;        *width = 192;  }
    else if (c < 256)  { *W = b1W; *bias = b1b; *local = c - 192;  *width = 64;   }
    else if (c < 4352) { *W = w2W; *bias = w2b; *local = c - 256;  *width = 4096; }
    else if (c < 4416) { *W = b2W; *bias = b2b; *local = c - 4352; *width = 64;   }
    else if (c < 4608) { *W = w3W; *bias = w3b; *local = c - 4416; *width = 192;  }
    else               { *W = b3W; *bias = b3b; *local = c - 4608; *width = 3;    }
}

// ---------------- K1: prep — build W' + init mins | compute M (raw) -----------
__global__ __launch_bounds__(256)
void prep_kernel(const float* __restrict__ w1W, const float* __restrict__ w1b,
                 const float* __restrict__ b1W, const float* __restrict__ b1b,
                 const float* __restrict__ w2W, const float* __restrict__ w2b,
                 const float* __restrict__ b2W, const float* __restrict__ b2b,
                 const float* __restrict__ w3W, const float* __restrict__ w3b,
                 const float* __restrict__ b3W, const float* __restrict__ b3b)
{
    if (blockIdx.x < 32) {
        const int c = blockIdx.x * 256 + threadIdx.x;
        if (c < BATCH) { g_minP[c] = 0xFFFFFFFFu; g_minG[c] = 0xFFFFFFFFu; }
        if (c >= DTOT) return;
        const float* W; const float* bias; int local, width;
        wp_sel(c, w1W, w1b, b1W, b1b, w2W, w2b, b2W, b2b, w3W, w3b, b3W, b3b,
               &W, &bias, &local, &width);
        #pragma unroll
        for (int k = 0; k < 25; k++) g_Wp[k * DTOT + c] = W[k * width + local];
        g_Wp[25 * DTOT + c] = bias[local];
    } else {
        __shared__ float sm[256];
        const int p = blockIdx.x - 32;          // 0..675
        const int a = p / RK, b = p % RK;
        float s = 0.f;
        for (int c = threadIdx.x; c < DTOT; c += 256) {
            const float* W; const float* bias; int local, width;
            wp_sel(c, w1W, w1b, b1W, b1b, w2W, w2b, b2W, b2b, w3W, w3b, b3W, b3b,
                   &W, &bias, &local, &width);
            const float va = (a < 25) ? W[a * width + local] : bias[local];
            const float vb = (b < 25) ? W[b * width + local] : bias[local];
            s += va * vb;
        }
        sm[threadIdx.x] = s;
        __syncthreads();
        for (int off = 128; off > 0; off >>= 1) {
            if (threadIdx.x < off) sm[threadIdx.x] += sm[threadIdx.x + off];
            __syncthreads();
        }
        if (threadIdx.x == 0) g_M[a * RK + b] = sm[0];
    }
}

// ---------------- K2: fused mid-stage — decode | pp | np_u ---------------------
#define NDEC 256          // decode blocks: 32 samples each
#define NPP  256          // pp blocks: 32 prior rows each
#define NNP  32           // np_u blocks: 256 samples each
#define DEC_SMEM_FLOATS 17696

#define CP16(dst, src) \
    asm volatile("cp.async.cg.shared.global [%0], [%1], 16;" \
                 :: "r"(dst), "l"(src) : "memory")
#define CP4(dst, src) \
    asm volatile("cp.async.ca.shared.global [%0], [%1], 4;" \
                 :: "r"(dst), "l"(src) : "memory")

__device__ void decode_part(int bid, int t,
                            float* smf,
                            const float* __restrict__ n,
                            const float* __restrict__ z,
                            const float* __restrict__ znext,
                            float* __restrict__ out,
                            const float* __restrict__ w1W, const float* __restrict__ w1b,
                            const float* __restrict__ b1W, const float* __restrict__ b1b,
                            const float* __restrict__ w2W, const float* __restrict__ w2b,
                            const float* __restrict__ b2W, const float* __restrict__ b2b,
                            const float* __restrict__ w3W, const float* __restrict__ w3b,
                            const float* __restrict__ b3W, const float* __restrict__ b3b)
{
    float* nn   = smf;                 // 832 (32*26)
    float* z3   = nn + 832;            // 128
    float* h1   = z3 + 128;            // 2176 (32*68)
    float* h2   = h1 + 2176;           // 2176
    float* ring = h2 + 2176;           // 12288 (3 x 4096) — stage-A staging reuses this
    float* zh   = ring + 12288;        // 96
    // stage-A staging (inside ring, freed before stage B):
    float* s1W  = ring;                // 4800
    float* s1b  = s1W + 4800;          // 192
    float* sb1W = s1b + 192;           // 1600
    float* sb1b = sb1W + 1600;         // 64

    const long b0 = (long)bid * 32;

    for (int idx = t; idx < 32 * 25; idx += 256) {
        const int s = idx / 25, k = idx % 25;
        nn[s * 26 + k] = n[(b0 + s) * 25 + k];
    }
    for (int idx = t; idx < 32 * 3; idx += 256)
        z3[(idx / 3) * 4 + (idx % 3)] = z[b0 * 3 + idx];
    for (int idx = t; idx < 25 * 192; idx += 256) s1W[idx] = w1W[idx];
    for (int idx = t; idx < 192; idx += 256) s1b[idx] = w1b[idx];
    for (int idx = t; idx < 25 * 64; idx += 256) sb1W[idx] = b1W[idx];
    for (int idx = t; idx < 64; idx += 256) sb1b[idx] = b1b[idx];
    __syncthreads();

    // stage A: h1 (32*64 outputs)
    for (int idx = t; idx < 2048; idx += 256) {
        const int s = idx >> 6, u = idx & 63;
        const float z0 = z3[s * 4], z1 = z3[s * 4 + 1], z2 = z3[s * 4 + 2];
        float acc = sb1b[u] + s1b[u * 3] * z0 + s1b[u * 3 + 1] * z1 + s1b[u * 3 + 2] * z2;
        #pragma unroll
        for (int k = 0; k < 25; k++)
            acc += nn[s * 26 + k] * (s1W[k * 192 + u * 3] * z0
                                   + s1W[k * 192 + u * 3 + 1] * z1
                                   + s1W[k * 192 + u * 3 + 2] * z2
                                   + sb1W[k * 64 + u]);
        h1[s * 68 + u] = (acc > 0.f) ? acc : expm1f(acc);
    }
    __syncthreads();       // stage-A staging dead; ring reclaimed for w2W stream

    // stage B: h2 — 3-stage cp.async ring; prescaled-h f32x2 accumulate
    const int s = t & 31, ig = t >> 5;
    const uint32_t ringa = smem_u32(ring);

    #pragma unroll
    for (int kk = 0; kk < 2; kk++) {
        const float* src = (kk < 25) ? (w2W + (long)kk * 4096) : w2b;
        #pragma unroll
        for (int q = 0; q < 4; q++) {
            const int idx = t + q * 256;
            CP16(ringa + (uint32_t)(kk * 16384 + idx * 16), src + idx * 4);
        }
        asm volatile("cp.async.commit_group;" ::: "memory");
    }

    unsigned long long acc2[8];
    #pragma unroll
    for (int m = 0; m < 8; m++) acc2[m] = 0ULL;

    for (int k = 0; k < 26; k++) {
        if (k < 25) asm volatile("cp.async.wait_group 1;" ::: "memory");
        else        asm volatile("cp.async.wait_group 0;" ::: "memory");
        __syncthreads();
        if (k + 2 < 26) {
            const float* src = (k + 2 < 25) ? (w2W + (long)(k + 2) * 4096) : w2b;
            #pragma unroll
            for (int q = 0; q < 4; q++) {
                const int idx = t + q * 256;
                CP16(ringa + (uint32_t)(((k + 2) % 3) * 16384 + idx * 16), src + idx * 4);
            }
            asm volatile("cp.async.commit_group;" ::: "memory");
        }

        const float* cur = ring + (k % 3) * 4096;
        const float coef = (k < 25) ? nn[s * 26 + k] : 1.f;
        unsigned long long coef2;
        asm("mov.b64 %0, {%1, %1};" : "=l"(coef2) : "f"(coef));

        #pragma unroll 4
        for (int j4 = 0; j4 < 16; j4++) {
            const float4 h4 = *reinterpret_cast<const float4*>(&h1[s * 68 + j4 * 4]);
            unsigned long long h01, h23, ch01, ch23;
            asm("mov.b64 %0, {%1, %2};" : "=l"(h01) : "f"(h4.x), "f"(h4.y));
            asm("mov.b64 %0, {%1, %2};" : "=l"(h23) : "f"(h4.z), "f"(h4.w));
            asm("mul.rn.f32x2 %0, %1, %2;" : "=l"(ch01) : "l"(coef2), "l"(h01));
            asm("mul.rn.f32x2 %0, %1, %2;" : "=l"(ch23) : "l"(coef2), "l"(h23));
            #pragma unroll
            for (int m = 0; m < 8; m++) {
                const float4 w4 = *reinterpret_cast<const float4*>(
                    &cur[(ig * 8 + m) * 64 + j4 * 4]);       // warp-broadcast
                unsigned long long w01, w23;
                asm("mov.b64 %0, {%1, %2};" : "=l"(w01) : "f"(w4.x), "f"(w4.y));
                asm("mov.b64 %0, {%1, %2};" : "=l"(w23) : "f"(w4.z), "f"(w4.w));
                asm("fma.rn.f32x2 %0, %1, %2, %0;" : "+l"(acc2[m]) : "l"(ch01), "l"(w01));
                asm("fma.rn.f32x2 %0, %1, %2, %0;" : "+l"(acc2[m]) : "l"(ch23), "l"(w23));
            }
        }
    }

    #pragma unroll
    for (int m = 0; m < 8; m++) {
        const int i = ig * 8 + m;
        float b2 = b2b[i];
        #pragma unroll
        for (int k = 0; k < 25; k++) b2 += nn[s * 26 + k] * b2W[k * 64 + i];
        float lo, hi;
        asm("mov.b64 {%0, %1}, %2;" : "=f"(lo), "=f"(hi) : "l"(acc2[m]));
        const float v = lo + hi + b2;
        h2[s * 68 + i] = (v > 0.f) ? v : expm1f(v);
    }
    __syncthreads();

    // stage C: z_hat (32*3 outputs)
    if (t < 96) {
        const int ss = t / 3, d = t % 3;
        float a3 = b3b[d];
        #pragma unroll
        for (int k = 0; k < 25; k++) a3 += nn[ss * 26 + k] * b3W[k * 3 + d];
        for (int k = 0; k < 26; k++) {
            const float* row = (k < 25) ? (w3W + (long)k * 192 + d * 64) : (w3b + d * 64);
            const float coef = (k < 25) ? nn[ss * 26 + k] : 1.f;
            float tk = 0.f;
            #pragma unroll 8
            for (int j = 0; j < 64; j++) tk = fmaf(row[j], h2[ss * 68 + j], tk);
            a3 = fmaf(coef, tk, a3);
        }
        out[2 + (b0 + ss) * 3 + d] = a3;
        zh[ss * 3 + d] = a3;
    }
    __syncthreads();
    if (t < 32) {
        const float d0 = zh[t * 3]     - znext[(b0 + t) * 3];
        const float d1 = zh[t * 3 + 1] - znext[(b0 + t) * 3 + 1];
        const float d2 = zh[t * 3 + 2] - znext[(b0 + t) * 3 + 2];
        g_recon[b0 + t] = d0 * d0 + d1 * d1 + d2 * d2;
    }
}

// pp: 3-stage cp.async ring, chunk width 96, single sync per chunk.
#define PPKC 96
#define PPSP 100                        // padded sp row stride (floats)
#define PPSTG (32 * PPSP + RK * PPKC)   // 5696 floats per stage
#define PPNCH ((DTOT + PPKC - 1) / PPKC)  // 49

__device__ void pp_issue_chunk(uint32_t stga, int ch, long row0, int t,
                               const float* __restrict__ prior, float* stg)
{
    const int k0 = ch * PPKC;
    for (int idx = t; idx < 32 * PPKC; idx += 256) {
        const int rr = idx / PPKC, c = idx % PPKC;
        if (k0 + c < DTOT)
            CP4(stga + (uint32_t)((rr * PPSP + c) * 4),
                prior + (row0 + rr) * (long)DTOT + k0 + c);
        else
            stg[rr * PPSP + c] = 0.f;
    }
    const uint32_t swa = stga + (uint32_t)(32 * PPSP * 4);
    float* sw = stg + 32 * PPSP;
    for (int idx = t; idx < RK * PPKC; idx += 256) {
        const int m = idx / PPKC, c = idx % PPKC;
        if (k0 + c < DTOT)
            CP4(swa + (uint32_t)((m * PPKC + c) * 4),
                g_Wp + (long)m * DTOT + k0 + c);
        else
            sw[m * PPKC + c] = 0.f;
    }
    asm volatile("cp.async.commit_group;" ::: "memory");
}

__device__ void pp_part(int pbid, int t, float* smf, const float* __restrict__ prior)
{
    const long row0 = (long)pbid * 32;
    const int r = t & 31;
    const int grp = t >> 5;            // warp-uniform, 0..7
    const uint32_t smfa = smem_u32(smf);

    pp_issue_chunk(smfa, 0, row0, t, prior, smf);
    pp_issue_chunk(smfa + (uint32_t)(PPSTG * 4), 1, row0, t, prior, smf + PPSTG);

    unsigned long long acc2[4];
    #pragma unroll
    for (int q = 0; q < 4; q++) acc2[q] = 0ULL;

    for (int ch = 0; ch < PPNCH; ch++) {
        if (ch + 1 < PPNCH) asm volatile("cp.async.wait_group 1;" ::: "memory");
        else                asm volatile("cp.async.wait_group 0;" ::: "memory");
        __syncthreads();
        if (ch + 2 < PPNCH) {
            const int st = (ch + 2) % 3;
            pp_issue_chunk(smfa + (uint32_t)(st * PPSTG * 4), ch + 2, row0, t,
                           prior, smf + st * PPSTG);
        }

        const float* sp = smf + (ch % 3) * PPSTG;
        const float* sw = sp + 32 * PPSP;

        #pragma unroll 4
        for (int c4 = 0; c4 < PPKC / 4; c4++) {
            const float4 sp4 = *reinterpret_cast<const float4*>(&sp[r * PPSP + c4 * 4]);
            unsigned long long s01, s23;
            asm("mov.b64 %0, {%1, %2};" : "=l"(s01) : "f"(sp4.x), "f"(sp4.y));
            asm("mov.b64 %0, {%1, %2};" : "=l"(s23) : "f"(sp4.z), "f"(sp4.w));
            #pragma unroll
            for (int q = 0; q < 4; q++) {
                const int m = 4 * grp + q;
                if (m > 26) continue;
                float4 w4;
                if (m < 26)
                    w4 = *reinterpret_cast<const float4*>(&sw[m * PPKC + c4 * 4]);
                else
                    w4 = sp4;          // norm: v*v
                unsigned long long w01, w23;
                asm("mov.b64 %0, {%1, %2};" : "=l"(w01) : "f"(w4.x), "f"(w4.y));
                asm("mov.b64 %0, {%1, %2};" : "=l"(w23) : "f"(w4.z), "f"(w4.w));
                asm("fma.rn.f32x2 %0, %1, %2, %0;" : "+l"(acc2[q]) : "l"(s01), "l"(w01));
                asm("fma.rn.f32x2 %0, %1, %2, %0;" : "+l"(acc2[q]) : "l"(s23), "l"(w23));
            }
        }
    }

    #pragma unroll
    for (int q = 0; q < 4; q++) {
        const int m = 4 * grp + q;
        if (m > 26) continue;
        float lo, hi;
        asm("mov.b64 {%0, %1}, %2;" : "=f"(lo), "=f"(hi) : "l"(acc2[q]));
        const float sum = lo + hi;
        if (m < 26) {
            const __half h = __float2half_rn(sum);
            g_Phi[(row0 + r) * KP + m] = h;
            g_Plo[(row0 + r) * KP + m] = __float2half_rn(sum - __half2float(h));
        } else {
            g_rnP[row0 + r] = sum;
        }
    }
    if (t < 192) {
        const int rr = t / 6, kp = 26 + t % 6;
        g_Phi[(row0 + rr) * KP + kp] = __float2half_rn(0.f);
        g_Plo[(row0 + rr) * KP + kp] = __float2half_rn(0.f);
    }
}

// np: compute U, N splits with smem-staged coalesced stores
__device__ void np_part(int nbid, int t, float* smf, const float* __restrict__ n)
{
    float* Ms  = smf;                  // 676
    float* nsh = Ms + 676;             // 256 x 26 = 6656
    __half* hbuf = (__half*)(nsh + 6656);   // 256 x 32 halves = 16 KB

    for (int idx = t; idx < RK * RK; idx += 256) Ms[idx] = g_M[idx];
    const long s0 = (long)nbid * 256;
    for (int idx = t; idx < 256 * 25; idx += 256) {
        const int s = idx / 25, k = idx % 25;
        nsh[s * 26 + k] = n[(s0 + s) * 25 + k];
    }
    for (int idx = t; idx < 256; idx += 256) nsh[idx * 26 + 25] = 1.f;
    __syncthreads();

    // compute u[] and rn; stage each half-matrix through smem, store coalesced
    float u[RK];
    float rn = 0.f;
    #pragma unroll
    for (int a = 0; a < RK; a++) {
        float uu = 0.f;
        #pragma unroll
        for (int b = 0; b < RK; b++) uu = fmaf(nsh[t * 26 + b], Ms[b * RK + a], uu);
        u[a] = uu;
        rn = fmaf(uu, nsh[t * 26 + a], rn);
    }
    g_rnG[s0 + t] = rn;

    const __half hz = __float2half_rn(0.f);
    uint4* gdst[4] = { reinterpret_cast<uint4*>(g_Uhi + s0 * KP),
                       reinterpret_cast<uint4*>(g_Ulo + s0 * KP),
                       reinterpret_cast<uint4*>(g_Nhi + s0 * KP),
                       reinterpret_cast<uint4*>(g_Nlo + s0 * KP) };
    #pragma unroll
    for (int arr = 0; arr < 4; arr++) {
        __syncthreads();
        #pragma unroll
        for (int a = 0; a < RK; a++) {
            const float v = (arr < 2) ? u[a] : nsh[t * 26 + a];
            const __half h = __float2half_rn(v);
            hbuf[t * KP + a] = (arr & 1)
                ? __float2half_rn(v - __half2float(h)) : h;
        }
        #pragma unroll
        for (int a = RK; a < KP; a++) hbuf[t * KP + a] = hz;
        __syncthreads();
        // coalesced copy: 256 rows x 64 B = 1024 uint4
        const uint4* src = reinterpret_cast<const uint4*>(hbuf);
        for (int q = t; q < 1024; q += 256) gdst[arr][q] = src[q];
    }
}

// 3 blocks/SM (regs capped ~84, smem 3 x 70.8 KB)
__global__ __launch_bounds__(256, 3)
void fused_mid_kernel(const float* __restrict__ n,
                      const float* __restrict__ z,
                      const float* __restrict__ znext,
                      const float* __restrict__ prior,
                      float* __restrict__ out,
                      const float* __restrict__ w1W, const float* __restrict__ w1b,
                      const float* __restrict__ b1W, const float* __restrict__ b1b,
                      const float* __restrict__ w2W, const float* __restrict__ w2b,
                      const float* __restrict__ b2W, const float* __restrict__ b2b,
                      const float* __restrict__ w3W, const float* __restrict__ w3b,
                      const float* __restrict__ b3W, const float* __restrict__ b3b)
{
    extern __shared__ float smf[];
    const int bid = blockIdx.x;
    const int t = threadIdx.x;
    if (bid < NDEC) {
        decode_part(bid, t, smf, n, z, znext, out,
                    w1W, w1b, b1W, b1b, w2W, w2b, b2W, b2b, w3W, w3b, b3W, b3b);
    } else if (bid < NDEC + NPP) {
        pp_part(bid - NDEC, t, smf, prior);
    } else {
        np_part(bid - NDEC - NPP, t, smf, n);
    }
}

// ---------------- K3: HMMA fp16-split min-GEMM, 2 j-subtiles per block --------
#define MT 128
#define NTILE (BATCH / MT)                 // 64
#define NJG  (NTILE / 2)                   // 32 j-groups of 2 tiles
#define NB0  (NTILE * NJG)                 // 2048 pass-0 blocks
#define NB1  (NJG * (NJG + 1))             // 1056 pass-1 blocks (sum 2jg+2)
#define ROWH 40                            // padded row stride in halves (80 B)
#define MINMIN_SMEM 66048

__global__ __launch_bounds__(256, 2)
void minmin_kernel()
{
    extern __shared__ char mshm[];
    __half* Ah  = (__half*)mshm;           // 5120
    __half* Al  = Ah + MT * ROWH;          // 5120
    __half* Bh0 = Al + MT * ROWH;          // 2 x 5120
    __half* Bl0 = Bh0 + 2 * MT * ROWH;     // 2 x 5120
    float* rnA  = (float*)(Bl0 + 2 * MT * ROWH);   // 128
    float* rnB  = rnA + MT;                // 256
    float* cbuf = rnB + 2 * MT;            // 256
    float* rbuf = cbuf + 2 * MT;           // 512

    const int bid = blockIdx.x;
    const int pass = (bid >= NB0);
    int ib, jg;
    if (!pass) { ib = bid >> 5; jg = bid & 31; }
    else {
        const int t0 = bid - NB0;
        jg = (int)((sqrtf(4.f * (float)t0 + 1.f) - 1.f) * 0.5f);
        while ((jg + 1) * (jg + 2) <= t0) jg++;
        while (jg * (jg + 1) > t0) jg--;
        ib = t0 - jg * (jg + 1);           // 0 .. 2jg+1
    }
    const long i0 = (long)ib * MT;
    const long j0 = (long)jg * 2 * MT;
    const __half* __restrict__ Ahg = pass ? g_Uhi : g_Phi;
    const __half* __restrict__ Alg = pass ? g_Ulo : g_Plo;
    const float* __restrict__ rnAs = pass ? g_rnG : g_rnP;
    unsigned* colmin                = pass ? g_minG : g_minP;

    const int t = threadIdx.x;

    // A tile (128 rows) + 2 B tiles (256 rows)
    for (int u = t; u < 512; u += 256) {
        const int r = u >> 2, c = u & 3;
        const long ga = (i0 + r) * KP + c * 8;
        *reinterpret_cast<uint4*>(reinterpret_cast<char*>(Ah) + r * 80 + c * 16)
            = *reinterpret_cast<const uint4*>(Ahg + ga);
        *reinterpret_cast<uint4*>(reinterpret_cast<char*>(Al) + r * 80 + c * 16)
            = *reinterpret_cast<const uint4*>(Alg + ga);
    }
    for (int u = t; u < 1024; u += 256) {
        const int r = u >> 2, c = u & 3;   // r = 0..255
        const long gb = (j0 + r) * KP + c * 8;
        const int sbt = r >> 7, rr = r & 127;
        *reinterpret_cast<uint4*>(reinterpret_cast<char*>(Bh0 + sbt * MT * ROWH)
                                  + rr * 80 + c * 16)
            = *reinterpret_cast<const uint4*>(g_Nhi + gb);
        *reinterpret_cast<uint4*>(reinterpret_cast<char*>(Bl0 + sbt * MT * ROWH)
                                  + rr * 80 + c * 16)
            = *reinterpret_cast<const uint4*>(g_Nlo + gb);
    }
    if (t < MT) rnA[t] = rnAs[i0 + t];
    rnB[t] = g_rnG[j0 + t];
    __syncthreads();

    const uint32_t sAh = smem_u32(Ah), sAl = smem_u32(Al);
    const int lane = t & 31, wid = t >> 5;
    const int wm = wid >> 2;               // 0..1 (64 rows)
    const int wn = wid & 3;                // 0..3 (32 cols)
    const int arow = wm * 64 + (lane & 7) + ((lane >> 3) & 1) * 8;
    const int ahalf = (lane >> 4) & 1;
    const int brow = wn * 32 + (lane & 7) + ((lane >> 4) & 1) * 8;
    const int bhalf = (lane >> 3) & 1;
    const int g = lane >> 2, tig = lane & 3;

    #pragma unroll
    for (int sub = 0; sub < 2; sub++) {
        const uint32_t sBh = smem_u32(Bh0 + sub * MT * ROWH);
        const uint32_t sBl = smem_u32(Bl0 + sub * MT * ROWH);
        const long j0s = j0 + sub * MT;
        const bool valid = !pass || (ib <= 2 * jg + sub);

        float d[4][4][4];
        #pragma unroll
        for (int mi = 0; mi < 4; mi++)
            #pragma unroll
            for (int ni = 0; ni < 4; ni++)
                #pragma unroll
                for (int q = 0; q < 4; q++) d[mi][ni][q] = 0.f;

        #pragma unroll
        for (int ks = 0; ks < 2; ks++) {
            const uint32_t ach = (uint32_t)((ks * 2 + ahalf) * 16);
            const uint32_t bch = (uint32_t)((ks * 2 + bhalf) * 16);
            uint32_t af[4][4], bfh[2][4], bfl[2][4];
            #pragma unroll
            for (int mi = 0; mi < 4; mi++)
                ldsm_x4(af[mi][0], af[mi][1], af[mi][2], af[mi][3],
                        sAh + (uint32_t)((arow + mi * 16) * 80) + ach);
            #pragma unroll
            for (int nb = 0; nb < 2; nb++)
                ldsm_x4(bfh[nb][0], bfh[nb][1], bfh[nb][2], bfh[nb][3],
                        sBh + (uint32_t)((brow + nb * 16) * 80) + bch);
            #pragma unroll
            for (int nb = 0; nb < 2; nb++)
                ldsm_x4(bfl[nb][0], bfl[nb][1], bfl[nb][2], bfl[nb][3],
                        sBl + (uint32_t)((brow + nb * 16) * 80) + bch);
            #pragma unroll
            for (int mi = 0; mi < 4; mi++)
                #pragma unroll
                for (int nb = 0; nb < 2; nb++) {
                    mma16816(d[mi][nb * 2],     af[mi], bfh[nb][0], bfh[nb][1]);
                    mma16816(d[mi][nb * 2 + 1], af[mi], bfh[nb][2], bfh[nb][3]);
                    mma16816(d[mi][nb * 2],     af[mi], bfl[nb][0], bfl[nb][1]);
                    mma16816(d[mi][nb * 2 + 1], af[mi], bfl[nb][2], bfl[nb][3]);
                }
            #pragma unroll
            for (int mi = 0; mi < 4; mi++)
                ldsm_x4(af[mi][0], af[mi][1], af[mi][2], af[mi][3],
                        sAl + (uint32_t)((arow + mi * 16) * 80) + ach);
            #pragma unroll
            for (int mi = 0; mi < 4; mi++)
                #pragma unroll
                for (int nb = 0; nb < 2; nb++) {
                    mma16816(d[mi][nb * 2],     af[mi], bfh[nb][0], bfh[nb][1]);
                    mma16816(d[mi][nb * 2 + 1], af[mi], bfh[nb][2], bfh[nb][3]);
                }
        }

        // -------- epilogue for this subtile --------
        float cmin[4][2], rmin[4][2];
        #pragma unroll
        for (int q = 0; q < 4; q++) { cmin[q][0] = 1e30f; cmin[q][1] = 1e30f;
                                      rmin[q][0] = 1e30f; rmin[q][1] = 1e30f; }

        #pragma unroll
        for (int mi = 0; mi < 4; mi++) {
            const int r0 = wm * 64 + mi * 16 + g;
            const long ig0 = i0 + r0;
            const long ig1 = ig0 + 8;
            const float rn0 = rnA[r0];
            const float rn1 = rnA[r0 + 8];
            #pragma unroll
            for (int ni = 0; ni < 4; ni++) {
                const float d0 = d[mi][ni][0], d1 = d[mi][ni][1];
                const float d2 = d[mi][ni][2], d3 = d[mi][ni][3];
                float v0 = fmaf(-2.f, d0, rn0);
                float v1 = fmaf(-2.f, d1, rn0);
                float v2 = fmaf(-2.f, d2, rn1);
                float v3 = fmaf(-2.f, d3, rn1);
                if (pass) {
                    const int cc = wn * 32 + ni * 8 + 2 * tig;
                    const long jgl = j0s + cc;
                    float w0 = fmaf(-2.f, d0, rnB[sub * MT + cc]);
                    float w1 = fmaf(-2.f, d1, rnB[sub * MT + cc + 1]);
                    float w2 = fmaf(-2.f, d2, rnB[sub * MT + cc]);
                    float w3 = fmaf(-2.f, d3, rnB[sub * MT + cc + 1]);
                    if (ig0 == jgl)     { v0 = 1e30f; w0 = 1e30f; }
                    if (ig0 == jgl + 1) { v1 = 1e30f; w1 = 1e30f; }
                    if (ig1 == jgl)     { v2 = 1e30f; w2 = 1e30f; }
                    if (ig1 == jgl + 1) { v3 = 1e30f; w3 = 1e30f; }
                    rmin[mi][0] = fminf(rmin[mi][0], fminf(w0, w1));
                    rmin[mi][1] = fminf(rmin[mi][1], fminf(w2, w3));
                }
                cmin[ni][0] = fminf(cmin[ni][0], fminf(v0, v2));
                cmin[ni][1] = fminf(cmin[ni][1], fminf(v1, v3));
            }
        }

        #pragma unroll
        for (int off = 4; off <= 16; off <<= 1)
            #pragma unroll
            for (int ni = 0; ni < 4; ni++) {
                cmin[ni][0] = fminf(cmin[ni][0], __shfl_xor_sync(0xFFFFFFFFu, cmin[ni][0], off));
                cmin[ni][1] = fminf(cmin[ni][1], __shfl_xor_sync(0xFFFFFFFFu, cmin[ni][1], off));
            }
        if (pass) {
            #pragma unroll
            for (int off = 1; off <= 2; off <<= 1)
                #pragma unroll
                for (int mi = 0; mi < 4; mi++) {
                    rmin[mi][0] = fminf(rmin[mi][0], __shfl_xor_sync(0xFFFFFFFFu, rmin[mi][0], off));
                    rmin[mi][1] = fminf(rmin[mi][1], __shfl_xor_sync(0xFFFFFFFFu, rmin[mi][1], off));
                }
        }

        if (lane < 4) {
            #pragma unroll
            for (int ni = 0; ni < 4; ni++) {
                const int col = wn * 32 + ni * 8 + 2 * lane;
                cbuf[wm * MT + col]     = cmin[ni][0];
                cbuf[wm * MT + col + 1] = cmin[ni][1];
            }
        }
        if (pass && tig == 0) {
            #pragma unroll
            for (int mi = 0; mi < 4; mi++) {
                const int r0 = wm * 64 + mi * 16 + g;
                rbuf[r0 * 4 + wn]       = rmin[mi][0];
                rbuf[(r0 + 8) * 4 + wn] = rmin[mi][1];
            }
        }
        __syncthreads();

        if (valid) {
            if (t < MT) {
                atomicMin(&colmin[j0s + t], fkey(fminf(cbuf[t], cbuf[MT + t])));
                if (pass) {
                    const float m2 = fminf(fminf(rbuf[t * 4], rbuf[t * 4 + 1]),
                                           fminf(rbuf[t * 4 + 2], rbuf[t * 4 + 3]));
                    atomicMin(&colmin[i0 + t], fkey(m2));
                }
            }
        }
        __syncthreads();     // cbuf/rbuf reuse by next subtile
    }
}

// ---------------- K4: final scalar reductions ----------------------------------
__global__ void finalize_kernel(float* __restrict__ out)
{
    __shared__ float s1[1024], s2[1024];
    const int t = threadIdx.x;
    float rsum = 0.f, ksum = 0.f;
    for (int j = t * 2; j < BATCH; j += 2048) {
        const float2 rc = *reinterpret_cast<const float2*>(&g_recon[j]);
        const float2 rn = *reinterpret_cast<const float2*>(&g_rnG[j]);
        const uint2  mp = *reinterpret_cast<const uint2*>(&g_minP[j]);
        const uint2  mg = *reinterpret_cast<const uint2*>(&g_minG[j]);
        rsum += rc.x + rc.y;
        float wp0 = sqrtf(fmaxf(funkey(mp.x) + rn.x, 0.f) + 1e-8f);
        float ww0 = sqrtf(fmaxf(funkey(mg.x) + rn.x, 0.f) + 1e-8f);
        float wp1 = sqrtf(fmaxf(funkey(mp.y) + rn.y, 0.f) + 1e-8f);
        float ww1 = sqrtf(fmaxf(funkey(mg.y) + rn.y, 0.f) + 1e-8f);
        ksum += logf(wp0 / (ww0 + 1e-8f) + 1e-8f);
        ksum += logf(wp1 / (ww1 + 1e-8f) + 1e-8f);
    }
    s1[t] = rsum; s2[t] = ksum;
    __syncthreads();
    for (int off = 512; off > 0; off >>= 1) {
        if (t < off) { s1[t] += s1[t + off]; s2[t] += s2[t + off]; }
        __syncthreads();
    }
    if (t == 0) {
        out[0] = s1[0] / (float)BATCH;
        out[1] = s2[0] / (float)BATCH * (float)DTOT
               + logf((float)BATCH / (float)(BATCH - 1));
    }
}

// ---------------- launch --------------------------------------------------------
extern "C" void kernel_launch(void* const* d_in, const int* in_sizes, int n_in,
                              void* d_out, int out_size)
{
    (void)in_sizes; (void)n_in; (void)out_size;
    const float* z     = (const float*)d_in[0];
    const float* znext = (const float*)d_in[1];
    const float* n     = (const float*)d_in[2];
    const float* prior = (const float*)d_in[3];
    const float* w1W = (const float*)d_in[4];  const float* w1b = (const float*)d_in[5];
    const float* b1W = (const float*)d_in[6];  const float* b1b = (const float*)d_in[7];
    const float* w2W = (const float*)d_in[8];  const float* w2b = (const float*)d_in[9];
    const float* b2W = (const float*)d_in[10]; const float* b2b = (const float*)d_in[11];
    const float* w3W = (const float*)d_in[12]; const float* w3b = (const float*)d_in[13];
    const float* b3W = (const float*)d_in[14]; const float* b3b = (const float*)d_in[15];
    float* out = (float*)d_out;

    cudaFuncSetAttribute(fused_mid_kernel,
                         cudaFuncAttributeMaxDynamicSharedMemorySize,
                         DEC_SMEM_FLOATS * (int)sizeof(float));
    cudaFuncSetAttribute(minmin_kernel,
                         cudaFuncAttributeMaxDynamicSharedMemorySize, MINMIN_SMEM);

    prep_kernel<<<32 + RK * RK, 256>>>(
        w1W, w1b, b1W, b1b, w2W, w2b, b2W, b2b, w3W, w3b, b3W, b3b);
    fused_mid_kernel<<<NDEC + NPP + NNP, 256, DEC_SMEM_FLOATS * sizeof(float)>>>(
        n, z, znext, prior, out,
        w1W, w1b, b1W, b1b, w2W, w2b, b2W, b2b, w3W, w3b, b3W, b3b);
    minmin_kernel<<<NB0 + NB1, 256, MINMIN_SMEM>>>();
    finalize_kernel<<<1, 1024>>>(out);
}

// round 16
// speedup vs baseline: 17.1200x; 1.0195x over previous
#include <cuda_runtime.h>
#include <cuda_fp16.h>
#include <math.h>
#include <stdint.h>

#define BATCH 8192
#define DTOT  4611
#define RK    26               // rank of G: 25 noise dims + bias
#define KP    32               // fp16 K padded

// ---------------- static device scratch -------------------------------------
__device__ float g_Wp[RK * DTOT];      // W' (26 x 4611)
__device__ float g_M[RK * RK];         // W' W'^T
__device__ __half g_Uhi[(size_t)BATCH * KP];   // hi/lo splits, K padded to 32
__device__ __half g_Ulo[(size_t)BATCH * KP];
__device__ __half g_Nhi[(size_t)BATCH * KP];
__device__ __half g_Nlo[(size_t)BATCH * KP];
__device__ __half g_Phi[(size_t)BATCH * KP];
__device__ __half g_Plo[(size_t)BATCH * KP];
__device__ float    g_rnP[BATCH];
__device__ float    g_rnG[BATCH];
__device__ unsigned g_minP[BATCH];
__device__ unsigned g_minG[BATCH];
__device__ float    g_recon[BATCH];
__device__ unsigned g_done;

__device__ __forceinline__ unsigned fkey(float f) {
    unsigned u = __float_as_uint(f);
    return (u & 0x80000000u) ? ~u : (u | 0x80000000u);
}
__device__ __forceinline__ float funkey(unsigned k) {
    unsigned u = (k & 0x80000000u) ? (k ^ 0x80000000u) : ~k;
    return __uint_as_float(u);
}

__device__ __forceinline__ uint32_t smem_u32(const void* p) {
    uint32_t a;
    asm("{ .reg .u64 t; cvta.to.shared.u64 t, %1; cvt.u32.u64 %0, t; }" : "=r"(a) : "l"(p));
    return a;
}
__device__ __forceinline__ void ldsm_x4(uint32_t& r0, uint32_t& r1, uint32_t& r2,
                                        uint32_t& r3, uint32_t addr) {
    asm volatile("ldmatrix.sync.aligned.m8n8.x4.shared.b16 {%0,%1,%2,%3}, [%4];"
                 : "=r"(r0), "=r"(r1), "=r"(r2), "=r"(r3) : "r"(addr));
}
__device__ __forceinline__ void mma16816(float* d, const uint32_t* a,
                                         uint32_t b0, uint32_t b1) {
    asm volatile("mma.sync.aligned.m16n8k16.row.col.f32.f16.f16.f32 "
                 "{%0,%1,%2,%3}, {%4,%5,%6,%7}, {%8,%9}, {%0,%1,%2,%3};"
                 : "+f"(d[0]), "+f"(d[1]), "+f"(d[2]), "+f"(d[3])
                 : "r"(a[0]), "r"(a[1]), "r"(a[2]), "r"(a[3]), "r"(b0), "r"(b1));
}

// raw-weight selector: segment for column c of W'
__device__ __forceinline__ void wp_sel(int c,
                                       const float* w1W, const float* w1b,
                                       const float* b1W, const float* b1b,
                                       const float* w2W, const float* w2b,
                                       const float* b2W, const float* b2b,
                                       const float* w3W, const float* w3b,
                                       const float* b3W, const float* b3b,
                                       const float** W, const float** bias,
                                       int* local, int* width)
{
    if      (c < 192)  { *W = w1W; *bias = w1b; *local = c;        *width = 192;  }
    else if (c < 256)  { *W = b1W; *bias = b1b; *local = c - 192;  *width = 64;   }
    else if (c < 4352) { *W = w2W; *bias = w2b; *local = c - 256;  *width = 4096; }
    else if (c < 4416) { *W = b2W; *bias = b2b; *local = c - 4352; *width = 64;   }
    else if (c < 4608) { *W = w3W; *bias = w3b; *local = c - 4416; *width = 192;  }
    else               { *W = b3W; *bias = b3b; *local = c - 4608; *width = 3;    }
}

// ---------------- K1: prep — build W' + init mins + g_done | compute M --------
__global__ __launch_bounds__(256)
void prep_kernel(const float* __restrict__ w1W, const float* __restrict__ w1b,
                 const float* __restrict__ b1W, const float* __restrict__ b1b,
                 const float* __restrict__ w2W, const float* __restrict__ w2b,
                 const float* __restrict__ b2W, const float* __restrict__ b2b,
                 const float* __restrict__ w3W, const float* __restrict__ w3b,
                 const float* __restrict__ b3W, const float* __restrict__ b3b)
{
    if (blockIdx.x == 0 && threadIdx.x == 0) g_done = 0u;
    if (blockIdx.x < 32) {
        const int c = blockIdx.x * 256 + threadIdx.x;
        if (c < BATCH) { g_minP[c] = 0xFFFFFFFFu; g_minG[c] = 0xFFFFFFFFu; }
        if (c >= DTOT) return;
        const float* W; const float* bias; int local, width;
        wp_sel(c, w1W, w1b, b1W, b1b, w2W, w2b, b2W, b2b, w3W, w3b, b3W, b3b,
               &W, &bias, &local, &width);
        #pragma unroll
        for (int k = 0; k < 25; k++) g_Wp[k * DTOT + c] = W[k * width + local];
        g_Wp[25 * DTOT + c] = bias[local];
    } else {
        __shared__ float sm[256];
        const int p = blockIdx.x - 32;          // 0..675
        const int a = p / RK, b = p % RK;
        float s = 0.f;
        for (int c = threadIdx.x; c < DTOT; c += 256) {
            const float* W; const float* bias; int local, width;
            wp_sel(c, w1W, w1b, b1W, b1b, w2W, w2b, b2W, b2b, w3W, w3b, b3W, b3b,
                   &W, &bias, &local, &width);
            const float va = (a < 25) ? W[a * width + local] : bias[local];
            const float vb = (b < 25) ? W[b * width + local] : bias[local];
            s += va * vb;
        }
        sm[threadIdx.x] = s;
        __syncthreads();
        for (int off = 128; off > 0; off >>= 1) {
            if (threadIdx.x < off) sm[threadIdx.x] += sm[threadIdx.x + off];
            __syncthreads();
        }
        if (threadIdx.x == 0) g_M[a * RK + b] = sm[0];
    }
}

// ---------------- K2: fused pre — pp | np_u -----------------------------------
#define NPP  256          // pp blocks: 32 prior rows each
#define NNP  32           // np_u blocks: 256 samples each

#define CP16(dst, src) \
    asm volatile("cp.async.cg.shared.global [%0], [%1], 16;" \
                 :: "r"(dst), "l"(src) : "memory")
#define CP4(dst, src) \
    asm volatile("cp.async.ca.shared.global [%0], [%1], 4;" \
                 :: "r"(dst), "l"(src) : "memory")

// pp: 3-stage cp.async ring, chunk width 96, single sync per chunk.
#define PPKC 96
#define PPSP 100                        // padded sp row stride (floats)
#define PPSTG (32 * PPSP + RK * PPKC)   // 5696 floats per stage
#define PPNCH ((DTOT + PPKC - 1) / PPKC)  // 49
#define PRE_SMEM_BYTES (PPSTG * 3 * 4)    // 68352

__device__ void pp_issue_chunk(uint32_t stga, int ch, long row0, int t,
                               const float* __restrict__ prior, float* stg)
{
    const int k0 = ch * PPKC;
    for (int idx = t; idx < 32 * PPKC; idx += 256) {
        const int rr = idx / PPKC, c = idx % PPKC;
        if (k0 + c < DTOT)
            CP4(stga + (uint32_t)((rr * PPSP + c) * 4),
                prior + (row0 + rr) * (long)DTOT + k0 + c);
        else
            stg[rr * PPSP + c] = 0.f;
    }
    const uint32_t swa = stga + (uint32_t)(32 * PPSP * 4);
    float* sw = stg + 32 * PPSP;
    for (int idx = t; idx < RK * PPKC; idx += 256) {
        const int m = idx / PPKC, c = idx % PPKC;
        if (k0 + c < DTOT)
            CP4(swa + (uint32_t)((m * PPKC + c) * 4),
                g_Wp + (long)m * DTOT + k0 + c);
        else
            sw[m * PPKC + c] = 0.f;
    }
    asm volatile("cp.async.commit_group;" ::: "memory");
}

__device__ void pp_part(int pbid, int t, float* smf, const float* __restrict__ prior)
{
    const long row0 = (long)pbid * 32;
    const int r = t & 31;
    const int grp = t >> 5;            // warp-uniform, 0..7
    const uint32_t smfa = smem_u32(smf);

    pp_issue_chunk(smfa, 0, row0, t, prior, smf);
    pp_issue_chunk(smfa + (uint32_t)(PPSTG * 4), 1, row0, t, prior, smf + PPSTG);

    unsigned long long acc2[4];
    #pragma unroll
    for (int q = 0; q < 4; q++) acc2[q] = 0ULL;

    for (int ch = 0; ch < PPNCH; ch++) {
        if (ch + 1 < PPNCH) asm volatile("cp.async.wait_group 1;" ::: "memory");
        else                asm volatile("cp.async.wait_group 0;" ::: "memory");
        __syncthreads();
        if (ch + 2 < PPNCH) {
            const int st = (ch + 2) % 3;
            pp_issue_chunk(smfa + (uint32_t)(st * PPSTG * 4), ch + 2, row0, t,
                           prior, smf + st * PPSTG);
        }

        const float* sp = smf + (ch % 3) * PPSTG;
        const float* sw = sp + 32 * PPSP;

        #pragma unroll 4
        for (int c4 = 0; c4 < PPKC / 4; c4++) {
            const float4 sp4 = *reinterpret_cast<const float4*>(&sp[r * PPSP + c4 * 4]);
            unsigned long long s01, s23;
            asm("mov.b64 %0, {%1, %2};" : "=l"(s01) : "f"(sp4.x), "f"(sp4.y));
            asm("mov.b64 %0, {%1, %2};" : "=l"(s23) : "f"(sp4.z), "f"(sp4.w));
            #pragma unroll
            for (int q = 0; q < 4; q++) {
                const int m = 4 * grp + q;
                if (m > 26) continue;
                float4 w4;
                if (m < 26)
                    w4 = *reinterpret_cast<const float4*>(&sw[m * PPKC + c4 * 4]);
                else
                    w4 = sp4;          // norm: v*v
                unsigned long long w01, w23;
                asm("mov.b64 %0, {%1, %2};" : "=l"(w01) : "f"(w4.x), "f"(w4.y));
                asm("mov.b64 %0, {%1, %2};" : "=l"(w23) : "f"(w4.z), "f"(w4.w));
                asm("fma.rn.f32x2 %0, %1, %2, %0;" : "+l"(acc2[q]) : "l"(s01), "l"(w01));
                asm("fma.rn.f32x2 %0, %1, %2, %0;" : "+l"(acc2[q]) : "l"(s23), "l"(w23));
            }
        }
    }

    #pragma unroll
    for (int q = 0; q < 4; q++) {
        const int m = 4 * grp + q;
        if (m > 26) continue;
        float lo, hi;
        asm("mov.b64 {%0, %1}, %2;" : "=f"(lo), "=f"(hi) : "l"(acc2[q]));
        const float sum = lo + hi;
        if (m < 26) {
            const __half h = __float2half_rn(sum);
            g_Phi[(row0 + r) * KP + m] = h;
            g_Plo[(row0 + r) * KP + m] = __float2half_rn(sum - __half2float(h));
        } else {
            g_rnP[row0 + r] = sum;
        }
    }
    if (t < 192) {
        const int rr = t / 6, kp = 26 + t % 6;
        g_Phi[(row0 + rr) * KP + kp] = __float2half_rn(0.f);
        g_Plo[(row0 + rr) * KP + kp] = __float2half_rn(0.f);
    }
}

// np: compute U, N splits with smem-staged coalesced stores
__device__ void np_part(int nbid, int t, float* smf, const float* __restrict__ n)
{
    float* Ms  = smf;                  // 676
    float* nsh = Ms + 676;             // 256 x 26 = 6656
    __half* hbuf = (__half*)(nsh + 6656);   // 256 x 32 halves = 16 KB

    for (int idx = t; idx < RK * RK; idx += 256) Ms[idx] = g_M[idx];
    const long s0 = (long)nbid * 256;
    for (int idx = t; idx < 256 * 25; idx += 256) {
        const int s = idx / 25, k = idx % 25;
        nsh[s * 26 + k] = n[(s0 + s) * 25 + k];
    }
    for (int idx = t; idx < 256; idx += 256) nsh[idx * 26 + 25] = 1.f;
    __syncthreads();

    float u[RK];
    float rn = 0.f;
    #pragma unroll
    for (int a = 0; a < RK; a++) {
        float uu = 0.f;
        #pragma unroll
        for (int b = 0; b < RK; b++) uu = fmaf(nsh[t * 26 + b], Ms[b * RK + a], uu);
        u[a] = uu;
        rn = fmaf(uu, nsh[t * 26 + a], rn);
    }
    g_rnG[s0 + t] = rn;

    const __half hz = __float2half_rn(0.f);
    uint4* gdst[4] = { reinterpret_cast<uint4*>(g_Uhi + s0 * KP),
                       reinterpret_cast<uint4*>(g_Ulo + s0 * KP),
                       reinterpret_cast<uint4*>(g_Nhi + s0 * KP),
                       reinterpret_cast<uint4*>(g_Nlo + s0 * KP) };
    #pragma unroll
    for (int arr = 0; arr < 4; arr++) {
        __syncthreads();
        #pragma unroll
        for (int a = 0; a < RK; a++) {
            const float v = (arr < 2) ? u[a] : nsh[t * 26 + a];
            const __half h = __float2half_rn(v);
            hbuf[t * KP + a] = (arr & 1)
                ? __float2half_rn(v - __half2float(h)) : h;
        }
        #pragma unroll
        for (int a = RK; a < KP; a++) hbuf[t * KP + a] = hz;
        __syncthreads();
        const uint4* src = reinterpret_cast<const uint4*>(hbuf);
        for (int q = t; q < 1024; q += 256) gdst[arr][q] = src[q];
    }
}

__global__ __launch_bounds__(256, 3)
void fused_pre_kernel(const float* __restrict__ n,
                      const float* __restrict__ prior)
{
    extern __shared__ float smf[];
    if (blockIdx.x < NPP) pp_part(blockIdx.x, threadIdx.x, smf, prior);
    else                  np_part(blockIdx.x - NPP, threadIdx.x, smf, n);
}

// ---------------- decode (runs inside K3, overlapping minmin) ------------------
#define NDEC 256          // decode blocks: 32 samples each
#define DEC_SMEM_FLOATS 17696

__device__ void decode_part(int bid, int t,
                            float* smf,
                            const float* __restrict__ n,
                            const float* __restrict__ z,
                            const float* __restrict__ znext,
                            float* __restrict__ out,
                            const float* __restrict__ w1W, const float* __restrict__ w1b,
                            const float* __restrict__ b1W, const float* __restrict__ b1b,
                            const float* __restrict__ w2W, const float* __restrict__ w2b,
                            const float* __restrict__ b2W, const float* __restrict__ b2b,
                            const float* __restrict__ w3W, const float* __restrict__ w3b,
                            const float* __restrict__ b3W, const float* __restrict__ b3b)
{
    float* nn   = smf;                 // 832 (32*26)
    float* z3   = nn + 832;            // 128
    float* h1   = z3 + 128;            // 2176 (32*68)
    float* h2   = h1 + 2176;           // 2176
    float* ring = h2 + 2176;           // 12288 (3 x 4096) — stage-A staging reuses this
    float* zh   = ring + 12288;        // 96
    float* s1W  = ring;                // 4800
    float* s1b  = s1W + 4800;          // 192
    float* sb1W = s1b + 192;           // 1600
    float* sb1b = sb1W + 1600;         // 64

    const long b0 = (long)bid * 32;

    for (int idx = t; idx < 32 * 25; idx += 256) {
        const int s = idx / 25, k = idx % 25;
        nn[s * 26 + k] = n[(b0 + s) * 25 + k];
    }
    for (int idx = t; idx < 32 * 3; idx += 256)
        z3[(idx / 3) * 4 + (idx % 3)] = z[b0 * 3 + idx];
    for (int idx = t; idx < 25 * 192; idx += 256) s1W[idx] = w1W[idx];
    for (int idx = t; idx < 192; idx += 256) s1b[idx] = w1b[idx];
    for (int idx = t; idx < 25 * 64; idx += 256) sb1W[idx] = b1W[idx];
    for (int idx = t; idx < 64; idx += 256) sb1b[idx] = b1b[idx];
    __syncthreads();

    for (int idx = t; idx < 2048; idx += 256) {
        const int s = idx >> 6, u = idx & 63;
        const float z0 = z3[s * 4], z1 = z3[s * 4 + 1], z2 = z3[s * 4 + 2];
        float acc = sb1b[u] + s1b[u * 3] * z0 + s1b[u * 3 + 1] * z1 + s1b[u * 3 + 2] * z2;
        #pragma unroll
        for (int k = 0; k < 25; k++)
            acc += nn[s * 26 + k] * (s1W[k * 192 + u * 3] * z0
                                   + s1W[k * 192 + u * 3 + 1] * z1
                                   + s1W[k * 192 + u * 3 + 2] * z2
                                   + sb1W[k * 64 + u]);
        h1[s * 68 + u] = (acc > 0.f) ? acc : expm1f(acc);
    }
    __syncthreads();

    const int s = t & 31, ig = t >> 5;
    const uint32_t ringa = smem_u32(ring);

    #pragma unroll
    for (int kk = 0; kk < 2; kk++) {
        const float* src = (kk < 25) ? (w2W + (long)kk * 4096) : w2b;
        #pragma unroll
        for (int q = 0; q < 4; q++) {
            const int idx = t + q * 256;
            CP16(ringa + (uint32_t)(kk * 16384 + idx * 16), src + idx * 4);
        }
        asm volatile("cp.async.commit_group;" ::: "memory");
    }

    unsigned long long acc2[8];
    #pragma unroll
    for (int m = 0; m < 8; m++) acc2[m] = 0ULL;

    for (int k = 0; k < 26; k++) {
        if (k < 25) asm volatile("cp.async.wait_group 1;" ::: "memory");
        else        asm volatile("cp.async.wait_group 0;" ::: "memory");
        __syncthreads();
        if (k + 2 < 26) {
            const float* src = (k + 2 < 25) ? (w2W + (long)(k + 2) * 4096) : w2b;
            #pragma unroll
            for (int q = 0; q < 4; q++) {
                const int idx = t + q * 256;
                CP16(ringa + (uint32_t)(((k + 2) % 3) * 16384 + idx * 16), src + idx * 4);
            }
            asm volatile("cp.async.commit_group;" ::: "memory");
        }

        const float* cur = ring + (k % 3) * 4096;
        const float coef = (k < 25) ? nn[s * 26 + k] : 1.f;
        unsigned long long coef2;
        asm("mov.b64 %0, {%1, %1};" : "=l"(coef2) : "f"(coef));

        #pragma unroll 4
        for (int j4 = 0; j4 < 16; j4++) {
            const float4 h4 = *reinterpret_cast<const float4*>(&h1[s * 68 + j4 * 4]);
            unsigned long long h01, h23, ch01, ch23;
            asm("mov.b64 %0, {%1, %2};" : "=l"(h01) : "f"(h4.x), "f"(h4.y));
            asm("mov.b64 %0, {%1, %2};" : "=l"(h23) : "f"(h4.z), "f"(h4.w));
            asm("mul.rn.f32x2 %0, %1, %2;" : "=l"(ch01) : "l"(coef2), "l"(h01));
            asm("mul.rn.f32x2 %0, %1, %2;" : "=l"(ch23) : "l"(coef2), "l"(h23));
            #pragma unroll
            for (int m = 0; m < 8; m++) {
                const float4 w4 = *reinterpret_cast<const float4*>(
                    &cur[(ig * 8 + m) * 64 + j4 * 4]);
                unsigned long long w01, w23;
                asm("mov.b64 %0, {%1, %2};" : "=l"(w01) : "f"(w4.x), "f"(w4.y));
                asm("mov.b64 %0, {%1, %2};" : "=l"(w23) : "f"(w4.z), "f"(w4.w));
                asm("fma.rn.f32x2 %0, %1, %2, %0;" : "+l"(acc2[m]) : "l"(ch01), "l"(w01));
                asm("fma.rn.f32x2 %0, %1, %2, %0;" : "+l"(acc2[m]) : "l"(ch23), "l"(w23));
            }
        }
    }

    #pragma unroll
    for (int m = 0; m < 8; m++) {
        const int i = ig * 8 + m;
        float b2 = b2b[i];
        #pragma unroll
        for (int k = 0; k < 25; k++) b2 += nn[s * 26 + k] * b2W[k * 64 + i];
        float lo, hi;
        asm("mov.b64 {%0, %1}, %2;" : "=f"(lo), "=f"(hi) : "l"(acc2[m]));
        const float v = lo + hi + b2;
        h2[s * 68 + i] = (v > 0.f) ? v : expm1f(v);
    }
    __syncthreads();

    if (t < 96) {
        const int ss = t / 3, d = t % 3;
        float a3 = b3b[d];
        #pragma unroll
        for (int k = 0; k < 25; k++) a3 += nn[ss * 26 + k] * b3W[k * 3 + d];
        for (int k = 0; k < 26; k++) {
            const float* row = (k < 25) ? (w3W + (long)k * 192 + d * 64) : (w3b + d * 64);
            const float coef = (k < 25) ? nn[ss * 26 + k] : 1.f;
            float tk = 0.f;
            #pragma unroll 8
            for (int j = 0; j < 64; j++) tk = fmaf(row[j], h2[ss * 68 + j], tk);
            a3 = fmaf(coef, tk, a3);
        }
        out[2 + (b0 + ss) * 3 + d] = a3;
        zh[ss * 3 + d] = a3;
    }
    __syncthreads();
    if (t < 32) {
        const float d0 = zh[t * 3]     - znext[(b0 + t) * 3];
        const float d1 = zh[t * 3 + 1] - znext[(b0 + t) * 3 + 1];
        const float d2 = zh[t * 3 + 2] - znext[(b0 + t) * 3 + 2];
        g_recon[b0 + t] = d0 * d0 + d1 * d1 + d2 * d2;
    }
}

// ---------------- minmin body (HMMA fp16-split, 2 j-subtiles per block) --------
#define MT 128
#define NTILE (BATCH / MT)                 // 64
#define NJG  (NTILE / 2)                   // 32 j-groups of 2 tiles
#define NB0  (NTILE * NJG)                 // 2048 pass-0 blocks
#define NB1  (NJG * (NJG + 1))             // 1056 pass-1 blocks
#define ROWH 40                            // padded row stride in halves (80 B)
#define K3_SMEM_BYTES (DEC_SMEM_FLOATS * 4)   // 70784 (covers minmin's 66048)
#define K3_NBLK (NDEC + NB0 + NB1)            // 3360

__device__ void minmin_body(int bid, int t, char* mshm)
{
    __half* Ah  = (__half*)mshm;
    __half* Al  = Ah + MT * ROWH;
    __half* Bh0 = Al + MT * ROWH;
    __half* Bl0 = Bh0 + 2 * MT * ROWH;
    float* rnA  = (float*)(Bl0 + 2 * MT * ROWH);
    float* rnB  = rnA + MT;
    float* cbuf = rnB + 2 * MT;
    float* rbuf = cbuf + 2 * MT;

    const int pass = (bid >= NB0);
    int ib, jg;
    if (!pass) { ib = bid >> 5; jg = bid & 31; }
    else {
        const int t0 = bid - NB0;
        jg = (int)((sqrtf(4.f * (float)t0 + 1.f) - 1.f) * 0.5f);
        while ((jg + 1) * (jg + 2) <= t0) jg++;
        while (jg * (jg + 1) > t0) jg--;
        ib = t0 - jg * (jg + 1);           // 0 .. 2jg+1
    }
    const long i0 = (long)ib * MT;
    const long j0 = (long)jg * 2 * MT;
    const __half* __restrict__ Ahg = pass ? g_Uhi : g_Phi;
    const __half* __restrict__ Alg = pass ? g_Ulo : g_Plo;
    const float* __restrict__ rnAs = pass ? g_rnG : g_rnP;
    unsigned* colmin                = pass ? g_minG : g_minP;

    for (int u = t; u < 512; u += 256) {
        const int r = u >> 2, c = u & 3;
        const long ga = (i0 + r) * KP + c * 8;
        *reinterpret_cast<uint4*>(reinterpret_cast<char*>(Ah) + r * 80 + c * 16)
            = *reinterpret_cast<const uint4*>(Ahg + ga);
        *reinterpret_cast<uint4*>(reinterpret_cast<char*>(Al) + r * 80 + c * 16)
            = *reinterpret_cast<const uint4*>(Alg + ga);
    }
    for (int u = t; u < 1024; u += 256) {
        const int r = u >> 2, c = u & 3;
        const long gb = (j0 + r) * KP + c * 8;
        const int sbt = r >> 7, rr = r & 127;
        *reinterpret_cast<uint4*>(reinterpret_cast<char*>(Bh0 + sbt * MT * ROWH)
                                  + rr * 80 + c * 16)
            = *reinterpret_cast<const uint4*>(g_Nhi + gb);
        *reinterpret_cast<uint4*>(reinterpret_cast<char*>(Bl0 + sbt * MT * ROWH)
                                  + rr * 80 + c * 16)
            = *reinterpret_cast<const uint4*>(g_Nlo + gb);
    }
    if (t < MT) rnA[t] = rnAs[i0 + t];
    rnB[t] = g_rnG[j0 + t];
    __syncthreads();

    const uint32_t sAh = smem_u32(Ah), sAl = smem_u32(Al);
    const int lane = t & 31, wid = t >> 5;
    const int wm = wid >> 2;               // 0..1 (64 rows)
    const int wn = wid & 3;                // 0..3 (32 cols)
    const int arow = wm * 64 + (lane & 7) + ((lane >> 3) & 1) * 8;
    const int ahalf = (lane >> 4) & 1;
    const int brow = wn * 32 + (lane & 7) + ((lane >> 4) & 1) * 8;
    const int bhalf = (lane >> 3) & 1;
    const int g = lane >> 2, tig = lane & 3;

    #pragma unroll
    for (int sub = 0; sub < 2; sub++) {
        const uint32_t sBh = smem_u32(Bh0 + sub * MT * ROWH);
        const uint32_t sBl = smem_u32(Bl0 + sub * MT * ROWH);
        const long j0s = j0 + sub * MT;
        const bool valid = !pass || (ib <= 2 * jg + sub);

        float d[4][4][4];
        #pragma unroll
        for (int mi = 0; mi < 4; mi++)
            #pragma unroll
            for (int ni = 0; ni < 4; ni++)
                #pragma unroll
                for (int q = 0; q < 4; q++) d[mi][ni][q] = 0.f;

        #pragma unroll
        for (int ks = 0; ks < 2; ks++) {
            const uint32_t ach = (uint32_t)((ks * 2 + ahalf) * 16);
            const uint32_t bch = (uint32_t)((ks * 2 + bhalf) * 16);
            uint32_t af[4][4], bfh[2][4], bfl[2][4];
            #pragma unroll
            for (int mi = 0; mi < 4; mi++)
                ldsm_x4(af[mi][0], af[mi][1], af[mi][2], af[mi][3],
                        sAh + (uint32_t)((arow + mi * 16) * 80) + ach);
            #pragma unroll
            for (int nb = 0; nb < 2; nb++)
                ldsm_x4(bfh[nb][0], bfh[nb][1], bfh[nb][2], bfh[nb][3],
                        sBh + (uint32_t)((brow + nb * 16) * 80) + bch);
            #pragma unroll
            for (int nb = 0; nb < 2; nb++)
                ldsm_x4(bfl[nb][0], bfl[nb][1], bfl[nb][2], bfl[nb][3],
                        sBl + (uint32_t)((brow + nb * 16) * 80) + bch);
            #pragma unroll
            for (int mi = 0; mi < 4; mi++)
                #pragma unroll
                for (int nb = 0; nb < 2; nb++) {
                    mma16816(d[mi][nb * 2],     af[mi], bfh[nb][0], bfh[nb][1]);
                    mma16816(d[mi][nb * 2 + 1], af[mi], bfh[nb][2], bfh[nb][3]);
                    mma16816(d[mi][nb * 2],     af[mi], bfl[nb][0], bfl[nb][1]);
                    mma16816(d[mi][nb * 2 + 1], af[mi], bfl[nb][2], bfl[nb][3]);
                }
            #pragma unroll
            for (int mi = 0; mi < 4; mi++)
                ldsm_x4(af[mi][0], af[mi][1], af[mi][2], af[mi][3],
                        sAl + (uint32_t)((arow + mi * 16) * 80) + ach);
            #pragma unroll
            for (int mi = 0; mi < 4; mi++)
                #pragma unroll
                for (int nb = 0; nb < 2; nb++) {
                    mma16816(d[mi][nb * 2],     af[mi], bfh[nb][0], bfh[nb][1]);
                    mma16816(d[mi][nb * 2 + 1], af[mi], bfh[nb][2], bfh[nb][3]);
                }
        }

        float cmin[4][2], rmin[4][2];
        #pragma unroll
        for (int q = 0; q < 4; q++) { cmin[q][0] = 1e30f; cmin[q][1] = 1e30f;
                                      rmin[q][0] = 1e30f; rmin[q][1] = 1e30f; }

        #pragma unroll
        for (int mi = 0; mi < 4; mi++) {
            const int r0 = wm * 64 + mi * 16 + g;
            const long ig0 = i0 + r0;
            const long ig1 = ig0 + 8;
            const float rn0 = rnA[r0];
            const float rn1 = rnA[r0 + 8];
            #pragma unroll
            for (int ni = 0; ni < 4; ni++) {
                const float d0 = d[mi][ni][0], d1 = d[mi][ni][1];
                const float d2 = d[mi][ni][2], d3 = d[mi][ni][3];
                float v0 = fmaf(-2.f, d0, rn0);
                float v1 = fmaf(-2.f, d1, rn0);
                float v2 = fmaf(-2.f, d2, rn1);
                float v3 = fmaf(-2.f, d3, rn1);
                if (pass) {
                    const int cc = wn * 32 + ni * 8 + 2 * tig;
                    const long jgl = j0s + cc;
                    float w0 = fmaf(-2.f, d0, rnB[sub * MT + cc]);
                    float w1 = fmaf(-2.f, d1, rnB[sub * MT + cc + 1]);
                    float w2 = fmaf(-2.f, d2, rnB[sub * MT + cc]);
                    float w3 = fmaf(-2.f, d3, rnB[sub * MT + cc + 1]);
                    if (ig0 == jgl)     { v0 = 1e30f; w0 = 1e30f; }
                    if (ig0 == jgl + 1) { v1 = 1e30f; w1 = 1e30f; }
                    if (ig1 == jgl)     { v2 = 1e30f; w2 = 1e30f; }
                    if (ig1 == jgl + 1) { v3 = 1e30f; w3 = 1e30f; }
                    rmin[mi][0] = fminf(rmin[mi][0], fminf(w0, w1));
                    rmin[mi][1] = fminf(rmin[mi][1], fminf(w2, w3));
                }
                cmin[ni][0] = fminf(cmin[ni][0], fminf(v0, v2));
                cmin[ni][1] = fminf(cmin[ni][1], fminf(v1, v3));
            }
        }

        #pragma unroll
        for (int off = 4; off <= 16; off <<= 1)
            #pragma unroll
            for (int ni = 0; ni < 4; ni++) {
                cmin[ni][0] = fminf(cmin[ni][0], __shfl_xor_sync(0xFFFFFFFFu, cmin[ni][0], off));
                cmin[ni][1] = fminf(cmin[ni][1], __shfl_xor_sync(0xFFFFFFFFu, cmin[ni][1], off));
            }
        if (pass) {
            #pragma unroll
            for (int off = 1; off <= 2; off <<= 1)
                #pragma unroll
                for (int mi = 0; mi < 4; mi++) {
                    rmin[mi][0] = fminf(rmin[mi][0], __shfl_xor_sync(0xFFFFFFFFu, rmin[mi][0], off));
                    rmin[mi][1] = fminf(rmin[mi][1], __shfl_xor_sync(0xFFFFFFFFu, rmin[mi][1], off));
                }
        }

        if (lane < 4) {
            #pragma unroll
            for (int ni = 0; ni < 4; ni++) {
                const int col = wn * 32 + ni * 8 + 2 * lane;
                cbuf[wm * MT + col]     = cmin[ni][0];
                cbuf[wm * MT + col + 1] = cmin[ni][1];
            }
        }
        if (pass && tig == 0) {
            #pragma unroll
            for (int mi = 0; mi < 4; mi++) {
                const int r0 = wm * 64 + mi * 16 + g;
                rbuf[r0 * 4 + wn]       = rmin[mi][0];
                rbuf[(r0 + 8) * 4 + wn] = rmin[mi][1];
            }
        }
        __syncthreads();

        if (valid && t < MT) {
            atomicMin(&colmin[j0s + t], fkey(fminf(cbuf[t], cbuf[MT + t])));
            if (pass) {
                const float m2 = fminf(fminf(rbuf[t * 4], rbuf[t * 4 + 1]),
                                       fminf(rbuf[t * 4 + 2], rbuf[t * 4 + 3]));
                atomicMin(&colmin[i0 + t], fkey(m2));
            }
        }
        __syncthreads();
    }
}

// ---------------- in-kernel finalize (last-block pattern) ----------------------
__device__ void finalize_body(float* smf, float* __restrict__ out, int t)
{
    float* s1 = smf;            // 256
    float* s2 = s1 + 256;       // 256
    float rsum = 0.f, ksum = 0.f;
    for (int j = t * 2; j < BATCH; j += 512) {
        const float2 rc = *reinterpret_cast<const float2*>(&g_recon[j]);
        const float2 rn = *reinterpret_cast<const float2*>(&g_rnG[j]);
        const uint2  mp = *reinterpret_cast<const uint2*>(&g_minP[j]);
        const uint2  mg = *reinterpret_cast<const uint2*>(&g_minG[j]);
        rsum += rc.x + rc.y;
        float wp0 = sqrtf(fmaxf(funkey(mp.x) + rn.x, 0.f) + 1e-8f);
        float ww0 = sqrtf(fmaxf(funkey(mg.x) + rn.x, 0.f) + 1e-8f);
        float wp1 = sqrtf(fmaxf(funkey(mp.y) + rn.y, 0.f) + 1e-8f);
        float ww1 = sqrtf(fmaxf(funkey(mg.y) + rn.y, 0.f) + 1e-8f);
        ksum += logf(wp0 / (ww0 + 1e-8f) + 1e-8f);
        ksum += logf(wp1 / (ww1 + 1e-8f) + 1e-8f);
    }
    s1[t] = rsum; s2[t] = ksum;
    __syncthreads();
    for (int off = 128; off > 0; off >>= 1) {
        if (t < off) { s1[t] += s1[t + off]; s2[t] += s2[t + off]; }
        __syncthreads();
    }
    if (t == 0) {
        out[0] = s1[0] / (float)BATCH;
        out[1] = s2[0] / (float)BATCH * (float)DTOT
               + logf((float)BATCH / (float)(BATCH - 1));
    }
}

// ---------------- K3: decode | minmin | last-block finalize --------------------
__global__ __launch_bounds__(256, 2)
void minmin_decode_kernel(const float* __restrict__ n,
                          const float* __restrict__ z,
                          const float* __restrict__ znext,
                          float* __restrict__ out,
                          const float* __restrict__ w1W, const float* __restrict__ w1b,
                          const float* __restrict__ b1W, const float* __restrict__ b1b,
                          const float* __restrict__ w2W, const float* __restrict__ w2b,
                          const float* __restrict__ b2W, const float* __restrict__ b2b,
                          const float* __restrict__ w3W, const float* __restrict__ w3b,
                          const float* __restrict__ b3W, const float* __restrict__ b3b)
{
    extern __shared__ char mshm[];
    const int t = threadIdx.x;
    if ((int)blockIdx.x < NDEC) {
        decode_part(blockIdx.x, t, (float*)mshm, n, z, znext, out,
                    w1W, w1b, b1W, b1b, w2W, w2b, b2W, b2b, w3W, w3b, b3W, b3b);
    } else {
        minmin_body(blockIdx.x - NDEC, t, mshm);
    }

    // last-block finalize: all colmin atomics + g_recon writes precede the fence
    __threadfence();
    __shared__ unsigned ticket;
    if (t == 0) ticket = atomicAdd(&g_done, 1u);
    __syncthreads();
    if (ticket == K3_NBLK - 1) {
        __syncthreads();                   // mshm reuse ordering within block
        finalize_body((float*)mshm, out, t);
    }
}

// ---------------- launch --------------------------------------------------------
extern "C" void kernel_launch(void* const* d_in, const int* in_sizes, int n_in,
                              void* d_out, int out_size)
{
    (void)in_sizes; (void)n_in; (void)out_size;
    const float* z     = (const float*)d_in[0];
    const float* znext = (const float*)d_in[1];
    const float* n     = (const float*)d_in[2];
    const float* prior = (const float*)d_in[3];
    const float* w1W = (const float*)d_in[4];  const float* w1b = (const float*)d_in[5];
    const float* b1W = (const float*)d_in[6];  const float* b1b = (const float*)d_in[7];
    const float* w2W = (const float*)d_in[8];  const float* w2b = (const float*)d_in[9];
    const float* b2W = (const float*)d_in[10]; const float* b2b = (const float*)d_in[11];
    const float* w3W = (const float*)d_in[12]; const float* w3b = (const float*)d_in[13];
    const float* b3W = (const float*)d_in[14]; const float* b3b = (const float*)d_in[15];
    float* out = (float*)d_out;

    cudaFuncSetAttribute(fused_pre_kernel,
                         cudaFuncAttributeMaxDynamicSharedMemorySize, PRE_SMEM_BYTES);
    cudaFuncSetAttribute(minmin_decode_kernel,
                         cudaFuncAttributeMaxDynamicSharedMemorySize, K3_SMEM_BYTES);

    prep_kernel<<<32 + RK * RK, 256>>>(
        w1W, w1b, b1W, b1b, w2W, w2b, b2W, b2b, w3W, w3b, b3W, b3b);
    fused_pre_kernel<<<NPP + NNP, 256, PRE_SMEM_BYTES>>>(n, prior);
    minmin_decode_kernel<<<K3_NBLK, 256, K3_SMEM_BYTES>>>(
        n, z, znext, out,
        w1W, w1b, b1W, b1b, w2W, w2b, b2W, b2b, w3W, w3b, b3W, b3b);
}

// round 17
// speedup vs baseline: 17.2335x; 1.0066x over previous
#include <cuda_runtime.h>
#include <cuda_fp16.h>
#include <math.h>
#include <stdint.h>

#define BATCH 8192
#define DTOT  4611
#define RK    26               // rank of G: 25 noise dims + bias
#define KP    32               // fp16 K padded

// ---------------- static device scratch -------------------------------------
__device__ float g_Wp[RK * DTOT];      // W' (26 x 4611)
__device__ float g_M[RK * RK];         // W' W'^T
__device__ __half g_Uhi[(size_t)BATCH * KP];   // hi/lo splits, K padded to 32
__device__ __half g_Ulo[(size_t)BATCH * KP];
__device__ __half g_Nhi[(size_t)BATCH * KP];
__device__ __half g_Nlo[(size_t)BATCH * KP];
__device__ __half g_Phi[(size_t)BATCH * KP];
__device__ __half g_Plo[(size_t)BATCH * KP];
__device__ float    g_rnP[BATCH];
__device__ float    g_rnG[BATCH];
__device__ unsigned g_minP[BATCH];
__device__ unsigned g_minG[BATCH];
__device__ float    g_recon[BATCH];
__device__ unsigned g_done;

__device__ __forceinline__ unsigned fkey(float f) {
    unsigned u = __float_as_uint(f);
    return (u & 0x80000000u) ? ~u : (u | 0x80000000u);
}
__device__ __forceinline__ float funkey(unsigned k) {
    unsigned u = (k & 0x80000000u) ? (k ^ 0x80000000u) : ~k;
    return __uint_as_float(u);
}

__device__ __forceinline__ uint32_t smem_u32(const void* p) {
    uint32_t a;
    asm("{ .reg .u64 t; cvta.to.shared.u64 t, %1; cvt.u32.u64 %0, t; }" : "=r"(a) : "l"(p));
    return a;
}
__device__ __forceinline__ void ldsm_x4(uint32_t& r0, uint32_t& r1, uint32_t& r2,
                                        uint32_t& r3, uint32_t addr) {
    asm volatile("ldmatrix.sync.aligned.m8n8.x4.shared.b16 {%0,%1,%2,%3}, [%4];"
                 : "=r"(r0), "=r"(r1), "=r"(r2), "=r"(r3) : "r"(addr));
}
__device__ __forceinline__ void mma16816(float* d, const uint32_t* a,
                                         uint32_t b0, uint32_t b1) {
    asm volatile("mma.sync.aligned.m16n8k16.row.col.f32.f16.f16.f32 "
                 "{%0,%1,%2,%3}, {%4,%5,%6,%7}, {%8,%9}, {%0,%1,%2,%3};"
                 : "+f"(d[0]), "+f"(d[1]), "+f"(d[2]), "+f"(d[3])
                 : "r"(a[0]), "r"(a[1]), "r"(a[2]), "r"(a[3]), "r"(b0), "r"(b1));
}
__device__ __forceinline__ unsigned long long ld2u64(const float* p) {
    return *reinterpret_cast<const unsigned long long*>(p);
}

// raw-weight selector: segment for column c of W'
__device__ __forceinline__ void wp_sel(int c,
                                       const float* w1W, const float* w1b,
                                       const float* b1W, const float* b1b,
                                       const float* w2W, const float* w2b,
                                       const float* b2W, const float* b2b,
                                       const float* w3W, const float* w3b,
                                       const float* b3W, const float* b3b,
                                       const float** W, const float** bias,
                                       int* local, int* width)
{
    if      (c < 192)  { *W = w1W; *bias = w1b; *local = c;        *width = 192;  }
    else if (c < 256)  { *W = b1W; *bias = b1b; *local = c - 192;  *width = 64;   }
    else if (c < 4352) { *W = w2W; *bias = w2b; *local = c - 256;  *width = 4096; }
    else if (c < 4416) { *W = b2W; *bias = b2b; *local = c - 4352; *width = 64;   }
    else if (c < 4608) { *W = w3W; *bias = w3b; *local = c - 4416; *width = 192;  }
    else               { *W = b3W; *bias = b3b; *local = c - 4608; *width = 3;    }
}

// ---------------- K1: prep — build W' + init mins + g_done | compute M --------
__global__ __launch_bounds__(256)
void prep_kernel(const float* __restrict__ w1W, const float* __restrict__ w1b,
                 const float* __restrict__ b1W, const float* __restrict__ b1b,
                 const float* __restrict__ w2W, const float* __restrict__ w2b,
                 const float* __restrict__ b2W, const float* __restrict__ b2b,
                 const float* __restrict__ w3W, const float* __restrict__ w3b,
                 const float* __restrict__ b3W, const float* __restrict__ b3b)
{
    if (blockIdx.x == 0 && threadIdx.x == 0) g_done = 0u;
    if (blockIdx.x < 32) {
        const int c = blockIdx.x * 256 + threadIdx.x;
        if (c < BATCH) { g_minP[c] = 0xFFFFFFFFu; g_minG[c] = 0xFFFFFFFFu; }
        if (c >= DTOT) return;
        const float* W; const float* bias; int local, width;
        wp_sel(c, w1W, w1b, b1W, b1b, w2W, w2b, b2W, b2b, w3W, w3b, b3W, b3b,
               &W, &bias, &local, &width);
        #pragma unroll
        for (int k = 0; k < 25; k++) g_Wp[k * DTOT + c] = W[k * width + local];
        g_Wp[25 * DTOT + c] = bias[local];
    } else {
        __shared__ float sm[256];
        const int p = blockIdx.x - 32;          // 0..675
        const int a = p / RK, b = p % RK;
        float s = 0.f;
        for (int c = threadIdx.x; c < DTOT; c += 256) {
            const float* W; const float* bias; int local, width;
            wp_sel(c, w1W, w1b, b1W, b1b, w2W, w2b, b2W, b2b, w3W, w3b, b3W, b3b,
                   &W, &bias, &local, &width);
            const float va = (a < 25) ? W[a * width + local] : bias[local];
            const float vb = (b < 25) ? W[b * width + local] : bias[local];
            s += va * vb;
        }
        sm[threadIdx.x] = s;
        __syncthreads();
        for (int off = 128; off > 0; off >>= 1) {
            if (threadIdx.x < off) sm[threadIdx.x] += sm[threadIdx.x + off];
            __syncthreads();
        }
        if (threadIdx.x == 0) g_M[a * RK + b] = sm[0];
    }
}

// ---------------- K2: fused pre — pp | np_u -----------------------------------
#define NPP  256          // pp blocks: 32 prior rows each
#define NNP  32           // np_u blocks: 256 samples each

#define CP16(dst, src) \
    asm volatile("cp.async.cg.shared.global [%0], [%1], 16;" \
                 :: "r"(dst), "l"(src) : "memory")
#define CP4(dst, src) \
    asm volatile("cp.async.ca.shared.global [%0], [%1], 4;" \
                 :: "r"(dst), "l"(src) : "memory")

// pp: 3-stage cp.async ring, chunk width 96, single sync per chunk.
#define PPKC 96
#define PPSP 100                        // padded sp row stride (floats)
#define PPSTG (32 * PPSP + RK * PPKC)   // 5696 floats per stage
#define PPNCH ((DTOT + PPKC - 1) / PPKC)  // 49
#define PRE_SMEM_BYTES (PPSTG * 3 * 4)    // 68352

__device__ void pp_issue_chunk(uint32_t stga, int ch, long row0, int t,
                               const float* __restrict__ prior, float* stg)
{
    const int k0 = ch * PPKC;
    for (int idx = t; idx < 32 * PPKC; idx += 256) {
        const int rr = idx / PPKC, c = idx % PPKC;
        if (k0 + c < DTOT)
            CP4(stga + (uint32_t)((rr * PPSP + c) * 4),
                prior + (row0 + rr) * (long)DTOT + k0 + c);
        else
            stg[rr * PPSP + c] = 0.f;
    }
    const uint32_t swa = stga + (uint32_t)(32 * PPSP * 4);
    float* sw = stg + 32 * PPSP;
    for (int idx = t; idx < RK * PPKC; idx += 256) {
        const int m = idx / PPKC, c = idx % PPKC;
        if (k0 + c < DTOT)
            CP4(swa + (uint32_t)((m * PPKC + c) * 4),
                g_Wp + (long)m * DTOT + k0 + c);
        else
            sw[m * PPKC + c] = 0.f;
    }
    asm volatile("cp.async.commit_group;" ::: "memory");
}

__device__ void pp_part(int pbid, int t, float* smf, const float* __restrict__ prior)
{
    const long row0 = (long)pbid * 32;
    const int r = t & 31;
    const int grp = t >> 5;            // warp-uniform, 0..7
    const uint32_t smfa = smem_u32(smf);

    pp_issue_chunk(smfa, 0, row0, t, prior, smf);
    pp_issue_chunk(smfa + (uint32_t)(PPSTG * 4), 1, row0, t, prior, smf + PPSTG);

    unsigned long long acc2[4];
    #pragma unroll
    for (int q = 0; q < 4; q++) acc2[q] = 0ULL;

    for (int ch = 0; ch < PPNCH; ch++) {
        if (ch + 1 < PPNCH) asm volatile("cp.async.wait_group 1;" ::: "memory");
        else                asm volatile("cp.async.wait_group 0;" ::: "memory");
        __syncthreads();
        if (ch + 2 < PPNCH) {
            const int st = (ch + 2) % 3;
            pp_issue_chunk(smfa + (uint32_t)(st * PPSTG * 4), ch + 2, row0, t,
                           prior, smf + st * PPSTG);
        }

        const float* sp = smf + (ch % 3) * PPSTG;
        const float* sw = sp + 32 * PPSP;

        // mov-free inner loop: operand pairs loaded directly as 64-bit LDS
        #pragma unroll 4
        for (int c4 = 0; c4 < PPKC / 4; c4++) {
            const unsigned long long s01 = ld2u64(&sp[r * PPSP + c4 * 4]);
            const unsigned long long s23 = ld2u64(&sp[r * PPSP + c4 * 4 + 2]);
            #pragma unroll
            for (int q = 0; q < 4; q++) {
                const int m = 4 * grp + q;
                if (m > 26) continue;
                unsigned long long w01, w23;
                if (m < 26) {
                    w01 = ld2u64(&sw[m * PPKC + c4 * 4]);
                    w23 = ld2u64(&sw[m * PPKC + c4 * 4 + 2]);
                } else {
                    w01 = s01; w23 = s23;           // norm: v*v
                }
                asm("fma.rn.f32x2 %0, %1, %2, %0;" : "+l"(acc2[q]) : "l"(s01), "l"(w01));
                asm("fma.rn.f32x2 %0, %1, %2, %0;" : "+l"(acc2[q]) : "l"(s23), "l"(w23));
            }
        }
    }

    #pragma unroll
    for (int q = 0; q < 4; q++) {
        const int m = 4 * grp + q;
        if (m > 26) continue;
        float lo, hi;
        asm("mov.b64 {%0, %1}, %2;" : "=f"(lo), "=f"(hi) : "l"(acc2[q]));
        const float sum = lo + hi;
        if (m < 26) {
            const __half h = __float2half_rn(sum);
            g_Phi[(row0 + r) * KP + m] = h;
            g_Plo[(row0 + r) * KP + m] = __float2half_rn(sum - __half2float(h));
        } else {
            g_rnP[row0 + r] = sum;
        }
    }
    if (t < 192) {
        const int rr = t / 6, kp = 26 + t % 6;
        g_Phi[(row0 + rr) * KP + kp] = __float2half_rn(0.f);
        g_Plo[(row0 + rr) * KP + kp] = __float2half_rn(0.f);
    }
}

// np: compute U, N splits with smem-staged coalesced stores
__device__ void np_part(int nbid, int t, float* smf, const float* __restrict__ n)
{
    float* Ms  = smf;                  // 676
    float* nsh = Ms + 676;             // 256 x 26 = 6656
    __half* hbuf = (__half*)(nsh + 6656);   // 256 x 32 halves = 16 KB

    for (int idx = t; idx < RK * RK; idx += 256) Ms[idx] = g_M[idx];
    const long s0 = (long)nbid * 256;
    for (int idx = t; idx < 256 * 25; idx += 256) {
        const int s = idx / 25, k = idx % 25;
        nsh[s * 26 + k] = n[(s0 + s) * 25 + k];
    }
    for (int idx = t; idx < 256; idx += 256) nsh[idx * 26 + 25] = 1.f;
    __syncthreads();

    float u[RK];
    float rn = 0.f;
    #pragma unroll
    for (int a = 0; a < RK; a++) {
        float uu = 0.f;
        #pragma unroll
        for (int b = 0; b < RK; b++) uu = fmaf(nsh[t * 26 + b], Ms[b * RK + a], uu);
        u[a] = uu;
        rn = fmaf(uu, nsh[t * 26 + a], rn);
    }
    g_rnG[s0 + t] = rn;

    const __half hz = __float2half_rn(0.f);
    uint4* gdst[4] = { reinterpret_cast<uint4*>(g_Uhi + s0 * KP),
                       reinterpret_cast<uint4*>(g_Ulo + s0 * KP),
                       reinterpret_cast<uint4*>(g_Nhi + s0 * KP),
                       reinterpret_cast<uint4*>(g_Nlo + s0 * KP) };
    #pragma unroll
    for (int arr = 0; arr < 4; arr++) {
        __syncthreads();
        #pragma unroll
        for (int a = 0; a < RK; a++) {
            const float v = (arr < 2) ? u[a] : nsh[t * 26 + a];
            const __half h = __float2half_rn(v);
            hbuf[t * KP + a] = (arr & 1)
                ? __float2half_rn(v - __half2float(h)) : h;
        }
        #pragma unroll
        for (int a = RK; a < KP; a++) hbuf[t * KP + a] = hz;
        __syncthreads();
        const uint4* src = reinterpret_cast<const uint4*>(hbuf);
        for (int q = t; q < 1024; q += 256) gdst[arr][q] = src[q];
    }
}

__global__ __launch_bounds__(256, 3)
void fused_pre_kernel(const float* __restrict__ n,
                      const float* __restrict__ prior)
{
    extern __shared__ float smf[];
    if (blockIdx.x < NPP) pp_part(blockIdx.x, threadIdx.x, smf, prior);
    else                  np_part(blockIdx.x - NPP, threadIdx.x, smf, n);
}

// ---------------- decode (runs inside K3, overlapping minmin) ------------------
#define NDEC 256          // decode blocks: 32 samples each
#define DEC_SMEM_FLOATS 17696

__device__ void decode_part(int bid, int t,
                            float* smf,
                            const float* __restrict__ n,
                            const float* __restrict__ z,
                            const float* __restrict__ znext,
                            float* __restrict__ out,
                            const float* __restrict__ w1W, const float* __restrict__ w1b,
                            const float* __restrict__ b1W, const float* __restrict__ b1b,
                            const float* __restrict__ w2W, const float* __restrict__ w2b,
                            const float* __restrict__ b2W, const float* __restrict__ b2b,
                            const float* __restrict__ w3W, const float* __restrict__ w3b,
                            const float* __restrict__ b3W, const float* __restrict__ b3b)
{
    float* nn   = smf;                 // 832 (32*26)
    float* z3   = nn + 832;            // 128
    float* h1   = z3 + 128;            // 2176 (32*68)
    float* h2   = h1 + 2176;           // 2176
    float* ring = h2 + 2176;           // 12288 (3 x 4096) — stage-A staging reuses this
    float* zh   = ring + 12288;        // 96
    float* s1W  = ring;                // 4800
    float* s1b  = s1W + 4800;          // 192
    float* sb1W = s1b + 192;           // 1600
    float* sb1b = sb1W + 1600;         // 64

    const long b0 = (long)bid * 32;

    for (int idx = t; idx < 32 * 25; idx += 256) {
        const int s = idx / 25, k = idx % 25;
        nn[s * 26 + k] = n[(b0 + s) * 25 + k];
    }
    for (int idx = t; idx < 32 * 3; idx += 256)
        z3[(idx / 3) * 4 + (idx % 3)] = z[b0 * 3 + idx];
    for (int idx = t; idx < 25 * 192; idx += 256) s1W[idx] = w1W[idx];
    for (int idx = t; idx < 192; idx += 256) s1b[idx] = w1b[idx];
    for (int idx = t; idx < 25 * 64; idx += 256) sb1W[idx] = b1W[idx];
    for (int idx = t; idx < 64; idx += 256) sb1b[idx] = b1b[idx];
    __syncthreads();

    for (int idx = t; idx < 2048; idx += 256) {
        const int s = idx >> 6, u = idx & 63;
        const float z0 = z3[s * 4], z1 = z3[s * 4 + 1], z2 = z3[s * 4 + 2];
        float acc = sb1b[u] + s1b[u * 3] * z0 + s1b[u * 3 + 1] * z1 + s1b[u * 3 + 2] * z2;
        #pragma unroll
        for (int k = 0; k < 25; k++)
            acc += nn[s * 26 + k] * (s1W[k * 192 + u * 3] * z0
                                   + s1W[k * 192 + u * 3 + 1] * z1
                                   + s1W[k * 192 + u * 3 + 2] * z2
                                   + sb1W[k * 64 + u]);
        h1[s * 68 + u] = (acc > 0.f) ? acc : expm1f(acc);
    }
    __syncthreads();

    const int s = t & 31, ig = t >> 5;
    const uint32_t ringa = smem_u32(ring);

    #pragma unroll
    for (int kk = 0; kk < 2; kk++) {
        const float* src = (kk < 25) ? (w2W + (long)kk * 4096) : w2b;
        #pragma unroll
        for (int q = 0; q < 4; q++) {
            const int idx = t + q * 256;
            CP16(ringa + (uint32_t)(kk * 16384 + idx * 16), src + idx * 4);
        }
        asm volatile("cp.async.commit_group;" ::: "memory");
    }

    unsigned long long acc2[8];
    #pragma unroll
    for (int m = 0; m < 8; m++) acc2[m] = 0ULL;

    for (int k = 0; k < 26; k++) {
        if (k < 25) asm volatile("cp.async.wait_group 1;" ::: "memory");
        else        asm volatile("cp.async.wait_group 0;" ::: "memory");
        __syncthreads();
        if (k + 2 < 26) {
            const float* src = (k + 2 < 25) ? (w2W + (long)(k + 2) * 4096) : w2b;
            #pragma unroll
            for (int q = 0; q < 4; q++) {
                const int idx = t + q * 256;
                CP16(ringa + (uint32_t)(((k + 2) % 3) * 16384 + idx * 16), src + idx * 4);
            }
            asm volatile("cp.async.commit_group;" ::: "memory");
        }

        const float* cur = ring + (k % 3) * 4096;
        const float coef = (k < 25) ? nn[s * 26 + k] : 1.f;
        unsigned long long coef2;
        asm("mov.b64 %0, {%1, %1};" : "=l"(coef2) : "f"(coef));

        // mov-free inner loop: 64-bit LDS into f32x2 operands
        #pragma unroll 4
        for (int j4 = 0; j4 < 16; j4++) {
            const unsigned long long h01 = ld2u64(&h1[s * 68 + j4 * 4]);
            const unsigned long long h23 = ld2u64(&h1[s * 68 + j4 * 4 + 2]);
            unsigned long long ch01, ch23;
            asm("mul.rn.f32x2 %0, %1, %2;" : "=l"(ch01) : "l"(coef2), "l"(h01));
            asm("mul.rn.f32x2 %0, %1, %2;" : "=l"(ch23) : "l"(coef2), "l"(h23));
            #pragma unroll
            for (int m = 0; m < 8; m++) {
                const unsigned long long w01 = ld2u64(&cur[(ig * 8 + m) * 64 + j4 * 4]);
                const unsigned long long w23 = ld2u64(&cur[(ig * 8 + m) * 64 + j4 * 4 + 2]);
                asm("fma.rn.f32x2 %0, %1, %2, %0;" : "+l"(acc2[m]) : "l"(ch01), "l"(w01));
                asm("fma.rn.f32x2 %0, %1, %2, %0;" : "+l"(acc2[m]) : "l"(ch23), "l"(w23));
            }
        }
    }

    #pragma unroll
    for (int m = 0; m < 8; m++) {
        const int i = ig * 8 + m;
        float b2 = b2b[i];
        #pragma unroll
        for (int k = 0; k < 25; k++) b2 += nn[s * 26 + k] * b2W[k * 64 + i];
        float lo, hi;
        asm("mov.b64 {%0, %1}, %2;" : "=f"(lo), "=f"(hi) : "l"(acc2[m]));
        const float v = lo + hi + b2;
        h2[s * 68 + i] = (v > 0.f) ? v : expm1f(v);
    }
    __syncthreads();

    if (t < 96) {
        const int ss = t / 3, d = t % 3;
        float a3 = b3b[d];
        #pragma unroll
        for (int k = 0; k < 25; k++) a3 += nn[ss * 26 + k] * b3W[k * 3 + d];
        for (int k = 0; k < 26; k++) {
            const float* row = (k < 25) ? (w3W + (long)k * 192 + d * 64) : (w3b + d * 64);
            const float coef = (k < 25) ? nn[ss * 26 + k] : 1.f;
            float tk = 0.f;
            #pragma unroll 8
            for (int j = 0; j < 64; j++) tk = fmaf(row[j], h2[ss * 68 + j], tk);
            a3 = fmaf(coef, tk, a3);
        }
        out[2 + (b0 + ss) * 3 + d] = a3;
        zh[ss * 3 + d] = a3;
    }
    __syncthreads();
    if (t < 32) {
        const float d0 = zh[t * 3]     - znext[(b0 + t) * 3];
        const float d1 = zh[t * 3 + 1] - znext[(b0 + t) * 3 + 1];
        const float d2 = zh[t * 3 + 2] - znext[(b0 + t) * 3 + 2];
        g_recon[b0 + t] = d0 * d0 + d1 * d1 + d2 * d2;
    }
}

// ---------------- minmin body (HMMA fp16-split, 2 j-subtiles per block) --------
#define MT 128
#define NTILE (BATCH / MT)                 // 64
#define NJG  (NTILE / 2)                   // 32 j-groups of 2 tiles
#define NB0  (NTILE * NJG)                 // 2048 pass-0 blocks
#define NB1  (NJG * (NJG + 1))             // 1056 pass-1 blocks
#define ROWH 40                            // padded row stride in halves (80 B)
#define K3_SMEM_BYTES (DEC_SMEM_FLOATS * 4)   // 70784
#define K3_NBLK (NDEC + NB0 + NB1)            // 3360

__device__ void minmin_body(int bid, int t, char* mshm)
{
    __half* Ah  = (__half*)mshm;
    __half* Al  = Ah + MT * ROWH;
    __half* Bh0 = Al + MT * ROWH;
    __half* Bl0 = Bh0 + 2 * MT * ROWH;
    float* rnA  = (float*)(Bl0 + 2 * MT * ROWH);
    float* rnB  = rnA + MT;
    float* cbuf = rnB + 2 * MT;
    float* rbuf = cbuf + 2 * MT;

    const int pass = (bid >= NB0);
    int ib, jg;
    if (!pass) { ib = bid >> 5; jg = bid & 31; }
    else {
        const int t0 = bid - NB0;
        jg = (int)((sqrtf(4.f * (float)t0 + 1.f) - 1.f) * 0.5f);
        while ((jg + 1) * (jg + 2) <= t0) jg++;
        while (jg * (jg + 1) > t0) jg--;
        ib = t0 - jg * (jg + 1);           // 0 .. 2jg+1
    }
    const long i0 = (long)ib * MT;
    const long j0 = (long)jg * 2 * MT;
    const __half* __restrict__ Ahg = pass ? g_Uhi : g_Phi;
    const __half* __restrict__ Alg = pass ? g_Ulo : g_Plo;
    const float* __restrict__ rnAs = pass ? g_rnG : g_rnP;
    unsigned* colmin                = pass ? g_minG : g_minP;

    for (int u = t; u < 512; u += 256) {
        const int r = u >> 2, c = u & 3;
        const long ga = (i0 + r) * KP + c * 8;
        *reinterpret_cast<uint4*>(reinterpret_cast<char*>(Ah) + r * 80 + c * 16)
            = *reinterpret_cast<const uint4*>(Ahg + ga);
        *reinterpret_cast<uint4*>(reinterpret_cast<char*>(Al) + r * 80 + c * 16)
            = *reinterpret_cast<const uint4*>(Alg + ga);
    }
    for (int u = t; u < 1024; u += 256) {
        const int r = u >> 2, c = u & 3;
        const long gb = (j0 + r) * KP + c * 8;
        const int sbt = r >> 7, rr = r & 127;
        *reinterpret_cast<uint4*>(reinterpret_cast<char*>(Bh0 + sbt * MT * ROWH)
                                  + rr * 80 + c * 16)
            = *reinterpret_cast<const uint4*>(g_Nhi + gb);
        *reinterpret_cast<uint4*>(reinterpret_cast<char*>(Bl0 + sbt * MT * ROWH)
                                  + rr * 80 + c * 16)
            = *reinterpret_cast<const uint4*>(g_Nlo + gb);
    }
    if (t < MT) rnA[t] = rnAs[i0 + t];
    rnB[t] = g_rnG[j0 + t];
    __syncthreads();

    const uint32_t sAh = smem_u32(Ah), sAl = smem_u32(Al);
    const int lane = t & 31, wid = t >> 5;
    const int wm = wid >> 2;               // 0..1 (64 rows)
    const int wn = wid & 3;                // 0..3 (32 cols)
    const int arow = wm * 64 + (lane & 7) + ((lane >> 3) & 1) * 8;
    const int ahalf = (lane >> 4) & 1;
    const int brow = wn * 32 + (lane & 7) + ((lane >> 4) & 1) * 8;
    const int bhalf = (lane >> 3) & 1;
    const int g = lane >> 2, tig = lane & 3;

    #pragma unroll
    for (int sub = 0; sub < 2; sub++) {
        const uint32_t sBh = smem_u32(Bh0 + sub * MT * ROWH);
        const uint32_t sBl = smem_u32(Bl0 + sub * MT * ROWH);
        const long j0s = j0 + sub * MT;
        const bool valid = !pass || (ib <= 2 * jg + sub);

        float d[4][4][4];
        #pragma unroll
        for (int mi = 0; mi < 4; mi++)
            #pragma unroll
            for (int ni = 0; ni < 4; ni++)
                #pragma unroll
                for (int q = 0; q < 4; q++) d[mi][ni][q] = 0.f;

        #pragma unroll
        for (int ks = 0; ks < 2; ks++) {
            const uint32_t ach = (uint32_t)((ks * 2 + ahalf) * 16);
            const uint32_t bch = (uint32_t)((ks * 2 + bhalf) * 16);
            uint32_t af[4][4], bfh[2][4], bfl[2][4];
            #pragma unroll
            for (int mi = 0; mi < 4; mi++)
                ldsm_x4(af[mi][0], af[mi][1], af[mi][2], af[mi][3],
                        sAh + (uint32_t)((arow + mi * 16) * 80) + ach);
            #pragma unroll
            for (int nb = 0; nb < 2; nb++)
                ldsm_x4(bfh[nb][0], bfh[nb][1], bfh[nb][2], bfh[nb][3],
                        sBh + (uint32_t)((brow + nb * 16) * 80) + bch);
            #pragma unroll
            for (int nb = 0; nb < 2; nb++)
                ldsm_x4(bfl[nb][0], bfl[nb][1], bfl[nb][2], bfl[nb][3],
                        sBl + (uint32_t)((brow + nb * 16) * 80) + bch);
            #pragma unroll
            for (int mi = 0; mi < 4; mi++)
                #pragma unroll
                for (int nb = 0; nb < 2; nb++) {
                    mma16816(d[mi][nb * 2],     af[mi], bfh[nb][0], bfh[nb][1]);
                    mma16816(d[mi][nb * 2 + 1], af[mi], bfh[nb][2], bfh[nb][3]);
                    mma16816(d[mi][nb * 2],     af[mi], bfl[nb][0], bfl[nb][1]);
                    mma16816(d[mi][nb * 2 + 1], af[mi], bfl[nb][2], bfl[nb][3]);
                }
            #pragma unroll
            for (int mi = 0; mi < 4; mi++)
                ldsm_x4(af[mi][0], af[mi][1], af[mi][2], af[mi][3],
                        sAl + (uint32_t)((arow + mi * 16) * 80) + ach);
            #pragma unroll
            for (int mi = 0; mi < 4; mi++)
                #pragma unroll
                for (int nb = 0; nb < 2; nb++) {
                    mma16816(d[mi][nb * 2],     af[mi], bfh[nb][0], bfh[nb][1]);
                    mma16816(d[mi][nb * 2 + 1], af[mi], bfh[nb][2], bfh[nb][3]);
                }
        }

        float cmin[4][2], rmin[4][2];
        #pragma unroll
        for (int q = 0; q < 4; q++) { cmin[q][0] = 1e30f; cmin[q][1] = 1e30f;
                                      rmin[q][0] = 1e30f; rmin[q][1] = 1e30f; }

        #pragma unroll
        for (int mi = 0; mi < 4; mi++) {
            const int r0 = wm * 64 + mi * 16 + g;
            const long ig0 = i0 + r0;
            const long ig1 = ig0 + 8;
            const float rn0 = rnA[r0];
            const float rn1 = rnA[r0 + 8];
            #pragma unroll
            for (int ni = 0; ni < 4; ni++) {
                const float d0 = d[mi][ni][0], d1 = d[mi][ni][1];
                const float d2 = d[mi][ni][2], d3 = d[mi][ni][3];
                float v0 = fmaf(-2.f, d0, rn0);
                float v1 = fmaf(-2.f, d1, rn0);
                float v2 = fmaf(-2.f, d2, rn1);
                float v3 = fmaf(-2.f, d3, rn1);
                if (pass) {
                    const int cc = wn * 32 + ni * 8 + 2 * tig;
                    const long jgl = j0s + cc;
                    float w0 = fmaf(-2.f, d0, rnB[sub * MT + cc]);
                    float w1 = fmaf(-2.f, d1, rnB[sub * MT + cc + 1]);
                    float w2 = fmaf(-2.f, d2, rnB[sub * MT + cc]);
                    float w3 = fmaf(-2.f, d3, rnB[sub * MT + cc + 1]);
                    if (ig0 == jgl)     { v0 = 1e30f; w0 = 1e30f; }
                    if (ig0 == jgl + 1) { v1 = 1e30f; w1 = 1e30f; }
                    if (ig1 == jgl)     { v2 = 1e30f; w2 = 1e30f; }
                    if (ig1 == jgl + 1) { v3 = 1e30f; w3 = 1e30f; }
                    rmin[mi][0] = fminf(rmin[mi][0], fminf(w0, w1));
                    rmin[mi][1] = fminf(rmin[mi][1], fminf(w2, w3));
                }
                cmin[ni][0] = fminf(cmin[ni][0], fminf(v0, v2));
                cmin[ni][1] = fminf(cmin[ni][1], fminf(v1, v3));
            }
        }

        #pragma unroll
        for (int off = 4; off <= 16; off <<= 1)
            #pragma unroll
            for (int ni = 0; ni < 4; ni++) {
                cmin[ni][0] = fminf(cmin[ni][0], __shfl_xor_sync(0xFFFFFFFFu, cmin[ni][0], off));
                cmin[ni][1] = fminf(cmin[ni][1], __shfl_xor_sync(0xFFFFFFFFu, cmin[ni][1], off));
            }
        if (pass) {
            #pragma unroll
            for (int off = 1; off <= 2; off <<= 1)
                #pragma unroll
                for (int mi = 0; mi < 4; mi++) {
                    rmin[mi][0] = fminf(rmin[mi][0], __shfl_xor_sync(0xFFFFFFFFu, rmin[mi][0], off));
                    rmin[mi][1] = fminf(rmin[mi][1], __shfl_xor_sync(0xFFFFFFFFu, rmin[mi][1], off));
                }
        }

        if (lane < 4) {
            #pragma unroll
            for (int ni = 0; ni < 4; ni++) {
                const int col = wn * 32 + ni * 8 + 2 * lane;
                cbuf[wm * MT + col]     = cmin[ni][0];
                cbuf[wm * MT + col + 1] = cmin[ni][1];
            }
        }
        if (pass && tig == 0) {
            #pragma unroll
            for (int mi = 0; mi < 4; mi++) {
                const int r0 = wm * 64 + mi * 16 + g;
                rbuf[r0 * 4 + wn]       = rmin[mi][0];
                rbuf[(r0 + 8) * 4 + wn] = rmin[mi][1];
            }
        }
        __syncthreads();

        if (valid && t < MT) {
            atomicMin(&colmin[j0s + t], fkey(fminf(cbuf[t], cbuf[MT + t])));
            if (pass) {
                const float m2 = fminf(fminf(rbuf[t * 4], rbuf[t * 4 + 1]),
                                       fminf(rbuf[t * 4 + 2], rbuf[t * 4 + 3]));
                atomicMin(&colmin[i0 + t], fkey(m2));
            }
        }
        __syncthreads();
    }
}

// ---------------- in-kernel finalize (last-block pattern) ----------------------
__device__ void finalize_body(float* smf, float* __restrict__ out, int t)
{
    float* s1 = smf;            // 256
    float* s2 = s1 + 256;       // 256
    float rsum = 0.f, ksum = 0.f;
    for (int j = t * 2; j < BATCH; j += 512) {
        const float2 rc = *reinterpret_cast<const float2*>(&g_recon[j]);
        const float2 rn = *reinterpret_cast<const float2*>(&g_rnG[j]);
        const uint2  mp = *reinterpret_cast<const uint2*>(&g_minP[j]);
        const uint2  mg = *reinterpret_cast<const uint2*>(&g_minG[j]);
        rsum += rc.x + rc.y;
        float wp0 = sqrtf(fmaxf(funkey(mp.x) + rn.x, 0.f) + 1e-8f);
        float ww0 = sqrtf(fmaxf(funkey(mg.x) + rn.x, 0.f) + 1e-8f);
        float wp1 = sqrtf(fmaxf(funkey(mp.y) + rn.y, 0.f) + 1e-8f);
        float ww1 = sqrtf(fmaxf(funkey(mg.y) + rn.y, 0.f) + 1e-8f);
        ksum += logf(wp0 / (ww0 + 1e-8f) + 1e-8f);
        ksum += logf(wp1 / (ww1 + 1e-8f) + 1e-8f);
    }
    s1[t] = rsum; s2[t] = ksum;
    __syncthreads();
    for (int off = 128; off > 0; off >>= 1) {
        if (t < off) { s1[t] += s1[t + off]; s2[t] += s2[t + off]; }
        __syncthreads();
    }
    if (t == 0) {
        out[0] = s1[0] / (float)BATCH;
        out[1] = s2[0] / (float)BATCH * (float)DTOT
               + logf((float)BATCH / (float)(BATCH - 1));
    }
}

// ---------------- K3: decode | minmin | last-block finalize --------------------
__global__ __launch_bounds__(256, 2)
void minmin_decode_kernel(const float* __restrict__ n,
                          const float* __restrict__ z,
                          const float* __restrict__ znext,
                          float* __restrict__ out,
                          const float* __restrict__ w1W, const float* __restrict__ w1b,
                          const float* __restrict__ b1W, const float* __restrict__ b1b,
                          const float* __restrict__ w2W, const float* __restrict__ w2b,
                          const float* __restrict__ b2W, const float* __restrict__ b2b,
                          const float* __restrict__ w3W, const float* __restrict__ w3b,
                          const float* __restrict__ b3W, const float* __restrict__ b3b)
{
    extern __shared__ char mshm[];
    const int t = threadIdx.x;
    if ((int)blockIdx.x < NDEC) {
        decode_part(blockIdx.x, t, (float*)mshm, n, z, znext, out,
                    w1W, w1b, b1W, b1b, w2W, w2b, b2W, b2b, w3W, w3b, b3W, b3b);
    } else {
        minmin_body(blockIdx.x - NDEC, t, mshm);
    }

    __threadfence();
    __shared__ unsigned ticket;
    if (t == 0) ticket = atomicAdd(&g_done, 1u);
    __syncthreads();
    if (ticket == K3_NBLK - 1) {
        __syncthreads();
        finalize_body((float*)mshm, out, t);
    }
}

// ---------------- launch --------------------------------------------------------
extern "C" void kernel_launch(void* const* d_in, const int* in_sizes, int n_in,
                              void* d_out, int out_size)
{
    (void)in_sizes; (void)n_in; (void)out_size;
    const float* z     = (const float*)d_in[0];
    const float* znext = (const float*)d_in[1];
    const float* n     = (const float*)d_in[2];
    const float* prior = (const float*)d_in[3];
    const float* w1W = (const float*)d_in[4];  const float* w1b = (const float*)d_in[5];
    const float* b1W = (const float*)d_in[6];  const float* b1b = (const float*)d_in[7];
    const float* w2W = (const float*)d_in[8];  const float* w2b = (const float*)d_in[9];
    const float* b2W = (const float*)d_in[10]; const float* b2b = (const float*)d_in[11];
    const float* w3W = (const float*)d_in[12]; const float* w3b = (const float*)d_in[13];
    const float* b3W = (const float*)d_in[14]; const float* b3b = (const float*)d_in[15];
    float* out = (float*)d_out;

    cudaFuncSetAttribute(fused_pre_kernel,
                         cudaFuncAttributeMaxDynamicSharedMemorySize, PRE_SMEM_BYTES);
    cudaFuncSetAttribute(minmin_decode_kernel,
                         cudaFuncAttributeMaxDynamicSharedMemorySize, K3_SMEM_BYTES);

    prep_kernel<<<32 + RK * RK, 256>>>(
        w1W, w1b, b1W, b1b, w2W, w2b, b2W, b2b, w3W, w3b, b3W, b3b);
    fused_pre_kernel<<<NPP + NNP, 256, PRE_SMEM_BYTES>>>(n, prior);
    minmin_decode_kernel<<<K3_NBLK, 256, K3_SMEM_BYTES>>>(
        n, z, znext, out,
        w1W, w1b, b1W, b1b, w2W, w2b, b2W, b2b, w3W, w3b, b3W, b3b);
}